// round 3
// baseline (speedup 1.0000x reference)
#include <cuda_runtime.h>
#include <cstdint>

#define BNR   1600
#define HD    256
#define SEQ   64
#define NSTEPS 10

// ------------------------- static device scratch --------------------------
__device__ uint32_t g_xbt[BNR * SEQ * HD];      // x as tf32, [m][t][k]
__device__ uint32_t g_h0tf[2][BNR * HD];
__device__ uint32_t g_h1tf[2][BNR * HD];
__device__ uint32_t g_httf[BNR * HD];
__device__ float    g_h1f [BNR * HD];
__device__ float    g_c0  [BNR * HD];
__device__ float    g_c1  [BNR * HD];
__device__ float    g_hid [BNR * 512];
__device__ uint32_t g_Wre0[1024 * 512];         // tf32, rows (j*4+g), k = [Wih|Whh]
__device__ uint32_t g_Wre1[1024 * 512];
__device__ float    g_bre0[1024];
__device__ float    g_bre1[1024];
__device__ uint32_t g_Wh1 [512 * 256];          // heads layer1 weights tf32
__device__ float    g_bh1 [512];

// ------------------------------ helpers -----------------------------------
__device__ __forceinline__ uint32_t f2tf(float x) {
    uint32_t r;
    asm("cvt.rna.tf32.f32 %0, %1;" : "=r"(r) : "f"(x));
    return r;
}

__device__ __forceinline__ void mma_tf32(float* d, const uint32_t* a,
                                         uint32_t b0, uint32_t b1) {
    asm volatile(
        "mma.sync.aligned.m16n8k8.row.col.f32.tf32.tf32.f32 "
        "{%0,%1,%2,%3}, {%4,%5,%6,%7}, {%8,%9}, {%0,%1,%2,%3};"
        : "+f"(d[0]), "+f"(d[1]), "+f"(d[2]), "+f"(d[3])
        : "r"(a[0]), "r"(a[1]), "r"(a[2]), "r"(a[3]), "r"(b0), "r"(b1));
}

__device__ __forceinline__ float sigf(float x) {
    return 1.0f / (1.0f + __expf(-x));
}

__device__ __forceinline__ void cpa16(uint32_t saddr, const void* g, int sz) {
    asm volatile("cp.async.cg.shared.global [%0], [%1], 16, %2;"
                 :: "r"(saddr), "l"(g), "r"(sz));
}
#define CP_COMMIT() asm volatile("cp.async.commit_group;")

// ------------------------------ setup kernels -----------------------------
__global__ void transpose_kernel(const float* __restrict__ x) {
    int id = blockIdx.x * blockDim.x + threadIdx.x;     // 1600*64*64 float4
    if (id >= BNR * SEQ * (HD / 4)) return;
    int h4 = id & 63;
    int t  = (id >> 6) & 63;
    int m  = id >> 12;
    int b  = m / 100;
    int n  = m - b * 100;
    float4 v = ((const float4*)x)[(((b * SEQ + t) * 100 + n) * 64 + h4)];
    uint4 o;
    o.x = f2tf(v.x); o.y = f2tf(v.y); o.z = f2tf(v.z); o.w = f2tf(v.w);
    ((uint4*)g_xbt)[(m * SEQ + t) * 64 + h4] = o;
}

__global__ void rearr_w_kernel(const float* __restrict__ Wih,
                               const float* __restrict__ Whh,
                               const float* __restrict__ bih,
                               const float* __restrict__ bhh,
                               uint32_t* __restrict__ Wre,
                               float* __restrict__ bre) {
    int id = blockIdx.x * 256 + threadIdx.x;   // 1024*512
    int nre = id >> 9, k = id & 511;
    int j = nre >> 2, g = nre & 3;
    int srow = g * 256 + j;
    float v = (k < 256) ? Wih[srow * 256 + k] : Whh[srow * 256 + k - 256];
    Wre[id] = f2tf(v);
    if (k == 0) bre[nre] = bih[srow] + bhh[srow];
}

__global__ void rearr_h1_kernel(const float* __restrict__ cw1, const float* __restrict__ cb1,
                                const float* __restrict__ sw1, const float* __restrict__ sb1,
                                const float* __restrict__ lw1, const float* __restrict__ lb1) {
    int id = blockIdx.x * 256 + threadIdx.x;   // 512*256
    int row = id >> 8, k = id & 255;
    float v, b;
    if (row < 128)      { v = cw1[row * 256 + k];         b = cb1[row]; }
    else if (row < 256) { v = sw1[(row - 128) * 256 + k]; b = sb1[row - 128]; }
    else                { v = lw1[(row - 256) * 256 + k]; b = lb1[row - 256]; }
    g_Wh1[id] = f2tf(v);
    if (k == 0) g_bh1[row] = b;
}

__global__ void zero_state_kernel() {
    int id = blockIdx.x * blockDim.x + threadIdx.x;
    if (id < BNR * HD) {
        g_c0[id] = 0.f; g_c1[id] = 0.f;
        g_h0tf[0][id] = 0u; g_h0tf[1][id] = 0u;
        g_h1tf[0][id] = 0u; g_h1tf[1][id] = 0u;
    }
}

// ---------------------------------------------------------------------------
// LSTM cell GEMM. BM=128 rows x BN=128 gate-rows (32 j-cols). Grid (13,8).
// K=512 in 16 chunks of 32, 3-stage cp.async pipeline, 1 syncthreads/chunk.
// ---------------------------------------------------------------------------
#define AS_OFF(st) ((st) * 128 * 36)
#define BS_OFF(st) (3 * 128 * 36 + (st) * 128 * 36)
#define BIAS_OFF   (6 * 128 * 36)
#define CELL_SMEM  ((6 * 128 * 36 + 128) * 4)

__global__ void __launch_bounds__(256, 1)
cell_kernel(const uint32_t* __restrict__ A0, int lda0,
            const uint32_t* __restrict__ A1, int lda1,
            const uint32_t* __restrict__ W,
            const float* __restrict__ bre,
            float* __restrict__ Cio,
            float* __restrict__ Hf32,
            uint32_t* __restrict__ Htf)
{
    extern __shared__ uint32_t sm[];
    float* biasS = (float*)(sm + BIAS_OFF);

    const int tid = threadIdx.x;
    const int m0 = blockIdx.x * 128;
    const int nb0 = blockIdx.y * 128;      // gate-row base (= j0*4)

    if (tid < 128) biasS[tid] = bre[nb0 + tid];

    const int arow = tid >> 3;             // 0..31
    const int ac4  = tid & 7;              // 0..7

    uint32_t sA0 = (uint32_t)__cvta_generic_to_shared(sm + arow * 36 + ac4 * 4);
    const uint32_t stageAB = 128 * 36 * 4;
    const uint32_t bsBase  = 3 * stageAB;

    int mrow[4]; int msz[4];
#pragma unroll
    for (int q = 0; q < 4; ++q) {
        int m = m0 + arow + 32 * q;
        bool p = m < BNR;
        mrow[q] = p ? m : 0;
        msz[q]  = p ? 16 : 0;
    }
    const uint32_t* bbase = W + (long)(nb0 + arow) * 512 + ac4 * 4;

    const int lane = tid & 31, wid = tid >> 5;
    const int wm = wid >> 2, wn = wid & 3;     // 2 warps M x 4 warps N
    const int g4 = lane >> 2, t4 = lane & 3;

    float acc[4][4][4];
#pragma unroll
    for (int a = 0; a < 4; ++a)
#pragma unroll
        for (int b = 0; b < 4; ++b)
#pragma unroll
            for (int k = 0; k < 4; ++k) acc[a][b][k] = 0.f;

#define ISSUE(c, st)                                                           \
    do {                                                                       \
        const uint32_t* ab; int lda, kk;                                       \
        if ((c) < 8) { ab = A0; lda = lda0; kk = (c) * 32; }                   \
        else         { ab = A1; lda = lda1; kk = ((c) - 8) * 32; }             \
        _Pragma("unroll")                                                      \
        for (int q = 0; q < 4; ++q) {                                          \
            cpa16(sA0 + (st) * stageAB + q * (32 * 36 * 4),                    \
                  ab + (long)mrow[q] * lda + kk + ac4 * 4, msz[q]);            \
            cpa16(sA0 + bsBase + (st) * stageAB + q * (32 * 36 * 4),           \
                  bbase + (long)q * 32 * 512 + (c) * 32, 16);                  \
        }                                                                      \
        CP_COMMIT();                                                           \
    } while (0)

    ISSUE(0, 0);
    ISSUE(1, 1);

    for (int c = 0; c < 16; ++c) {
        const int st = c % 3;
        if (c < 15) asm volatile("cp.async.wait_group 1;");
        else        asm volatile("cp.async.wait_group 0;");
        __syncthreads();
        if (c + 2 < 16) ISSUE(c + 2, (c + 2) % 3);

        const uint32_t* As = sm + AS_OFF(st);
        const uint32_t* Bs = sm + BS_OFF(st);
#pragma unroll
        for (int ks = 0; ks < 32; ks += 8) {
            uint32_t af[4][4], b0[4], b1[4];
#pragma unroll
            for (int mf = 0; mf < 4; ++mf) {
                int r = wm * 64 + mf * 16 + g4;
                af[mf][0] = As[r * 36 + ks + t4];
                af[mf][1] = As[(r + 8) * 36 + ks + t4];
                af[mf][2] = As[r * 36 + ks + t4 + 4];
                af[mf][3] = As[(r + 8) * 36 + ks + t4 + 4];
            }
#pragma unroll
            for (int nf = 0; nf < 4; ++nf) {
                int rb = wn * 32 + nf * 8 + g4;
                b0[nf] = Bs[rb * 36 + ks + t4];
                b1[nf] = Bs[rb * 36 + ks + t4 + 4];
            }
#pragma unroll
            for (int mf = 0; mf < 4; ++mf)
#pragma unroll
                for (int nf = 0; nf < 4; ++nf)
                    mma_tf32(acc[mf][nf], af[mf], b0[nf], b1[nf]);
        }
    }
#undef ISSUE

    // ---------------- LSTM epilogue -------------------
    const bool oddl = (t4 & 1);
    const unsigned FULL = 0xffffffffu;
#pragma unroll
    for (int mf = 0; mf < 4; ++mf) {
#pragma unroll
        for (int nf = 0; nf < 4; ++nf) {
            float c0v = acc[mf][nf][0], c1v = acc[mf][nf][1];
            float c2v = acc[mf][nf][2], c3v = acc[mf][nf][3];
            float x0 = __shfl_xor_sync(FULL, c0v, 1);
            float x1 = __shfl_xor_sync(FULL, c1v, 1);
            float x2 = __shfl_xor_sync(FULL, c2v, 1);
            float x3 = __shfl_xor_sync(FULL, c3v, 1);
            float gi, gf, gg, go; int rloc;
            if (!oddl) { gi = c0v; gf = c1v; gg = x0;  go = x1;  rloc = g4; }
            else       { gi = x2;  gf = x3;  gg = c2v; go = c3v; rloc = g4 + 8; }
            int rglob = m0 + wm * 64 + mf * 16 + rloc;
            if (rglob >= BNR) continue;
            int jl = wn * 8 + nf * 2 + (t4 >> 1);            // 0..31
            int jglob = (nb0 >> 2) + jl;
            gi += biasS[jl * 4 + 0];
            gf += biasS[jl * 4 + 1];
            gg += biasS[jl * 4 + 2];
            go += biasS[jl * 4 + 3];
            float cold = Cio[rglob * HD + jglob];
            float cn = sigf(gf) * cold + sigf(gi) * tanhf(gg);
            float hn = sigf(go) * tanhf(cn);
            Cio[rglob * HD + jglob] = cn;
            if (Hf32) Hf32[rglob * HD + jglob] = hn;
            Htf[rglob * HD + jglob] = f2tf(hn);
        }
    }
}

// ---------------------------------------------------------------------------
// heads layer-1: hid[1600][512] = relu(httf @ Wh1^T + b). BM=128, 32 n/CTA.
// ---------------------------------------------------------------------------
__global__ void __launch_bounds__(256, 2)
heads1_kernel(const uint32_t* __restrict__ A0,
              const uint32_t* __restrict__ W,
              const float* __restrict__ bias,
              float* __restrict__ hid)
{
    __shared__ __align__(16) uint32_t As[2][128][36];
    __shared__ __align__(16) uint32_t Bs[2][32][36];
    __shared__ float biasS[32];

    const int tid = threadIdx.x;
    const int m0 = blockIdx.x * 128;
    const int n0 = blockIdx.y * 32;

    if (tid < 32) biasS[tid] = bias[n0 + tid];

    const int arow = tid >> 3;
    const int ac4  = tid & 7;

    uint32_t sA[4], sB;
#pragma unroll
    for (int q = 0; q < 4; ++q)
        sA[q] = (uint32_t)__cvta_generic_to_shared(&As[0][arow + 32 * q][ac4 * 4]);
    sB = (uint32_t)__cvta_generic_to_shared(&Bs[0][arow][ac4 * 4]);
    const uint32_t stA = 128 * 36 * 4;
    const uint32_t stB = 32 * 36 * 4;

    int mrow[4]; int msz[4];
#pragma unroll
    for (int q = 0; q < 4; ++q) {
        int m = m0 + arow + 32 * q;
        bool p = m < BNR;
        mrow[q] = p ? m : 0;
        msz[q]  = p ? 16 : 0;
    }
    const uint32_t* bbase = W + (n0 + arow) * 256 + ac4 * 4;

    const int lane = tid & 31, wid = tid >> 5;
    const int wm = wid >> 1, wn = wid & 1;
    const int g4 = lane >> 2, t4 = lane & 3;

    float acc[2][2][4];
#pragma unroll
    for (int a = 0; a < 2; ++a)
#pragma unroll
        for (int b = 0; b < 2; ++b)
#pragma unroll
            for (int k = 0; k < 4; ++k) acc[a][b][k] = 0.f;

#define ISSUE(c, st)                                                          \
    do {                                                                      \
        int kk = (c) * 32;                                                    \
        _Pragma("unroll")                                                     \
        for (int q = 0; q < 4; ++q)                                           \
            cpa16(sA[q] + (st) * stA, A0 + (long)mrow[q] * 256 + kk + ac4 * 4,\
                  msz[q]);                                                    \
        cpa16(sB + (st) * stB, bbase + kk, 16);                               \
        CP_COMMIT();                                                          \
    } while (0)

    ISSUE(0, 0);
    ISSUE(1, 1);

    for (int c = 0; c < 8; ++c) {
        const int st = c & 1;
        if (c < 7) asm volatile("cp.async.wait_group 1;");
        else       asm volatile("cp.async.wait_group 0;");
        __syncthreads();
#pragma unroll
        for (int ks = 0; ks < 32; ks += 8) {
            uint32_t af[2][4], b0[2], b1[2];
#pragma unroll
            for (int mf = 0; mf < 2; ++mf) {
                int r = wm * 32 + mf * 16 + g4;
                af[mf][0] = As[st][r    ][ks + t4];
                af[mf][1] = As[st][r + 8][ks + t4];
                af[mf][2] = As[st][r    ][ks + t4 + 4];
                af[mf][3] = As[st][r + 8][ks + t4 + 4];
            }
#pragma unroll
            for (int nf = 0; nf < 2; ++nf) {
                int rb = wn * 16 + nf * 8 + g4;
                b0[nf] = Bs[st][rb][ks + t4];
                b1[nf] = Bs[st][rb][ks + t4 + 4];
            }
#pragma unroll
            for (int mf = 0; mf < 2; ++mf)
#pragma unroll
                for (int nf = 0; nf < 2; ++nf)
                    mma_tf32(acc[mf][nf], af[mf], b0[nf], b1[nf]);
        }
        __syncthreads();
        if (c + 2 < 8) ISSUE(c + 2, st);
    }
#undef ISSUE

#pragma unroll
    for (int mf = 0; mf < 2; ++mf) {
#pragma unroll
        for (int nf = 0; nf < 2; ++nf) {
            int col = wn * 16 + nf * 8 + 2 * t4;
            int r0 = m0 + wm * 32 + mf * 16 + g4;
            float v0 = acc[mf][nf][0] + biasS[col];
            float v1 = acc[mf][nf][1] + biasS[col + 1];
            float v2 = acc[mf][nf][2] + biasS[col];
            float v3 = acc[mf][nf][3] + biasS[col + 1];
            if (r0 < BNR) {
                hid[r0 * 512 + n0 + col]     = fmaxf(v0, 0.f);
                hid[r0 * 512 + n0 + col + 1] = fmaxf(v1, 0.f);
            }
            if (r0 + 8 < BNR) {
                hid[(r0 + 8) * 512 + n0 + col]     = fmaxf(v2, 0.f);
                hid[(r0 + 8) * 512 + n0 + col + 1] = fmaxf(v3, 0.f);
            }
        }
    }
}

// ---------------------------------------------------------------------------
__global__ void __launch_bounds__(128)
heads2_kernel(const float* __restrict__ hid,
              const float* __restrict__ cw2, const float* __restrict__ cb2,
              const float* __restrict__ sw2, const float* __restrict__ sb2,
              const float* __restrict__ lw2, const float* __restrict__ lb2,
              float* __restrict__ out, int s)
{
    int m = blockIdx.x;
    __shared__ float hs[512];
    for (int i = threadIdx.x; i < 512; i += 128) hs[i] = hid[m * 512 + i];
    __syncthreads();

    int wid = threadIdx.x >> 5, lane = threadIdx.x & 31;
    int b = m / 100, n = m - b * 100;
    float* obase = out + (((b * NSTEPS + s) * 100 + n) * 22);

    for (int o = wid; o < 22; o += 4) {
        const float* w; float bb; int base, klen;
        if (o < 4)       { w = cw2 + o * 128;        bb = cb2[o];     base = 0;   klen = 128; }
        else if (o < 6)  { w = sw2 + (o - 4) * 128;  bb = sb2[o - 4]; base = 128; klen = 128; }
        else             { w = lw2 + (o - 6) * 256;  bb = lb2[o - 6]; base = 256; klen = 256; }
        float acc = 0.f;
        for (int k = lane; k < klen; k += 32) acc += hs[base + k] * w[k];
#pragma unroll
        for (int off = 16; off; off >>= 1)
            acc += __shfl_xor_sync(0xffffffffu, acc, off);
        if (lane == 0) obase[o] = acc + bb;
    }
}

// ---------------------------------------------------------------------------
__global__ void __launch_bounds__(256)
ln_kernel(const float* __restrict__ hin, const float* __restrict__ gamma,
          const float* __restrict__ beta, uint32_t* __restrict__ outtf)
{
    int m = blockIdx.x, t = threadIdx.x;
    float v = hin[m * 256 + t];
    float s1 = v, s2 = v * v;
#pragma unroll
    for (int o = 16; o; o >>= 1) {
        s1 += __shfl_xor_sync(0xffffffffu, s1, o);
        s2 += __shfl_xor_sync(0xffffffffu, s2, o);
    }
    __shared__ float r1[8], r2[8];
    if ((t & 31) == 0) { r1[t >> 5] = s1; r2[t >> 5] = s2; }
    __syncthreads();
    float S1 = 0.f, S2 = 0.f;
#pragma unroll
    for (int i = 0; i < 8; ++i) { S1 += r1[i]; S2 += r2[i]; }
    float mean = S1 * (1.f / 256.f);
    float var  = S2 * (1.f / 256.f) - mean * mean;
    float o = (v - mean) * rsqrtf(var + 1e-5f) * gamma[t] + beta[t];
    outtf[m * 256 + t] = f2tf(o);
}

// ---------------------------------------------------------------------------
extern "C" void kernel_launch(void* const* d_in, const int* in_sizes, int n_in,
                              void* d_out, int out_size)
{
    (void)in_sizes; (void)n_in; (void)out_size;
    const float* x    = (const float*)d_in[0];
    const float* Wih0 = (const float*)d_in[1];
    const float* Whh0 = (const float*)d_in[2];
    const float* bih0 = (const float*)d_in[3];
    const float* bhh0 = (const float*)d_in[4];
    const float* Wih1 = (const float*)d_in[5];
    const float* Whh1 = (const float*)d_in[6];
    const float* bih1 = (const float*)d_in[7];
    const float* bhh1 = (const float*)d_in[8];
    const float* lng  = (const float*)d_in[9];
    const float* lnb  = (const float*)d_in[10];
    const float* cw1  = (const float*)d_in[11];
    const float* cb1  = (const float*)d_in[12];
    const float* cw2  = (const float*)d_in[13];
    const float* cb2  = (const float*)d_in[14];
    const float* sw1  = (const float*)d_in[15];
    const float* sb1  = (const float*)d_in[16];
    const float* sw2  = (const float*)d_in[17];
    const float* sb2  = (const float*)d_in[18];
    const float* lw1  = (const float*)d_in[19];
    const float* lb1  = (const float*)d_in[20];
    const float* lw2  = (const float*)d_in[21];
    const float* lb2  = (const float*)d_in[22];
    float* out = (float*)d_out;

    uint32_t *xbt, *h0tf, *h1tf, *httf, *Wre0, *Wre1, *Wh1;
    float *h1f, *c0, *c1, *hid, *bre0, *bre1, *bh1;
    cudaGetSymbolAddress((void**)&xbt,  g_xbt);
    cudaGetSymbolAddress((void**)&h0tf, g_h0tf);
    cudaGetSymbolAddress((void**)&h1tf, g_h1tf);
    cudaGetSymbolAddress((void**)&httf, g_httf);
    cudaGetSymbolAddress((void**)&h1f,  g_h1f);
    cudaGetSymbolAddress((void**)&c0,   g_c0);
    cudaGetSymbolAddress((void**)&c1,   g_c1);
    cudaGetSymbolAddress((void**)&hid,  g_hid);
    cudaGetSymbolAddress((void**)&Wre0, g_Wre0);
    cudaGetSymbolAddress((void**)&Wre1, g_Wre1);
    cudaGetSymbolAddress((void**)&bre0, g_bre0);
    cudaGetSymbolAddress((void**)&bre1, g_bre1);
    cudaGetSymbolAddress((void**)&Wh1,  g_Wh1);
    cudaGetSymbolAddress((void**)&bh1,  g_bh1);

    cudaFuncSetAttribute(cell_kernel,
                         cudaFuncAttributeMaxDynamicSharedMemorySize, CELL_SMEM);

    uint32_t* H0[2] = {h0tf, h0tf + BNR * HD};
    uint32_t* H1[2] = {h1tf, h1tf + BNR * HD};

    transpose_kernel<<<25600, 256>>>(x);
    rearr_w_kernel<<<2048, 256>>>(Wih0, Whh0, bih0, bhh0, Wre0, bre0);
    rearr_w_kernel<<<2048, 256>>>(Wih1, Whh1, bih1, bhh1, Wre1, bre1);
    rearr_h1_kernel<<<512, 256>>>(cw1, cb1, sw1, sb1, lw1, lb1);
    zero_state_kernel<<<1600, 256>>>();

    dim3 cg(13, 8);
    int p0 = 0, p1 = 0;
    for (int t = 0; t < SEQ; ++t) {
        cell_kernel<<<cg, 256, CELL_SMEM>>>(xbt + t * HD, SEQ * HD,
                                            H0[p0], HD, Wre0, bre0,
                                            c0, nullptr, H0[p0 ^ 1]);
        cell_kernel<<<cg, 256, CELL_SMEM>>>(H0[p0 ^ 1], HD,
                                            H1[p1], HD, Wre1, bre1,
                                            c1, h1f, H1[p1 ^ 1]);
        p0 ^= 1; p1 ^= 1;
    }
    ln_kernel<<<1600, 256>>>(h1f, lng, lnb, httf);

    for (int s = 0; s < NSTEPS; ++s) {
        heads1_kernel<<<dim3(13, 16), 256>>>(httf, Wh1, bh1, hid);
        heads2_kernel<<<1600, 128>>>(hid, cw2, cb2, sw2, sb2, lw2, lb2, out, s);
        if (s < NSTEPS - 1) {
            cell_kernel<<<cg, 256, CELL_SMEM>>>(httf, HD,
                                                H0[p0], HD, Wre0, bre0,
                                                c0, nullptr, H0[p0 ^ 1]);
            cell_kernel<<<cg, 256, CELL_SMEM>>>(H0[p0 ^ 1], HD,
                                                H1[p1], HD, Wre1, bre1,
                                                c1, h1f, H1[p1 ^ 1]);
            p0 ^= 1; p1 ^= 1;
            ln_kernel<<<1600, 256>>>(h1f, lng, lnb, httf);
        }
    }
}

// round 4
// speedup vs baseline: 1.2265x; 1.2265x over previous
#include <cuda_runtime.h>
#include <cstdint>

#define BNR    1600
#define HD     256
#define SEQ    64
#define NSTEPS 10
#define NCTA   104
#define MT     13

// ------------------------- static device scratch --------------------------
__device__ uint32_t g_xbt[BNR * SEQ * HD];      // x as tf32, [m][t][k]
__device__ uint32_t g_h0buf[2][BNR * HD];
__device__ uint32_t g_h1buf[2][BNR * HD];
__device__ uint32_t g_httf[BNR * HD];
__device__ float    g_hid [BNR * 512];
__device__ uint32_t g_Wre0[1024 * 512];         // tf32, rows (j*4+g), k=[Wih|Whh]
__device__ uint32_t g_Wre1[1024 * 512];
__device__ float    g_bre0[1024];
__device__ float    g_bre1[1024];
__device__ uint32_t g_Wh1 [512 * 256];          // heads layer1 weights tf32
__device__ float    g_bh1 [512];
__device__ unsigned g_barCnt;
__device__ unsigned g_barGen;

// ------------------------------ helpers -----------------------------------
__device__ __forceinline__ uint32_t f2tf(float x) {
    uint32_t r;
    asm("cvt.rna.tf32.f32 %0, %1;" : "=r"(r) : "f"(x));
    return r;
}
__device__ __forceinline__ void mma_tf32(float* d, const uint32_t* a,
                                         uint32_t b0, uint32_t b1) {
    asm volatile(
        "mma.sync.aligned.m16n8k8.row.col.f32.tf32.tf32.f32 "
        "{%0,%1,%2,%3}, {%4,%5,%6,%7}, {%8,%9}, {%0,%1,%2,%3};"
        : "+f"(d[0]), "+f"(d[1]), "+f"(d[2]), "+f"(d[3])
        : "r"(a[0]), "r"(a[1]), "r"(a[2]), "r"(a[3]), "r"(b0), "r"(b1));
}
__device__ __forceinline__ float sigf(float x) { return 1.0f / (1.0f + __expf(-x)); }

__device__ __forceinline__ void cpa16(uint32_t saddr, const void* g, int sz) {
    asm volatile("cp.async.cg.shared.global [%0], [%1], 16, %2;"
                 :: "r"(saddr), "l"(g), "r"(sz));
}
#define CP_COMMIT() asm volatile("cp.async.commit_group;")

// grid-wide barrier (all NCTA CTAs resident by construction)
__device__ __forceinline__ void gbar() {
    __syncthreads();
    if (threadIdx.x == 0) {
        __threadfence();
        unsigned gen = ((volatile unsigned*)&g_barGen)[0];
        if (atomicAdd(&g_barCnt, 1u) == NCTA - 1) {
            ((volatile unsigned*)&g_barCnt)[0] = 0;
            __threadfence();
            atomicExch(&g_barGen, gen + 1);
        } else {
            while (((volatile unsigned*)&g_barGen)[0] == gen) __nanosleep(32);
        }
        __threadfence();
    }
    __syncthreads();
}

// ------------------------------ setup kernels -----------------------------
__global__ void transpose_kernel(const float* __restrict__ x) {
    int id = blockIdx.x * blockDim.x + threadIdx.x;
    if (id >= BNR * SEQ * (HD / 4)) return;
    int h4 = id & 63;
    int t  = (id >> 6) & 63;
    int m  = id >> 12;
    int b  = m / 100;
    int n  = m - b * 100;
    float4 v = ((const float4*)x)[(((b * SEQ + t) * 100 + n) * 64 + h4)];
    uint4 o;
    o.x = f2tf(v.x); o.y = f2tf(v.y); o.z = f2tf(v.z); o.w = f2tf(v.w);
    ((uint4*)g_xbt)[(m * SEQ + t) * 64 + h4] = o;
}

__global__ void rearr_w_kernel(const float* __restrict__ Wih,
                               const float* __restrict__ Whh,
                               const float* __restrict__ bih,
                               const float* __restrict__ bhh,
                               uint32_t* __restrict__ Wre,
                               float* __restrict__ bre) {
    int id = blockIdx.x * 256 + threadIdx.x;   // 1024*512
    int nre = id >> 9, k = id & 511;
    int j = nre >> 2, g = nre & 3;
    int srow = g * 256 + j;
    float v = (k < 256) ? Wih[srow * 256 + k] : Whh[srow * 256 + k - 256];
    Wre[id] = f2tf(v);
    if (k == 0) bre[nre] = bih[srow] + bhh[srow];
}

__global__ void rearr_h1_kernel(const float* __restrict__ cw1, const float* __restrict__ cb1,
                                const float* __restrict__ sw1, const float* __restrict__ sb1,
                                const float* __restrict__ lw1, const float* __restrict__ lb1) {
    int id = blockIdx.x * 256 + threadIdx.x;   // 512*256
    int row = id >> 8, k = id & 255;
    float v, b;
    if (row < 128)      { v = cw1[row * 256 + k];         b = cb1[row]; }
    else if (row < 256) { v = sw1[(row - 128) * 256 + k]; b = sb1[row - 128]; }
    else                { v = lw1[(row - 256) * 256 + k]; b = lb1[row - 256]; }
    g_Wh1[id] = f2tf(v);
    if (k == 0) g_bh1[row] = b;
}

__global__ void zero_state_kernel() {
    int id = blockIdx.x * blockDim.x + threadIdx.x;
    if (id < BNR * HD) { g_h0buf[0][id] = 0u; g_h1buf[0][id] = 0u; }
    if (id == 0) { g_barCnt = 0; }
}

// ---------------------------------------------------------------------------
// smem layout: 4 stages x (A 128x36 + B 128x36) u32 + biases
#define STG_W   9216                // words per stage
#define STG_B   (STG_W * 4)         // bytes per stage
#define BOF_B   (4608 * 4)          // B offset within stage (bytes)
#define BIAS_W  (4 * STG_W)         // bias area offset (words)
#define PSMEM   ((4 * STG_W + 320) * 4)

// ---------------- LSTM cell phase (device function) ------------------------
__device__ __forceinline__ void cell_phase(
    uint32_t* sm,
    const uint32_t* __restrict__ A0, long lda0,
    const uint32_t* __restrict__ A1,
    const uint32_t* __restrict__ Wsl,     // weight slice: rows nb0..nb0+127
    const float* biasS,                   // 128 combined biases (smem)
    float* cReg,                          // 16 cell-state registers
    uint32_t* __restrict__ Htf,
    int m0, int j0)
{
    const int tid  = threadIdx.x;
    const int arow = tid >> 3, ac4 = tid & 7;
    const int lane = tid & 31, wid = tid >> 5;
    const int wm = wid >> 2, wn = wid & 3;
    const int g4 = lane >> 2, t4 = lane & 3;

    int mrow[4], msz[4];
#pragma unroll
    for (int q = 0; q < 4; ++q) {
        int m = m0 + arow + 32 * q;
        bool p = m < BNR;
        mrow[q] = p ? m : 0;
        msz[q]  = p ? 16 : 0;
    }
    uint32_t sb = (uint32_t)__cvta_generic_to_shared(sm) +
                  (uint32_t)((arow * 36 + ac4 * 4) * 4);
    const uint32_t* bb = Wsl + (long)arow * 512 + ac4 * 4;

    float acc[4][4][4];
#pragma unroll
    for (int a = 0; a < 4; ++a)
#pragma unroll
        for (int b = 0; b < 4; ++b)
#pragma unroll
            for (int k = 0; k < 4; ++k) acc[a][b][k] = 0.f;

    auto issue = [&](int c, int st) {
        const uint32_t* ap; long lda; int kk;
        if (c < 8) { ap = A0; lda = lda0; kk = c * 32; }
        else       { ap = A1; lda = 256;  kk = (c - 8) * 32; }
#pragma unroll
        for (int q = 0; q < 4; ++q) {
            cpa16(sb + st * STG_B + q * 4608,
                  ap + (long)mrow[q] * lda + kk + ac4 * 4, msz[q]);
            cpa16(sb + st * STG_B + BOF_B + q * 4608,
                  bb + (long)q * 32 * 512 + c * 32, 16);
        }
        CP_COMMIT();
    };

    issue(0, 0); issue(1, 1); issue(2, 2);
    for (int c = 0; c < 16; ++c) {
        const int st = c & 3;
        if (c < 13) asm volatile("cp.async.wait_group 2;");
        else        asm volatile("cp.async.wait_group 0;");
        __syncthreads();
        if (c + 3 < 16) issue(c + 3, (c + 3) & 3);

        const uint32_t* As = sm + st * STG_W;
        const uint32_t* Bs = sm + st * STG_W + 4608;
#pragma unroll
        for (int ks = 0; ks < 32; ks += 8) {
            uint32_t af[4][4], b0[4], b1[4];
#pragma unroll
            for (int mf = 0; mf < 4; ++mf) {
                int r = wm * 64 + mf * 16 + g4;
                af[mf][0] = As[r * 36 + ks + t4];
                af[mf][1] = As[(r + 8) * 36 + ks + t4];
                af[mf][2] = As[r * 36 + ks + t4 + 4];
                af[mf][3] = As[(r + 8) * 36 + ks + t4 + 4];
            }
#pragma unroll
            for (int nf = 0; nf < 4; ++nf) {
                int rb = wn * 32 + nf * 8 + g4;
                b0[nf] = Bs[rb * 36 + ks + t4];
                b1[nf] = Bs[rb * 36 + ks + t4 + 4];
            }
#pragma unroll
            for (int mf = 0; mf < 4; ++mf)
#pragma unroll
                for (int nf = 0; nf < 4; ++nf)
                    mma_tf32(acc[mf][nf], af[mf], b0[nf], b1[nf]);
        }
    }

    // LSTM epilogue (c kept in registers)
    const bool oddl = (t4 & 1);
    const unsigned FULL = 0xffffffffu;
#pragma unroll
    for (int mf = 0; mf < 4; ++mf) {
#pragma unroll
        for (int nf = 0; nf < 4; ++nf) {
            float c0v = acc[mf][nf][0], c1v = acc[mf][nf][1];
            float c2v = acc[mf][nf][2], c3v = acc[mf][nf][3];
            float x0 = __shfl_xor_sync(FULL, c0v, 1);
            float x1 = __shfl_xor_sync(FULL, c1v, 1);
            float x2 = __shfl_xor_sync(FULL, c2v, 1);
            float x3 = __shfl_xor_sync(FULL, c3v, 1);
            float gi, gf, gg, go; int rloc;
            if (!oddl) { gi = c0v; gf = c1v; gg = x0;  go = x1;  rloc = g4; }
            else       { gi = x2;  gf = x3;  gg = c2v; go = c3v; rloc = g4 + 8; }
            int rglob = m0 + wm * 64 + mf * 16 + rloc;
            int jl = wn * 8 + nf * 2 + (t4 >> 1);
            gi += biasS[jl * 4 + 0];
            gf += biasS[jl * 4 + 1];
            gg += biasS[jl * 4 + 2];
            go += biasS[jl * 4 + 3];
            float cold = cReg[mf * 4 + nf];
            float cn = sigf(gf) * cold + sigf(gi) * tanhf(gg);
            float hn = sigf(go) * tanhf(cn);
            cReg[mf * 4 + nf] = cn;
            if (rglob < BNR) Htf[rglob * HD + j0 + jl] = f2tf(hn);
        }
    }
}

// ---------------- heads layer-1 phase --------------------------------------
__device__ __forceinline__ void heads1_phase(
    uint32_t* sm, const uint32_t* __restrict__ A0,
    const uint32_t* __restrict__ Wsl,     // Wh1 rows hn0..hn0+63
    const float* biasS,                   // 64
    float* __restrict__ hid, int m0, int n0)
{
    const int tid  = threadIdx.x;
    const int arow = tid >> 3, ac4 = tid & 7;
    const int lane = tid & 31, wid = tid >> 5;
    const int wm = wid >> 2, wn = wid & 3;
    const int g4 = lane >> 2, t4 = lane & 3;

    int mrow[4], msz[4];
#pragma unroll
    for (int q = 0; q < 4; ++q) {
        int m = m0 + arow + 32 * q;
        bool p = m < BNR;
        mrow[q] = p ? m : 0;
        msz[q]  = p ? 16 : 0;
    }
    uint32_t sb = (uint32_t)__cvta_generic_to_shared(sm) +
                  (uint32_t)((arow * 36 + ac4 * 4) * 4);
    const uint32_t* bb = Wsl + (long)arow * 256 + ac4 * 4;

    float acc[4][2][4];
#pragma unroll
    for (int a = 0; a < 4; ++a)
#pragma unroll
        for (int b = 0; b < 2; ++b)
#pragma unroll
            for (int k = 0; k < 4; ++k) acc[a][b][k] = 0.f;

    auto issue = [&](int c, int st) {
        int kk = c * 32;
#pragma unroll
        for (int q = 0; q < 4; ++q)
            cpa16(sb + st * STG_B + q * 4608,
                  A0 + (long)mrow[q] * 256 + kk + ac4 * 4, msz[q]);
#pragma unroll
        for (int q = 0; q < 2; ++q)
            cpa16(sb + st * STG_B + BOF_B + q * 4608,
                  bb + (long)q * 32 * 256 + kk, 16);
        CP_COMMIT();
    };

    issue(0, 0); issue(1, 1); issue(2, 2);
    for (int c = 0; c < 8; ++c) {
        const int st = c & 3;
        if (c < 5) asm volatile("cp.async.wait_group 2;");
        else       asm volatile("cp.async.wait_group 0;");
        __syncthreads();
        if (c + 3 < 8) issue(c + 3, (c + 3) & 3);

        const uint32_t* As = sm + st * STG_W;
        const uint32_t* Bs = sm + st * STG_W + 4608;
#pragma unroll
        for (int ks = 0; ks < 32; ks += 8) {
            uint32_t af[4][4], b0[2], b1[2];
#pragma unroll
            for (int mf = 0; mf < 4; ++mf) {
                int r = wm * 64 + mf * 16 + g4;
                af[mf][0] = As[r * 36 + ks + t4];
                af[mf][1] = As[(r + 8) * 36 + ks + t4];
                af[mf][2] = As[r * 36 + ks + t4 + 4];
                af[mf][3] = As[(r + 8) * 36 + ks + t4 + 4];
            }
#pragma unroll
            for (int nf = 0; nf < 2; ++nf) {
                int rb = wn * 16 + nf * 8 + g4;
                b0[nf] = Bs[rb * 36 + ks + t4];
                b1[nf] = Bs[rb * 36 + ks + t4 + 4];
            }
#pragma unroll
            for (int mf = 0; mf < 4; ++mf)
#pragma unroll
                for (int nf = 0; nf < 2; ++nf)
                    mma_tf32(acc[mf][nf], af[mf], b0[nf], b1[nf]);
        }
    }

#pragma unroll
    for (int mf = 0; mf < 4; ++mf) {
#pragma unroll
        for (int nf = 0; nf < 2; ++nf) {
            int col = wn * 16 + nf * 8 + 2 * t4;
            int r0 = m0 + wm * 64 + mf * 16 + g4;
            float v0 = acc[mf][nf][0] + biasS[col];
            float v1 = acc[mf][nf][1] + biasS[col + 1];
            float v2 = acc[mf][nf][2] + biasS[col];
            float v3 = acc[mf][nf][3] + biasS[col + 1];
            if (r0 < BNR) {
                hid[r0 * 512 + n0 + col]     = fmaxf(v0, 0.f);
                hid[r0 * 512 + n0 + col + 1] = fmaxf(v1, 0.f);
            }
            if (r0 + 8 < BNR) {
                hid[(r0 + 8) * 512 + n0 + col]     = fmaxf(v2, 0.f);
                hid[(r0 + 8) * 512 + n0 + col + 1] = fmaxf(v3, 0.f);
            }
        }
    }
}

// ---------------- LayerNorm phase (warp per row) ----------------------------
__device__ __forceinline__ void ln_phase(
    const uint32_t* __restrict__ h1, const float* __restrict__ gam,
    const float* __restrict__ bet, uint32_t* __restrict__ ht, int cta)
{
    const int wid = threadIdx.x >> 5, lane = threadIdx.x & 31;
    const unsigned FULL = 0xffffffffu;
#pragma unroll
    for (int rep = 0; rep < 2; ++rep) {
        int r = cta * 16 + rep * 8 + wid;
        if (r < BNR) {
            const uint4* p = (const uint4*)(h1 + r * HD + lane * 8);
            uint4 u0 = __ldcg(p);
            uint4 u1 = __ldcg(p + 1);
            float v[8];
            v[0] = __uint_as_float(u0.x); v[1] = __uint_as_float(u0.y);
            v[2] = __uint_as_float(u0.z); v[3] = __uint_as_float(u0.w);
            v[4] = __uint_as_float(u1.x); v[5] = __uint_as_float(u1.y);
            v[6] = __uint_as_float(u1.z); v[7] = __uint_as_float(u1.w);
            float s1 = 0.f, s2 = 0.f;
#pragma unroll
            for (int i = 0; i < 8; ++i) { s1 += v[i]; s2 += v[i] * v[i]; }
#pragma unroll
            for (int o = 16; o; o >>= 1) {
                s1 += __shfl_xor_sync(FULL, s1, o);
                s2 += __shfl_xor_sync(FULL, s2, o);
            }
            float mean = s1 * (1.f / 256.f);
            float var  = s2 * (1.f / 256.f) - mean * mean;
            float rstd = rsqrtf(var + 1e-5f);
            uint4 o0, o1;
            uint32_t* op = (uint32_t*)&o0;
#pragma unroll
            for (int i = 0; i < 8; ++i) {
                float g = __ldg(&gam[lane * 8 + i]);
                float b = __ldg(&bet[lane * 8 + i]);
                float ov = (v[i] - mean) * rstd * g + b;
                if (i < 4) op[i] = f2tf(ov);
                else       ((uint32_t*)&o1)[i - 4] = f2tf(ov);
            }
            uint4* q = (uint4*)(ht + r * HD + lane * 8);
            q[0] = o0; q[1] = o1;
        }
    }
}

// ---------------- heads layer-2 phase ---------------------------------------
__device__ __forceinline__ void heads2_phase(
    uint32_t* sm, const float* __restrict__ hid,
    const float* __restrict__ cw2, const float* __restrict__ cb2,
    const float* __restrict__ sw2, const float* __restrict__ sb2,
    const float* __restrict__ lw2, const float* __restrict__ lb2,
    float* __restrict__ out, int s, int cta)
{
    float* hs = (float*)sm;                 // 16 rows x 512 = 32KB
    const int tid = threadIdx.x;
    for (int i = tid; i < 16 * 128; i += 256) {
        int rr = i >> 7, c4 = i & 127;
        int r = cta * 16 + rr;
        float4 val = make_float4(0.f, 0.f, 0.f, 0.f);
        if (r < BNR) val = __ldcg((const float4*)(hid + r * 512) + c4);
        ((float4*)hs)[rr * 128 + c4] = val;
    }
    __syncthreads();

    const int wid = tid >> 5, lane = tid & 31;
    const unsigned FULL = 0xffffffffu;
#pragma unroll
    for (int rep = 0; rep < 2; ++rep) {
        int rr = rep * 8 + wid;
        int r = cta * 16 + rr;
        if (r < BNR) {
            int b = r / 100, n = r - b * 100;
            float* ob = out + (((b * NSTEPS + s) * 100 + n) * 22);
            const float* h = hs + rr * 512;
            for (int o = 0; o < 22; ++o) {
                const float* w; float bb; int base, klen;
                if (o < 4)      { w = cw2 + o * 128;       bb = __ldg(&cb2[o]);     base = 0;   klen = 128; }
                else if (o < 6) { w = sw2 + (o - 4) * 128; bb = __ldg(&sb2[o - 4]); base = 128; klen = 128; }
                else            { w = lw2 + (o - 6) * 256; bb = __ldg(&lb2[o - 6]); base = 256; klen = 256; }
                float a = 0.f;
                for (int k = lane; k < klen; k += 32) a += h[base + k] * __ldg(&w[k]);
#pragma unroll
                for (int off = 16; off; off >>= 1) a += __shfl_xor_sync(FULL, a, off);
                if (lane == 0) ob[o] = a + bb;
            }
        }
    }
    __syncthreads();   // protect smem before next phase reuses it
}

// ---------------------------------------------------------------------------
__global__ void __launch_bounds__(256, 1)
persist_kernel(const float* __restrict__ lng, const float* __restrict__ lnb,
               const float* __restrict__ cw2, const float* __restrict__ cb2,
               const float* __restrict__ sw2, const float* __restrict__ sb2,
               const float* __restrict__ lw2, const float* __restrict__ lb2,
               float* __restrict__ out)
{
    extern __shared__ uint32_t sm[];
    float* bS0 = (float*)(sm + BIAS_W);
    float* bS1 = bS0 + 128;
    float* bSh = bS1 + 128;

    const int tid = threadIdx.x;
    const int cta = blockIdx.x;
    const int mx = cta % MT, ny = cta / MT;
    const int m0  = mx * 128;
    const int nb0 = ny * 128;       // gate-row base for cells
    const int j0  = ny * 32;        // j-col base for cells
    const int hn0 = ny * 64;        // heads1 col base

    if (tid < 128) { bS0[tid] = g_bre0[nb0 + tid]; bS1[tid] = g_bre1[nb0 + tid]; }
    if (tid < 64)  { bSh[tid] = g_bh1[hn0 + tid]; }
    __syncthreads();

    float c0r[16], c1r[16];
#pragma unroll
    for (int i = 0; i < 16; ++i) { c0r[i] = 0.f; c1r[i] = 0.f; }

    const uint32_t* W0sl = g_Wre0 + (long)nb0 * 512;
    const uint32_t* W1sl = g_Wre1 + (long)nb0 * 512;
    const uint32_t* Wh1sl = g_Wh1 + (long)hn0 * 256;

    const uint32_t* h0cur = g_h0buf[0]; uint32_t* h0nxt = g_h0buf[1];
    const uint32_t* h1cur = g_h1buf[0]; uint32_t* h1nxt = g_h1buf[1];

    // ---------------- encoder ----------------
    for (int t = 0; t < SEQ; ++t) {
        cell_phase(sm, g_xbt + (long)t * HD, (long)SEQ * HD, h0cur,
                   W0sl, bS0, c0r, h0nxt, m0, j0);
        gbar();
        cell_phase(sm, h0nxt, HD, h1cur, W1sl, bS1, c1r, h1nxt, m0, j0);
        gbar();
        const uint32_t* tp;
        tp = h0cur; h0cur = h0nxt; h0nxt = (uint32_t*)tp;
        tp = h1cur; h1cur = h1nxt; h1nxt = (uint32_t*)tp;
    }

    ln_phase(h1cur, lng, lnb, g_httf, cta);
    gbar();

    // ---------------- decoder ----------------
    for (int s = 0; s < NSTEPS; ++s) {
        heads1_phase(sm, g_httf, Wh1sl, bSh, g_hid, m0, hn0);
        gbar();
        heads2_phase(sm, g_hid, cw2, cb2, sw2, sb2, lw2, lb2, out, s, cta);
        if (s < NSTEPS - 1) {
            cell_phase(sm, g_httf, HD, h0cur, W0sl, bS0, c0r, h0nxt, m0, j0);
            gbar();
            cell_phase(sm, h0nxt, HD, h1cur, W1sl, bS1, c1r, h1nxt, m0, j0);
            gbar();
            const uint32_t* tp;
            tp = h0cur; h0cur = h0nxt; h0nxt = (uint32_t*)tp;
            tp = h1cur; h1cur = h1nxt; h1nxt = (uint32_t*)tp;
            ln_phase(h1cur, lng, lnb, g_httf, cta);
            gbar();
        }
    }
}

// ---------------------------------------------------------------------------
extern "C" void kernel_launch(void* const* d_in, const int* in_sizes, int n_in,
                              void* d_out, int out_size)
{
    (void)in_sizes; (void)n_in; (void)out_size;
    const float* x    = (const float*)d_in[0];
    const float* Wih0 = (const float*)d_in[1];
    const float* Whh0 = (const float*)d_in[2];
    const float* bih0 = (const float*)d_in[3];
    const float* bhh0 = (const float*)d_in[4];
    const float* Wih1 = (const float*)d_in[5];
    const float* Whh1 = (const float*)d_in[6];
    const float* bih1 = (const float*)d_in[7];
    const float* bhh1 = (const float*)d_in[8];
    const float* lng  = (const float*)d_in[9];
    const float* lnb  = (const float*)d_in[10];
    const float* cw1  = (const float*)d_in[11];
    const float* cb1  = (const float*)d_in[12];
    const float* cw2  = (const float*)d_in[13];
    const float* cb2  = (const float*)d_in[14];
    const float* sw1  = (const float*)d_in[15];
    const float* sb1  = (const float*)d_in[16];
    const float* sw2  = (const float*)d_in[17];
    const float* sb2  = (const float*)d_in[18];
    const float* lw1  = (const float*)d_in[19];
    const float* lb1  = (const float*)d_in[20];
    const float* lw2  = (const float*)d_in[21];
    const float* lb2  = (const float*)d_in[22];
    float* out = (float*)d_out;

    uint32_t *Wre0, *Wre1;
    float *bre0, *bre1;
    cudaGetSymbolAddress((void**)&Wre0, g_Wre0);
    cudaGetSymbolAddress((void**)&Wre1, g_Wre1);
    cudaGetSymbolAddress((void**)&bre0, g_bre0);
    cudaGetSymbolAddress((void**)&bre1, g_bre1);

    cudaFuncSetAttribute(persist_kernel,
                         cudaFuncAttributeMaxDynamicSharedMemorySize, PSMEM);

    transpose_kernel<<<25600, 256>>>(x);
    rearr_w_kernel<<<2048, 256>>>(Wih0, Whh0, bih0, bhh0, Wre0, bre0);
    rearr_w_kernel<<<2048, 256>>>(Wih1, Whh1, bih1, bhh1, Wre1, bre1);
    rearr_h1_kernel<<<512, 256>>>(cw1, cb1, sw1, sb1, lw1, lb1);
    zero_state_kernel<<<1600, 256>>>();

    persist_kernel<<<NCTA, 256, PSMEM>>>(lng, lnb, cw2, cb2, sw2, sb2,
                                         lw2, lb2, out);
}

// round 7
// speedup vs baseline: 1.8489x; 1.5075x over previous
#include <cuda_runtime.h>
#include <cuda_fp16.h>
#include <cstdint>

#define BNR    1600
#define HD     256
#define SEQ    64
#define NSTEPS 10
#define NCTA   104
#define MT     13

// ------------------------- static device scratch --------------------------
// all operand tensors fp16 (stored/indexed as u32 words = 2 halves)
__device__ uint32_t g_xw  [BNR * SEQ * 128];    // x fp16 [m][t][128w]
__device__ uint32_t g_h0buf[2][BNR * 128];
__device__ uint32_t g_h1buf[2][BNR * 128];
__device__ uint32_t g_htw [BNR * 128];          // LN output fp16
__device__ float    g_hid [BNR * 512];
__device__ uint32_t g_Wre0[1024 * 256];         // fp16, rows (j*4+g), k=[Wih|Whh]
__device__ uint32_t g_Wre1[1024 * 256];
__device__ float    g_bre0[1024];
__device__ float    g_bre1[1024];
__device__ uint32_t g_Wh1 [512 * 128];          // heads layer1 weights fp16
__device__ float    g_bh1 [512];
__device__ unsigned g_barCnt;
__device__ unsigned g_barGen;

// ------------------------------ helpers -----------------------------------
__device__ __forceinline__ void mma_f16(float* d, const uint32_t* a,
                                        uint32_t b0, uint32_t b1) {
    asm volatile(
        "mma.sync.aligned.m16n8k16.row.col.f32.f16.f16.f32 "
        "{%0,%1,%2,%3}, {%4,%5,%6,%7}, {%8,%9}, {%0,%1,%2,%3};"
        : "+f"(d[0]), "+f"(d[1]), "+f"(d[2]), "+f"(d[3])
        : "r"(a[0]), "r"(a[1]), "r"(a[2]), "r"(a[3]), "r"(b0), "r"(b1));
}
__device__ __forceinline__ float sigf(float x) { return 1.0f / (1.0f + __expf(-x)); }

__device__ __forceinline__ void cpa16(uint32_t saddr, const void* g, int sz) {
    asm volatile("cp.async.cg.shared.global [%0], [%1], 16, %2;"
                 :: "r"(saddr), "l"(g), "r"(sz));
}
#define CP_COMMIT() asm volatile("cp.async.commit_group;")

// grid-wide barrier (all NCTA CTAs resident by construction)
__device__ __forceinline__ void gbar() {
    __syncthreads();
    if (threadIdx.x == 0) {
        __threadfence();
        unsigned gen = ((volatile unsigned*)&g_barGen)[0];
        if (atomicAdd(&g_barCnt, 1u) == NCTA - 1) {
            ((volatile unsigned*)&g_barCnt)[0] = 0;
            __threadfence();
            atomicExch(&g_barGen, gen + 1);
        } else {
            while (((volatile unsigned*)&g_barGen)[0] == gen) __nanosleep(32);
        }
        __threadfence();
    }
    __syncthreads();
}

// ------------------------------ setup kernels -----------------------------
// x [16,64,100,256]f32 -> g_xw [m][t][128w] fp16
__global__ void transpose_kernel(const float* __restrict__ x) {
    int id = blockIdx.x * blockDim.x + threadIdx.x;    // BNR*SEQ*32 groups of 8
    if (id >= BNR * SEQ * 32) return;
    int w8 = id & 31;
    int t  = (id >> 5) & 63;
    int m  = id >> 11;
    int b  = m / 100;
    int n  = m - b * 100;
    const float4* src = (const float4*)x + ((((long)(b * SEQ + t) * 100 + n) * 64) + 2 * w8);
    float4 v0 = src[0], v1 = src[1];
    __half2 h0 = __floats2half2_rn(v0.x, v0.y);
    __half2 h1 = __floats2half2_rn(v0.z, v0.w);
    __half2 h2 = __floats2half2_rn(v1.x, v1.y);
    __half2 h3 = __floats2half2_rn(v1.z, v1.w);
    uint4 o;
    o.x = *(uint32_t*)&h0; o.y = *(uint32_t*)&h1;
    o.z = *(uint32_t*)&h2; o.w = *(uint32_t*)&h3;
    ((uint4*)g_xw)[((long)m * SEQ + t) * 32 + w8] = o;
}

__global__ void rearr_w_kernel(const float* __restrict__ Wih,
                               const float* __restrict__ Whh,
                               const float* __restrict__ bih,
                               const float* __restrict__ bhh,
                               uint32_t* __restrict__ Wre,
                               float* __restrict__ bre) {
    int id = blockIdx.x * 256 + threadIdx.x;   // over 1024*256 words
    if (id >= 1024 * 256) return;
    int nre = id >> 8, kw = id & 255;          // kw = word (2 halves)
    int j = nre >> 2, g = nre & 3;
    int srow = g * 256 + j;
    int k = kw * 2;
    float v0, v1;
    if (k < 256) { v0 = Wih[srow * 256 + k];       v1 = Wih[srow * 256 + k + 1]; }
    else         { v0 = Whh[srow * 256 + k - 256]; v1 = Whh[srow * 256 + k - 255]; }
    __half2 h = __floats2half2_rn(v0, v1);
    Wre[id] = *(uint32_t*)&h;
    if (kw == 0) bre[nre] = bih[srow] + bhh[srow];
}

__global__ void rearr_h1_kernel(const float* __restrict__ cw1, const float* __restrict__ cb1,
                                const float* __restrict__ sw1, const float* __restrict__ sb1,
                                const float* __restrict__ lw1, const float* __restrict__ lb1) {
    int id = blockIdx.x * 256 + threadIdx.x;   // 512*128 words
    if (id >= 512 * 128) return;
    int row = id >> 7, kw = id & 127;
    int k = kw * 2;
    const float* w; float b;
    if (row < 128)      { w = cw1 + row * 256;         b = cb1[row]; }
    else if (row < 256) { w = sw1 + (row - 128) * 256; b = sb1[row - 128]; }
    else                { w = lw1 + (row - 256) * 256; b = lb1[row - 256]; }
    __half2 h = __floats2half2_rn(w[k], w[k + 1]);
    g_Wh1[id] = *(uint32_t*)&h;
    if (kw == 0) g_bh1[row] = b;
}

__global__ void zero_state_kernel() {
    int id = blockIdx.x * blockDim.x + threadIdx.x;
    if (id < BNR * 128) { g_h0buf[0][id] = 0u; g_h1buf[0][id] = 0u; }
    if (id == 0) { g_barCnt = 0; }
}

// ---------------------------------------------------------------------------
// smem: 4 stages x (A 128x36w + B 128x36w) + biases  (issue distance 3 < 4)
#define STG_W   9216
#define STG_B   (STG_W * 4)
#define BOF_B   (4608 * 4)
#define BIAS_W  (4 * STG_W)
#define PSMEM   ((4 * STG_W + 320) * 4)

// ---------------- LSTM cell phase (fp16 mma) --------------------------------
// gates[128 x 128 gate-rows], K = 512 halves = 8 chunks of 64 halves (32 words)
__device__ __forceinline__ void cell_phase(
    uint32_t* sm,
    const uint32_t* __restrict__ A0, long lda0,   // word-unit row stride
    const uint32_t* __restrict__ A1,
    const uint32_t* __restrict__ Wsl,             // fp16 weight slice rows (256w)
    const float* biasS, float* cReg,
    uint32_t* __restrict__ Hw,                    // fp16 h output (word base)
    int m0, int j0)
{
    const int tid  = threadIdx.x;
    const int arow = tid >> 3, ac4 = tid & 7;
    const int lane = tid & 31, wid = tid >> 5;
    const int wm = wid >> 2, wn = wid & 3;
    const int g4 = lane >> 2, t4 = lane & 3;

    int mrow[4], msz[4];
#pragma unroll
    for (int q = 0; q < 4; ++q) {
        int m = m0 + arow + 32 * q;
        bool p = m < BNR;
        mrow[q] = p ? m : 0;
        msz[q]  = p ? 16 : 0;
    }
    uint32_t sb = (uint32_t)__cvta_generic_to_shared(sm) +
                  (uint32_t)((arow * 36 + ac4 * 4) * 4);

    float acc[4][4][4];
#pragma unroll
    for (int a = 0; a < 4; ++a)
#pragma unroll
        for (int b = 0; b < 4; ++b)
#pragma unroll
            for (int k = 0; k < 4; ++k) acc[a][b][k] = 0.f;

    auto issue = [&](int c, int st) {
        const uint32_t* ap; long lda; int kk;
        if (c < 4) { ap = A0; lda = lda0; kk = c * 32; }
        else       { ap = A1; lda = 128;  kk = (c - 4) * 32; }
#pragma unroll
        for (int q = 0; q < 4; ++q) {
            cpa16(sb + st * STG_B + q * 4608,
                  ap + (long)mrow[q] * lda + kk + ac4 * 4, msz[q]);
            cpa16(sb + st * STG_B + BOF_B + q * 4608,
                  Wsl + (long)(arow + 32 * q) * 256 + c * 32 + ac4 * 4, 16);
        }
        CP_COMMIT();
    };

    issue(0, 0); issue(1, 1); issue(2, 2);
    for (int c = 0; c < 8; ++c) {
        const int st = c & 3;
        if (c <= 5)      asm volatile("cp.async.wait_group 2;");
        else if (c == 6) asm volatile("cp.async.wait_group 1;");
        else             asm volatile("cp.async.wait_group 0;");
        __syncthreads();
        if (c + 3 < 8) issue(c + 3, (c + 3) & 3);

        const uint32_t* As = sm + st * STG_W;
        const uint32_t* Bs = sm + st * STG_W + 4608;
#pragma unroll
        for (int ks = 0; ks < 32; ks += 8) {
            uint32_t af[4][4], b0[4], b1[4];
#pragma unroll
            for (int mf = 0; mf < 4; ++mf) {
                int r = wm * 64 + mf * 16 + g4;
                af[mf][0] = As[r * 36 + ks + t4];
                af[mf][1] = As[(r + 8) * 36 + ks + t4];
                af[mf][2] = As[r * 36 + ks + t4 + 4];
                af[mf][3] = As[(r + 8) * 36 + ks + t4 + 4];
            }
#pragma unroll
            for (int nf = 0; nf < 4; ++nf) {
                int rb = wn * 32 + nf * 8 + g4;
                b0[nf] = Bs[rb * 36 + ks + t4];
                b1[nf] = Bs[rb * 36 + ks + t4 + 4];
            }
#pragma unroll
            for (int mf = 0; mf < 4; ++mf)
#pragma unroll
                for (int nf = 0; nf < 4; ++nf)
                    mma_f16(acc[mf][nf], af[mf], b0[nf], b1[nf]);
        }
    }

    // LSTM epilogue (c in registers), gate shuffle identical to tf32 version
    const bool oddl = (t4 & 1);
    const unsigned FULL = 0xffffffffu;
    __half* Hh = (__half*)Hw;
#pragma unroll
    for (int mf = 0; mf < 4; ++mf) {
#pragma unroll
        for (int nf = 0; nf < 4; ++nf) {
            float c0v = acc[mf][nf][0], c1v = acc[mf][nf][1];
            float c2v = acc[mf][nf][2], c3v = acc[mf][nf][3];
            float x0 = __shfl_xor_sync(FULL, c0v, 1);
            float x1 = __shfl_xor_sync(FULL, c1v, 1);
            float x2 = __shfl_xor_sync(FULL, c2v, 1);
            float x3 = __shfl_xor_sync(FULL, c3v, 1);
            float gi, gf, gg, go; int rloc;
            if (!oddl) { gi = c0v; gf = c1v; gg = x0;  go = x1;  rloc = g4; }
            else       { gi = x2;  gf = x3;  gg = c2v; go = c3v; rloc = g4 + 8; }
            int rglob = m0 + wm * 64 + mf * 16 + rloc;
            int jl = wn * 8 + nf * 2 + (t4 >> 1);
            gi += biasS[jl * 4 + 0];
            gf += biasS[jl * 4 + 1];
            gg += biasS[jl * 4 + 2];
            go += biasS[jl * 4 + 3];
            float cold = cReg[mf * 4 + nf];
            float cn = sigf(gf) * cold + sigf(gi) * tanhf(gg);
            float hn = sigf(go) * tanhf(cn);
            cReg[mf * 4 + nf] = cn;
            if (rglob < BNR) Hh[(long)rglob * HD + j0 + jl] = __float2half_rn(hn);
        }
    }
}

// ---------------- heads layer-1 phase (fp16 mma) -----------------------------
__device__ __forceinline__ void heads1_phase(
    uint32_t* sm, const uint32_t* __restrict__ A0,
    const uint32_t* __restrict__ Wsl,            // Wh1 rows hn0..hn0+63 (128w)
    const float* biasS, float* __restrict__ hid, int m0, int n0)
{
    const int tid  = threadIdx.x;
    const int arow = tid >> 3, ac4 = tid & 7;
    const int lane = tid & 31, wid = tid >> 5;
    const int wm = wid >> 2, wn = wid & 3;
    const int g4 = lane >> 2, t4 = lane & 3;

    int mrow[4], msz[4];
#pragma unroll
    for (int q = 0; q < 4; ++q) {
        int m = m0 + arow + 32 * q;
        bool p = m < BNR;
        mrow[q] = p ? m : 0;
        msz[q]  = p ? 16 : 0;
    }
    uint32_t sb = (uint32_t)__cvta_generic_to_shared(sm) +
                  (uint32_t)((arow * 36 + ac4 * 4) * 4);

    float acc[4][2][4];
#pragma unroll
    for (int a = 0; a < 4; ++a)
#pragma unroll
        for (int b = 0; b < 2; ++b)
#pragma unroll
            for (int k = 0; k < 4; ++k) acc[a][b][k] = 0.f;

    auto issue = [&](int c, int st) {
        int kk = c * 32;
#pragma unroll
        for (int q = 0; q < 4; ++q)
            cpa16(sb + st * STG_B + q * 4608,
                  A0 + (long)mrow[q] * 128 + kk + ac4 * 4, msz[q]);
#pragma unroll
        for (int q = 0; q < 2; ++q)
            cpa16(sb + st * STG_B + BOF_B + q * 4608,
                  Wsl + (long)(arow + 32 * q) * 128 + kk + ac4 * 4, 16);
        CP_COMMIT();
    };

    issue(0, 0); issue(1, 1); issue(2, 2);
    for (int c = 0; c < 4; ++c) {
        const int st = c & 3;
        if (c <= 1)      asm volatile("cp.async.wait_group 2;");
        else if (c == 2) asm volatile("cp.async.wait_group 1;");
        else             asm volatile("cp.async.wait_group 0;");
        __syncthreads();
        if (c + 3 < 4) issue(c + 3, (c + 3) & 3);

        const uint32_t* As = sm + st * STG_W;
        const uint32_t* Bs = sm + st * STG_W + 4608;
#pragma unroll
        for (int ks = 0; ks < 32; ks += 8) {
            uint32_t af[4][4], b0[2], b1[2];
#pragma unroll
            for (int mf = 0; mf < 4; ++mf) {
                int r = wm * 64 + mf * 16 + g4;
                af[mf][0] = As[r * 36 + ks + t4];
                af[mf][1] = As[(r + 8) * 36 + ks + t4];
                af[mf][2] = As[r * 36 + ks + t4 + 4];
                af[mf][3] = As[(r + 8) * 36 + ks + t4 + 4];
            }
#pragma unroll
            for (int nf = 0; nf < 2; ++nf) {
                int rb = wn * 16 + nf * 8 + g4;
                b0[nf] = Bs[rb * 36 + ks + t4];
                b1[nf] = Bs[rb * 36 + ks + t4 + 4];
            }
#pragma unroll
            for (int mf = 0; mf < 4; ++mf)
#pragma unroll
                for (int nf = 0; nf < 2; ++nf)
                    mma_f16(acc[mf][nf], af[mf], b0[nf], b1[nf]);
        }
    }

#pragma unroll
    for (int mf = 0; mf < 4; ++mf) {
#pragma unroll
        for (int nf = 0; nf < 2; ++nf) {
            int col = wn * 16 + nf * 8 + 2 * t4;
            int r0 = m0 + wm * 64 + mf * 16 + g4;
            float v0 = acc[mf][nf][0] + biasS[col];
            float v1 = acc[mf][nf][1] + biasS[col + 1];
            float v2 = acc[mf][nf][2] + biasS[col];
            float v3 = acc[mf][nf][3] + biasS[col + 1];
            if (r0 < BNR) {
                hid[(long)r0 * 512 + n0 + col]     = fmaxf(v0, 0.f);
                hid[(long)r0 * 512 + n0 + col + 1] = fmaxf(v1, 0.f);
            }
            if (r0 + 8 < BNR) {
                hid[(long)(r0 + 8) * 512 + n0 + col]     = fmaxf(v2, 0.f);
                hid[(long)(r0 + 8) * 512 + n0 + col + 1] = fmaxf(v3, 0.f);
            }
        }
    }
}

// ---------------- LayerNorm phase (warp per row, fp16 in/out) ---------------
__device__ __forceinline__ void ln_phase(
    const uint32_t* __restrict__ h1, const float* __restrict__ gam,
    const float* __restrict__ bet, uint32_t* __restrict__ ht, int cta)
{
    const int wid = threadIdx.x >> 5, lane = threadIdx.x & 31;
    const unsigned FULL = 0xffffffffu;
#pragma unroll
    for (int rep = 0; rep < 2; ++rep) {
        int r = cta * 16 + rep * 8 + wid;
        if (r < BNR) {
            uint4 u = __ldcg((const uint4*)(h1 + (long)r * 128 + lane * 4));
            float v[8];
            __half2 hh;
            hh = *(__half2*)&u.x; v[0] = __low2float(hh); v[1] = __high2float(hh);
            hh = *(__half2*)&u.y; v[2] = __low2float(hh); v[3] = __high2float(hh);
            hh = *(__half2*)&u.z; v[4] = __low2float(hh); v[5] = __high2float(hh);
            hh = *(__half2*)&u.w; v[6] = __low2float(hh); v[7] = __high2float(hh);
            float s1 = 0.f, s2 = 0.f;
#pragma unroll
            for (int i = 0; i < 8; ++i) { s1 += v[i]; s2 += v[i] * v[i]; }
#pragma unroll
            for (int o = 16; o; o >>= 1) {
                s1 += __shfl_xor_sync(FULL, s1, o);
                s2 += __shfl_xor_sync(FULL, s2, o);
            }
            float mean = s1 * (1.f / 256.f);
            float var  = s2 * (1.f / 256.f) - mean * mean;
            float rstd = rsqrtf(var + 1e-5f);
            uint4 o4;
            uint32_t* op = (uint32_t*)&o4;
#pragma unroll
            for (int i = 0; i < 4; ++i) {
                float g0 = __ldg(&gam[lane * 8 + 2 * i]);
                float g1 = __ldg(&gam[lane * 8 + 2 * i + 1]);
                float b0 = __ldg(&bet[lane * 8 + 2 * i]);
                float b1 = __ldg(&bet[lane * 8 + 2 * i + 1]);
                float o0 = (v[2 * i]     - mean) * rstd * g0 + b0;
                float o1 = (v[2 * i + 1] - mean) * rstd * g1 + b1;
                __half2 ho = __floats2half2_rn(o0, o1);
                op[i] = *(uint32_t*)&ho;
            }
            *(uint4*)(ht + (long)r * 128 + lane * 4) = o4;
        }
    }
}

// ---------------- heads layer-2 phase ---------------------------------------
__device__ __forceinline__ void heads2_phase(
    uint32_t* sm, const float* __restrict__ hid,
    const float* __restrict__ cw2, const float* __restrict__ cb2,
    const float* __restrict__ sw2, const float* __restrict__ sb2,
    const float* __restrict__ lw2, const float* __restrict__ lb2,
    float* __restrict__ out, int s, int cta)
{
    float* hs = (float*)sm;                 // 16 rows x 512 f32 = 32KB
    const int tid = threadIdx.x;
    for (int i = tid; i < 16 * 128; i += 256) {
        int rr = i >> 7, c4 = i & 127;
        int r = cta * 16 + rr;
        float4 val = make_float4(0.f, 0.f, 0.f, 0.f);
        if (r < BNR) val = __ldcg((const float4*)(hid + (long)r * 512) + c4);
        ((float4*)hs)[rr * 128 + c4] = val;
    }
    __syncthreads();

    const int wid = tid >> 5, lane = tid & 31;
    const unsigned FULL = 0xffffffffu;
#pragma unroll
    for (int rep = 0; rep < 2; ++rep) {
        int rr = rep * 8 + wid;
        int r = cta * 16 + rr;
        if (r < BNR) {
            int b = r / 100, n = r - b * 100;
            float* ob = out + (((b * NSTEPS + s) * 100 + n) * 22);
            const float* h = hs + rr * 512;
            for (int o = 0; o < 22; ++o) {
                const float* w; float bb; int base, klen;
                if (o < 4)      { w = cw2 + o * 128;       bb = __ldg(&cb2[o]);     base = 0;   klen = 128; }
                else if (o < 6) { w = sw2 + (o - 4) * 128; bb = __ldg(&sb2[o - 4]); base = 128; klen = 128; }
                else            { w = lw2 + (o - 6) * 256; bb = __ldg(&lb2[o - 6]); base = 256; klen = 256; }
                float a = 0.f;
                for (int k = lane; k < klen; k += 32) a += h[base + k] * __ldg(&w[k]);
#pragma unroll
                for (int off = 16; off; off >>= 1) a += __shfl_xor_sync(FULL, a, off);
                if (lane == 0) ob[o] = a + bb;
            }
        }
    }
    __syncthreads();
}

// ---------------------------------------------------------------------------
__global__ void __launch_bounds__(256, 1)
persist_kernel(const float* __restrict__ lng, const float* __restrict__ lnb,
               const float* __restrict__ cw2, const float* __restrict__ cb2,
               const float* __restrict__ sw2, const float* __restrict__ sb2,
               const float* __restrict__ lw2, const float* __restrict__ lb2,
               float* __restrict__ out)
{
    extern __shared__ uint32_t sm[];
    float* bS0 = (float*)(sm + BIAS_W);
    float* bS1 = bS0 + 128;
    float* bSh = bS1 + 128;

    const int tid = threadIdx.x;
    const int cta = blockIdx.x;
    const int mx = cta % MT, ny = cta / MT;
    const int m0  = mx * 128;
    const int nb0 = ny * 128;       // gate-row base
    const int j0  = ny * 32;        // j-col base
    const int hn0 = ny * 64;        // heads1 col base

    if (tid < 128) { bS0[tid] = g_bre0[nb0 + tid]; bS1[tid] = g_bre1[nb0 + tid]; }
    if (tid < 64)  { bSh[tid] = g_bh1[hn0 + tid]; }
    __syncthreads();

    float c0r[16], c1r[16];
#pragma unroll
    for (int i = 0; i < 16; ++i) { c0r[i] = 0.f; c1r[i] = 0.f; }

    const uint32_t* W0sl  = g_Wre0 + (long)nb0 * 256;
    const uint32_t* W1sl  = g_Wre1 + (long)nb0 * 256;
    const uint32_t* Wh1sl = g_Wh1 + (long)hn0 * 128;

    const uint32_t* h0cur = g_h0buf[0]; uint32_t* h0nxt = g_h0buf[1];
    const uint32_t* h1cur = g_h1buf[0]; uint32_t* h1nxt = g_h1buf[1];

    // ---------------- encoder ----------------
    for (int t = 0; t < SEQ; ++t) {
        cell_phase(sm, g_xw + (long)t * 128, (long)SEQ * 128, h0cur,
                   W0sl, bS0, c0r, h0nxt, m0, j0);
        gbar();
        cell_phase(sm, h0nxt, 128, h1cur, W1sl, bS1, c1r, h1nxt, m0, j0);
        gbar();
        const uint32_t* tp;
        tp = h0cur; h0cur = h0nxt; h0nxt = (uint32_t*)tp;
        tp = h1cur; h1cur = h1nxt; h1nxt = (uint32_t*)tp;
    }

    ln_phase(h1cur, lng, lnb, g_htw, cta);
    gbar();

    // ---------------- decoder ----------------
    for (int s = 0; s < NSTEPS; ++s) {
        heads1_phase(sm, g_htw, Wh1sl, bSh, g_hid, m0, hn0);
        gbar();
        heads2_phase(sm, g_hid, cw2, cb2, sw2, sb2, lw2, lb2, out, s, cta);
        if (s < NSTEPS - 1) {
            cell_phase(sm, g_htw, 128, h0cur, W0sl, bS0, c0r, h0nxt, m0, j0);
            gbar();
            cell_phase(sm, h0nxt, 128, h1cur, W1sl, bS1, c1r, h1nxt, m0, j0);
            gbar();
            const uint32_t* tp;
            tp = h0cur; h0cur = h0nxt; h0nxt = (uint32_t*)tp;
            tp = h1cur; h1cur = h1nxt; h1nxt = (uint32_t*)tp;
            ln_phase(h1cur, lng, lnb, g_htw, cta);
            gbar();
        }
    }
}

// ---------------------------------------------------------------------------
extern "C" void kernel_launch(void* const* d_in, const int* in_sizes, int n_in,
                              void* d_out, int out_size)
{
    (void)in_sizes; (void)n_in; (void)out_size;
    const float* x    = (const float*)d_in[0];
    const float* Wih0 = (const float*)d_in[1];
    const float* Whh0 = (const float*)d_in[2];
    const float* bih0 = (const float*)d_in[3];
    const float* bhh0 = (const float*)d_in[4];
    const float* Wih1 = (const float*)d_in[5];
    const float* Whh1 = (const float*)d_in[6];
    const float* bih1 = (const float*)d_in[7];
    const float* bhh1 = (const float*)d_in[8];
    const float* lng  = (const float*)d_in[9];
    const float* lnb  = (const float*)d_in[10];
    const float* cw1  = (const float*)d_in[11];
    const float* cb1  = (const float*)d_in[12];
    const float* cw2  = (const float*)d_in[13];
    const float* cb2  = (const float*)d_in[14];
    const float* sw1  = (const float*)d_in[15];
    const float* sb1  = (const float*)d_in[16];
    const float* sw2  = (const float*)d_in[17];
    const float* sb2  = (const float*)d_in[18];
    const float* lw1  = (const float*)d_in[19];
    const float* lb1  = (const float*)d_in[20];
    const float* lw2  = (const float*)d_in[21];
    const float* lb2  = (const float*)d_in[22];
    float* out = (float*)d_out;

    uint32_t *Wre0, *Wre1;
    float *bre0, *bre1;
    cudaGetSymbolAddress((void**)&Wre0, g_Wre0);
    cudaGetSymbolAddress((void**)&Wre1, g_Wre1);
    cudaGetSymbolAddress((void**)&bre0, g_bre0);
    cudaGetSymbolAddress((void**)&bre1, g_bre1);

    cudaFuncSetAttribute(persist_kernel,
                         cudaFuncAttributeMaxDynamicSharedMemorySize, PSMEM);

    transpose_kernel<<<(BNR * SEQ * 32 + 255) / 256, 256>>>(x);
    rearr_w_kernel<<<1024, 256>>>(Wih0, Whh0, bih0, bhh0, Wre0, bre0);
    rearr_w_kernel<<<1024, 256>>>(Wih1, Whh1, bih1, bhh1, Wre1, bre1);
    rearr_h1_kernel<<<256, 256>>>(cw1, cb1, sw1, sb1, lw1, lb1);
    zero_state_kernel<<<800, 256>>>();

    persist_kernel<<<NCTA, 256, PSMEM>>>(lng, lnb, cw2, cb2, sw2, sb2,
                                         lw2, lb2, out);
}

// round 8
// speedup vs baseline: 2.2759x; 1.2309x over previous
#include <cuda_runtime.h>
#include <cuda_fp16.h>
#include <cstdint>

#define BNR    1600
#define HD     256
#define SEQ    64
#define NSTEPS 10
#define NCTA   104
#define MT     13

// ------------------------- static device scratch --------------------------
// all operand tensors fp16 (stored/indexed as u32 words = 2 halves)
__device__ uint32_t g_xw  [BNR * SEQ * 128];    // x fp16 [m][t][128w]
__device__ uint32_t g_h0buf[2][BNR * 128];
__device__ uint32_t g_h1buf[2][BNR * 128];
__device__ uint32_t g_htw [BNR * 128];          // LN output fp16
__device__ float    g_hid [BNR * 512];
__device__ uint32_t g_Wre0[1024 * 256];         // fp16, rows (j*4+g), k=[Wih|Whh]
__device__ uint32_t g_Wre1[1024 * 256];
__device__ float    g_bre0[1024];
__device__ float    g_bre1[1024];
__device__ uint32_t g_Wh1 [512 * 128];          // heads layer1 weights fp16
__device__ float    g_bh1 [512];
__device__ unsigned g_barCnt;
__device__ unsigned g_barGen;

// ------------------------------ helpers -----------------------------------
__device__ __forceinline__ void mma_f16(float* d, const uint32_t* a,
                                        uint32_t b0, uint32_t b1) {
    asm volatile(
        "mma.sync.aligned.m16n8k16.row.col.f32.f16.f16.f32 "
        "{%0,%1,%2,%3}, {%4,%5,%6,%7}, {%8,%9}, {%0,%1,%2,%3};"
        : "+f"(d[0]), "+f"(d[1]), "+f"(d[2]), "+f"(d[3])
        : "r"(a[0]), "r"(a[1]), "r"(a[2]), "r"(a[3]), "r"(b0), "r"(b1));
}
__device__ __forceinline__ float tanha(float x) {
    float r;
    asm("tanh.approx.f32 %0, %1;" : "=f"(r) : "f"(x));
    return r;
}
__device__ __forceinline__ float sigf(float x) {
    return fmaf(tanha(0.5f * x), 0.5f, 0.5f);
}

__device__ __forceinline__ void cpa16(uint32_t saddr, const void* g, int sz) {
    asm volatile("cp.async.cg.shared.global [%0], [%1], 16, %2;"
                 :: "r"(saddr), "l"(g), "r"(sz));
}
#define CP_COMMIT() asm volatile("cp.async.commit_group;")

// grid-wide barrier (all NCTA CTAs resident by construction)
__device__ __forceinline__ void gbar() {
    __syncthreads();
    if (threadIdx.x == 0) {
        __threadfence();
        unsigned gen = ((volatile unsigned*)&g_barGen)[0];
        if (atomicAdd(&g_barCnt, 1u) == NCTA - 1) {
            ((volatile unsigned*)&g_barCnt)[0] = 0;
            __threadfence();
            atomicExch(&g_barGen, gen + 1);
        } else {
            while (((volatile unsigned*)&g_barGen)[0] == gen) __nanosleep(32);
        }
        __threadfence();
    }
    __syncthreads();
}

// ------------------------------ setup kernels -----------------------------
// x [16,64,100,256]f32 -> g_xw [m][t][128w] fp16
__global__ void transpose_kernel(const float* __restrict__ x) {
    int id = blockIdx.x * blockDim.x + threadIdx.x;    // BNR*SEQ*32 groups of 8
    if (id >= BNR * SEQ * 32) return;
    int w8 = id & 31;
    int t  = (id >> 5) & 63;
    int m  = id >> 11;
    int b  = m / 100;
    int n  = m - b * 100;
    const float4* src = (const float4*)x + ((((long)(b * SEQ + t) * 100 + n) * 64) + 2 * w8);
    float4 v0 = src[0], v1 = src[1];
    __half2 h0 = __floats2half2_rn(v0.x, v0.y);
    __half2 h1 = __floats2half2_rn(v0.z, v0.w);
    __half2 h2 = __floats2half2_rn(v1.x, v1.y);
    __half2 h3 = __floats2half2_rn(v1.z, v1.w);
    uint4 o;
    o.x = *(uint32_t*)&h0; o.y = *(uint32_t*)&h1;
    o.z = *(uint32_t*)&h2; o.w = *(uint32_t*)&h3;
    ((uint4*)g_xw)[((long)m * SEQ + t) * 32 + w8] = o;
}

__global__ void rearr_w_kernel(const float* __restrict__ Wih,
                               const float* __restrict__ Whh,
                               const float* __restrict__ bih,
                               const float* __restrict__ bhh,
                               uint32_t* __restrict__ Wre,
                               float* __restrict__ bre) {
    int id = blockIdx.x * 256 + threadIdx.x;   // over 1024*256 words
    if (id >= 1024 * 256) return;
    int nre = id >> 8, kw = id & 255;          // kw = word (2 halves)
    int j = nre >> 2, g = nre & 3;
    int srow = g * 256 + j;
    int k = kw * 2;
    float v0, v1;
    if (k < 256) { v0 = Wih[srow * 256 + k];       v1 = Wih[srow * 256 + k + 1]; }
    else         { v0 = Whh[srow * 256 + k - 256]; v1 = Whh[srow * 256 + k - 255]; }
    __half2 h = __floats2half2_rn(v0, v1);
    Wre[id] = *(uint32_t*)&h;
    if (kw == 0) bre[nre] = bih[srow] + bhh[srow];
}

__global__ void rearr_h1_kernel(const float* __restrict__ cw1, const float* __restrict__ cb1,
                                const float* __restrict__ sw1, const float* __restrict__ sb1,
                                const float* __restrict__ lw1, const float* __restrict__ lb1) {
    int id = blockIdx.x * 256 + threadIdx.x;   // 512*128 words
    if (id >= 512 * 128) return;
    int row = id >> 7, kw = id & 127;
    int k = kw * 2;
    const float* w; float b;
    if (row < 128)      { w = cw1 + row * 256;         b = cb1[row]; }
    else if (row < 256) { w = sw1 + (row - 128) * 256; b = sb1[row - 128]; }
    else                { w = lw1 + (row - 256) * 256; b = lb1[row - 256]; }
    __half2 h = __floats2half2_rn(w[k], w[k + 1]);
    g_Wh1[id] = *(uint32_t*)&h;
    if (kw == 0) g_bh1[row] = b;
}

__global__ void zero_state_kernel() {
    int id = blockIdx.x * blockDim.x + threadIdx.x;
    if (id < BNR * 128) { g_h0buf[0][id] = 0u; g_h1buf[0][id] = 0u; }
    if (id == 0) { g_barCnt = 0; }
}

// ---------------------------------------------------------------------------
// smem: 4 stages x (A 128x36w + B 128x36w) + biases  (issue distance 3 < 4)
#define STG_W   9216
#define STG_B   (STG_W * 4)
#define BOF_B   (4608 * 4)
#define BIAS_W  (4 * STG_W)
#define PSMEM   ((4 * STG_W + 320) * 4)

// ---------------- LSTM cell phase (fp16 mma) --------------------------------
// gates[128 x 128 gate-rows], K = 512 halves = 8 chunks of 64 halves (32 words)
__device__ __forceinline__ void cell_phase(
    uint32_t* sm,
    const uint32_t* __restrict__ A0, long lda0,   // word-unit row stride
    const uint32_t* __restrict__ A1,
    const uint32_t* __restrict__ Wsl,             // fp16 weight slice rows (256w)
    const float* biasS, float* cReg,
    uint32_t* __restrict__ Hw,                    // fp16 h output (word base)
    int m0, int j0)
{
    const int tid  = threadIdx.x;
    const int arow = tid >> 3, ac4 = tid & 7;
    const int lane = tid & 31, wid = tid >> 5;
    const int wm = wid >> 2, wn = wid & 3;
    const int g4 = lane >> 2, t4 = lane & 3;

    int mrow[4], msz[4];
#pragma unroll
    for (int q = 0; q < 4; ++q) {
        int m = m0 + arow + 32 * q;
        bool p = m < BNR;
        mrow[q] = p ? m : 0;
        msz[q]  = p ? 16 : 0;
    }
    uint32_t sb = (uint32_t)__cvta_generic_to_shared(sm) +
                  (uint32_t)((arow * 36 + ac4 * 4) * 4);

    float acc[4][4][4];
#pragma unroll
    for (int a = 0; a < 4; ++a)
#pragma unroll
        for (int b = 0; b < 4; ++b)
#pragma unroll
            for (int k = 0; k < 4; ++k) acc[a][b][k] = 0.f;

    auto issue = [&](int c, int st) {
        const uint32_t* ap; long lda; int kk;
        if (c < 4) { ap = A0; lda = lda0; kk = c * 32; }
        else       { ap = A1; lda = 128;  kk = (c - 4) * 32; }
#pragma unroll
        for (int q = 0; q < 4; ++q) {
            cpa16(sb + st * STG_B + q * 4608,
                  ap + (long)mrow[q] * lda + kk + ac4 * 4, msz[q]);
            cpa16(sb + st * STG_B + BOF_B + q * 4608,
                  Wsl + (long)(arow + 32 * q) * 256 + c * 32 + ac4 * 4, 16);
        }
        CP_COMMIT();
    };

    issue(0, 0); issue(1, 1); issue(2, 2);
    for (int c = 0; c < 8; ++c) {
        const int st = c & 3;
        if (c <= 5)      asm volatile("cp.async.wait_group 2;");
        else if (c == 6) asm volatile("cp.async.wait_group 1;");
        else             asm volatile("cp.async.wait_group 0;");
        __syncthreads();
        if (c + 3 < 8) issue(c + 3, (c + 3) & 3);

        const uint32_t* As = sm + st * STG_W;
        const uint32_t* Bs = sm + st * STG_W + 4608;
#pragma unroll
        for (int ks = 0; ks < 32; ks += 8) {
            uint32_t af[4][4], b0[4], b1[4];
#pragma unroll
            for (int mf = 0; mf < 4; ++mf) {
                int r = wm * 64 + mf * 16 + g4;
                af[mf][0] = As[r * 36 + ks + t4];
                af[mf][1] = As[(r + 8) * 36 + ks + t4];
                af[mf][2] = As[r * 36 + ks + t4 + 4];
                af[mf][3] = As[(r + 8) * 36 + ks + t4 + 4];
            }
#pragma unroll
            for (int nf = 0; nf < 4; ++nf) {
                int rb = wn * 32 + nf * 8 + g4;
                b0[nf] = Bs[rb * 36 + ks + t4];
                b1[nf] = Bs[rb * 36 + ks + t4 + 4];
            }
#pragma unroll
            for (int mf = 0; mf < 4; ++mf)
#pragma unroll
                for (int nf = 0; nf < 4; ++nf)
                    mma_f16(acc[mf][nf], af[mf], b0[nf], b1[nf]);
        }
    }

    // LSTM epilogue (c in registers), fast tanh.approx activations
    const bool oddl = (t4 & 1);
    const unsigned FULL = 0xffffffffu;
    __half* Hh = (__half*)Hw;
#pragma unroll
    for (int mf = 0; mf < 4; ++mf) {
#pragma unroll
        for (int nf = 0; nf < 4; ++nf) {
            float c0v = acc[mf][nf][0], c1v = acc[mf][nf][1];
            float c2v = acc[mf][nf][2], c3v = acc[mf][nf][3];
            float x0 = __shfl_xor_sync(FULL, c0v, 1);
            float x1 = __shfl_xor_sync(FULL, c1v, 1);
            float x2 = __shfl_xor_sync(FULL, c2v, 1);
            float x3 = __shfl_xor_sync(FULL, c3v, 1);
            float gi, gf, gg, go; int rloc;
            if (!oddl) { gi = c0v; gf = c1v; gg = x0;  go = x1;  rloc = g4; }
            else       { gi = x2;  gf = x3;  gg = c2v; go = c3v; rloc = g4 + 8; }
            int rglob = m0 + wm * 64 + mf * 16 + rloc;
            int jl = wn * 8 + nf * 2 + (t4 >> 1);
            gi += biasS[jl * 4 + 0];
            gf += biasS[jl * 4 + 1];
            gg += biasS[jl * 4 + 2];
            go += biasS[jl * 4 + 3];
            float cold = cReg[mf * 4 + nf];
            float cn = sigf(gf) * cold + sigf(gi) * tanha(gg);
            float hn = sigf(go) * tanha(cn);
            cReg[mf * 4 + nf] = cn;
            if (rglob < BNR) Hh[(long)rglob * HD + j0 + jl] = __float2half_rn(hn);
        }
    }
}

// ---------------- heads layer-1 phase (fp16 mma) -----------------------------
__device__ __forceinline__ void heads1_phase(
    uint32_t* sm, const uint32_t* __restrict__ A0,
    const uint32_t* __restrict__ Wsl,            // Wh1 rows hn0..hn0+63 (128w)
    const float* biasS, float* __restrict__ hid, int m0, int n0)
{
    const int tid  = threadIdx.x;
    const int arow = tid >> 3, ac4 = tid & 7;
    const int lane = tid & 31, wid = tid >> 5;
    const int wm = wid >> 2, wn = wid & 3;
    const int g4 = lane >> 2, t4 = lane & 3;

    int mrow[4], msz[4];
#pragma unroll
    for (int q = 0; q < 4; ++q) {
        int m = m0 + arow + 32 * q;
        bool p = m < BNR;
        mrow[q] = p ? m : 0;
        msz[q]  = p ? 16 : 0;
    }
    uint32_t sb = (uint32_t)__cvta_generic_to_shared(sm) +
                  (uint32_t)((arow * 36 + ac4 * 4) * 4);

    float acc[4][2][4];
#pragma unroll
    for (int a = 0; a < 4; ++a)
#pragma unroll
        for (int b = 0; b < 2; ++b)
#pragma unroll
            for (int k = 0; k < 4; ++k) acc[a][b][k] = 0.f;

    auto issue = [&](int c, int st) {
        int kk = c * 32;
#pragma unroll
        for (int q = 0; q < 4; ++q)
            cpa16(sb + st * STG_B + q * 4608,
                  A0 + (long)mrow[q] * 128 + kk + ac4 * 4, msz[q]);
#pragma unroll
        for (int q = 0; q < 2; ++q)
            cpa16(sb + st * STG_B + BOF_B + q * 4608,
                  Wsl + (long)(arow + 32 * q) * 128 + kk + ac4 * 4, 16);
        CP_COMMIT();
    };

    issue(0, 0); issue(1, 1); issue(2, 2);
    for (int c = 0; c < 4; ++c) {
        const int st = c & 3;
        if (c <= 1)      asm volatile("cp.async.wait_group 2;");
        else if (c == 2) asm volatile("cp.async.wait_group 1;");
        else             asm volatile("cp.async.wait_group 0;");
        __syncthreads();
        if (c + 3 < 4) issue(c + 3, (c + 3) & 3);

        const uint32_t* As = sm + st * STG_W;
        const uint32_t* Bs = sm + st * STG_W + 4608;
#pragma unroll
        for (int ks = 0; ks < 32; ks += 8) {
            uint32_t af[4][4], b0[2], b1[2];
#pragma unroll
            for (int mf = 0; mf < 4; ++mf) {
                int r = wm * 64 + mf * 16 + g4;
                af[mf][0] = As[r * 36 + ks + t4];
                af[mf][1] = As[(r + 8) * 36 + ks + t4];
                af[mf][2] = As[r * 36 + ks + t4 + 4];
                af[mf][3] = As[(r + 8) * 36 + ks + t4 + 4];
            }
#pragma unroll
            for (int nf = 0; nf < 2; ++nf) {
                int rb = wn * 16 + nf * 8 + g4;
                b0[nf] = Bs[rb * 36 + ks + t4];
                b1[nf] = Bs[rb * 36 + ks + t4 + 4];
            }
#pragma unroll
            for (int mf = 0; mf < 4; ++mf)
#pragma unroll
                for (int nf = 0; nf < 2; ++nf)
                    mma_f16(acc[mf][nf], af[mf], b0[nf], b1[nf]);
        }
    }

#pragma unroll
    for (int mf = 0; mf < 4; ++mf) {
#pragma unroll
        for (int nf = 0; nf < 2; ++nf) {
            int col = wn * 16 + nf * 8 + 2 * t4;
            int r0 = m0 + wm * 64 + mf * 16 + g4;
            float v0 = acc[mf][nf][0] + biasS[col];
            float v1 = acc[mf][nf][1] + biasS[col + 1];
            float v2 = acc[mf][nf][2] + biasS[col];
            float v3 = acc[mf][nf][3] + biasS[col + 1];
            if (r0 < BNR) {
                hid[(long)r0 * 512 + n0 + col]     = fmaxf(v0, 0.f);
                hid[(long)r0 * 512 + n0 + col + 1] = fmaxf(v1, 0.f);
            }
            if (r0 + 8 < BNR) {
                hid[(long)(r0 + 8) * 512 + n0 + col]     = fmaxf(v2, 0.f);
                hid[(long)(r0 + 8) * 512 + n0 + col + 1] = fmaxf(v3, 0.f);
            }
        }
    }
}

// ---------------- LayerNorm phase (warp per row, fp16 in/out) ---------------
__device__ __forceinline__ void ln_phase(
    const uint32_t* __restrict__ h1, const float* __restrict__ gam,
    const float* __restrict__ bet, uint32_t* __restrict__ ht, int cta)
{
    const int wid = threadIdx.x >> 5, lane = threadIdx.x & 31;
    const unsigned FULL = 0xffffffffu;
#pragma unroll
    for (int rep = 0; rep < 2; ++rep) {
        int r = cta * 16 + rep * 8 + wid;
        if (r < BNR) {
            uint4 u = __ldcg((const uint4*)(h1 + (long)r * 128 + lane * 4));
            float v[8];
            __half2 hh;
            hh = *(__half2*)&u.x; v[0] = __low2float(hh); v[1] = __high2float(hh);
            hh = *(__half2*)&u.y; v[2] = __low2float(hh); v[3] = __high2float(hh);
            hh = *(__half2*)&u.z; v[4] = __low2float(hh); v[5] = __high2float(hh);
            hh = *(__half2*)&u.w; v[6] = __low2float(hh); v[7] = __high2float(hh);
            float s1 = 0.f, s2 = 0.f;
#pragma unroll
            for (int i = 0; i < 8; ++i) { s1 += v[i]; s2 += v[i] * v[i]; }
#pragma unroll
            for (int o = 16; o; o >>= 1) {
                s1 += __shfl_xor_sync(FULL, s1, o);
                s2 += __shfl_xor_sync(FULL, s2, o);
            }
            float mean = s1 * (1.f / 256.f);
            float var  = s2 * (1.f / 256.f) - mean * mean;
            float rstd = rsqrtf(var + 1e-5f);
            uint4 o4;
            uint32_t* op = (uint32_t*)&o4;
#pragma unroll
            for (int i = 0; i < 4; ++i) {
                float g0 = __ldg(&gam[lane * 8 + 2 * i]);
                float g1 = __ldg(&gam[lane * 8 + 2 * i + 1]);
                float b0 = __ldg(&bet[lane * 8 + 2 * i]);
                float b1 = __ldg(&bet[lane * 8 + 2 * i + 1]);
                float o0 = (v[2 * i]     - mean) * rstd * g0 + b0;
                float o1 = (v[2 * i + 1] - mean) * rstd * g1 + b1;
                __half2 ho = __floats2half2_rn(o0, o1);
                op[i] = *(uint32_t*)&ho;
            }
            *(uint4*)(ht + (long)r * 128 + lane * 4) = o4;
        }
    }
}

// ---------------- heads layer-2 phase ---------------------------------------
__device__ __forceinline__ void heads2_phase(
    uint32_t* sm, const float* __restrict__ hid,
    const float* __restrict__ cw2, const float* __restrict__ cb2,
    const float* __restrict__ sw2, const float* __restrict__ sb2,
    const float* __restrict__ lw2, const float* __restrict__ lb2,
    float* __restrict__ out, int s, int cta)
{
    float* hs = (float*)sm;                 // 16 rows x 512 f32 = 32KB (stage0)
    const int tid = threadIdx.x;
    for (int i = tid; i < 16 * 128; i += 256) {
        int rr = i >> 7, c4 = i & 127;
        int r = cta * 16 + rr;
        float4 val = make_float4(0.f, 0.f, 0.f, 0.f);
        if (r < BNR) val = __ldcg((const float4*)(hid + (long)r * 512) + c4);
        ((float4*)hs)[rr * 128 + c4] = val;
    }
    __syncthreads();

    const int wid = tid >> 5, lane = tid & 31;
    const unsigned FULL = 0xffffffffu;
#pragma unroll
    for (int rep = 0; rep < 2; ++rep) {
        int rr = rep * 8 + wid;
        int r = cta * 16 + rr;
        if (r < BNR) {
            int b = r / 100, n = r - b * 100;
            float* ob = out + (((b * NSTEPS + s) * 100 + n) * 22);
            const float* h = hs + rr * 512;
            for (int o = 0; o < 22; ++o) {
                const float* w; float bb; int base, klen;
                if (o < 4)      { w = cw2 + o * 128;       bb = __ldg(&cb2[o]);     base = 0;   klen = 128; }
                else if (o < 6) { w = sw2 + (o - 4) * 128; bb = __ldg(&sb2[o - 4]); base = 128; klen = 128; }
                else            { w = lw2 + (o - 6) * 256; bb = __ldg(&lb2[o - 6]); base = 256; klen = 256; }
                float a = 0.f;
                for (int k = lane; k < klen; k += 32) a += h[base + k] * __ldg(&w[k]);
#pragma unroll
                for (int off = 16; off; off >>= 1) a += __shfl_xor_sync(FULL, a, off);
                if (lane == 0) ob[o] = a + bb;
            }
        }
    }
    __syncthreads();
}

// ---------------------------------------------------------------------------
__global__ void __launch_bounds__(256, 1)
persist_kernel(const float* __restrict__ lng, const float* __restrict__ lnb,
               const float* __restrict__ cw2, const float* __restrict__ cb2,
               const float* __restrict__ sw2, const float* __restrict__ sb2,
               const float* __restrict__ lw2, const float* __restrict__ lb2,
               float* __restrict__ out)
{
    extern __shared__ uint32_t sm[];
    float* bS0 = (float*)(sm + BIAS_W);
    float* bS1 = bS0 + 128;
    float* bSh = bS1 + 128;

    const int tid = threadIdx.x;
    const int cta = blockIdx.x;
    const int mx = cta % MT, ny = cta / MT;
    const int m0  = mx * 128;
    const int nb0 = ny * 128;       // gate-row base
    const int j0  = ny * 32;        // j-col base
    const int hn0 = ny * 64;        // heads1 col base

    if (tid < 128) { bS0[tid] = g_bre0[nb0 + tid]; bS1[tid] = g_bre1[nb0 + tid]; }
    if (tid < 64)  { bSh[tid] = g_bh1[hn0 + tid]; }
    __syncthreads();

    float c0r[16], c1r[16];
#pragma unroll
    for (int i = 0; i < 16; ++i) { c0r[i] = 0.f; c1r[i] = 0.f; }

    const uint32_t* W0sl  = g_Wre0 + (long)nb0 * 256;
    const uint32_t* W1sl  = g_Wre1 + (long)nb0 * 256;
    const uint32_t* Wh1sl = g_Wh1 + (long)hn0 * 128;

    // ---------------- encoder (software-pipelined: phase t = L0(t)+L1(t-1)) --
    // h0(t) lives in g_h0buf[(t+1)&1]; h1(t) in g_h1buf[(t+1)&1]
    cell_phase(sm, g_xw, (long)SEQ * 128, g_h0buf[0],
               W0sl, bS0, c0r, g_h0buf[1], m0, j0);            // L0(0)
    gbar();
    for (int t = 1; t < SEQ; ++t) {
        cell_phase(sm, g_xw + (long)t * 128, (long)SEQ * 128, g_h0buf[t & 1],
                   W0sl, bS0, c0r, g_h0buf[(t + 1) & 1], m0, j0);      // L0(t)
        cell_phase(sm, g_h0buf[t & 1], 128, g_h1buf[(t + 1) & 1],
                   W1sl, bS1, c1r, g_h1buf[t & 1], m0, j0);            // L1(t-1)
        gbar();
    }
    cell_phase(sm, g_h0buf[0], 128, g_h1buf[1],
               W1sl, bS1, c1r, g_h1buf[0], m0, j0);             // L1(63)
    gbar();
    ln_phase(g_h1buf[0], lng, lnb, g_htw, cta);
    gbar();

    // ---------------- decoder ----------------
    for (int s = 0; s < NSTEPS; ++s) {
        // phase A: heads1(s) + L0d(s)   (both read only g_htw + old state)
        heads1_phase(sm, g_htw, Wh1sl, bSh, g_hid, m0, hn0);
        cell_phase(sm, g_htw, 128, g_h0buf[s & 1],
                   W0sl, bS0, c0r, g_h0buf[(s + 1) & 1], m0, j0);
        gbar();
        // phase B: L1d(s) + heads2(s)
        cell_phase(sm, g_h0buf[(s + 1) & 1], 128, g_h1buf[s & 1],
                   W1sl, bS1, c1r, g_h1buf[(s + 1) & 1], m0, j0);
        heads2_phase(sm, g_hid, cw2, cb2, sw2, sb2, lw2, lb2, out, s, cta);
        if (s < NSTEPS - 1) {
            gbar();
            ln_phase(g_h1buf[(s + 1) & 1], lng, lnb, g_htw, cta);
            gbar();
        }
    }
}

// ---------------------------------------------------------------------------
extern "C" void kernel_launch(void* const* d_in, const int* in_sizes, int n_in,
                              void* d_out, int out_size)
{
    (void)in_sizes; (void)n_in; (void)out_size;
    const float* x    = (const float*)d_in[0];
    const float* Wih0 = (const float*)d_in[1];
    const float* Whh0 = (const float*)d_in[2];
    const float* bih0 = (const float*)d_in[3];
    const float* bhh0 = (const float*)d_in[4];
    const float* Wih1 = (const float*)d_in[5];
    const float* Whh1 = (const float*)d_in[6];
    const float* bih1 = (const float*)d_in[7];
    const float* bhh1 = (const float*)d_in[8];
    const float* lng  = (const float*)d_in[9];
    const float* lnb  = (const float*)d_in[10];
    const float* cw1  = (const float*)d_in[11];
    const float* cb1  = (const float*)d_in[12];
    const float* cw2  = (const float*)d_in[13];
    const float* cb2  = (const float*)d_in[14];
    const float* sw1  = (const float*)d_in[15];
    const float* sb1  = (const float*)d_in[16];
    const float* sw2  = (const float*)d_in[17];
    const float* sb2  = (const float*)d_in[18];
    const float* lw1  = (const float*)d_in[19];
    const float* lb1  = (const float*)d_in[20];
    const float* lw2  = (const float*)d_in[21];
    const float* lb2  = (const float*)d_in[22];
    float* out = (float*)d_out;

    uint32_t *Wre0, *Wre1;
    float *bre0, *bre1;
    cudaGetSymbolAddress((void**)&Wre0, g_Wre0);
    cudaGetSymbolAddress((void**)&Wre1, g_Wre1);
    cudaGetSymbolAddress((void**)&bre0, g_bre0);
    cudaGetSymbolAddress((void**)&bre1, g_bre1);

    cudaFuncSetAttribute(persist_kernel,
                         cudaFuncAttributeMaxDynamicSharedMemorySize, PSMEM);

    transpose_kernel<<<(BNR * SEQ * 32 + 255) / 256, 256>>>(x);
    rearr_w_kernel<<<1024, 256>>>(Wih0, Whh0, bih0, bhh0, Wre0, bre0);
    rearr_w_kernel<<<1024, 256>>>(Wih1, Whh1, bih1, bhh1, Wre1, bre1);
    rearr_h1_kernel<<<256, 256>>>(cw1, cb1, sw1, sb1, lw1, lb1);
    zero_state_kernel<<<800, 256>>>();

    persist_kernel<<<NCTA, 256, PSMEM>>>(lng, lnb, cw2, cb2, sw2, sb2,
                                         lw2, lb2, out);
}

// round 9
// speedup vs baseline: 2.3811x; 1.0463x over previous
#include <cuda_runtime.h>
#include <cuda_fp16.h>
#include <cstdint>

#define BNR    1600
#define HD     256
#define SEQ    64
#define NSTEPS 10
#define NCTA   104
#define MT     13

// ------------------------- static device scratch --------------------------
__device__ uint32_t g_xw  [BNR * SEQ * 128];    // x fp16 [m][t][128w]
__device__ uint32_t g_h0buf[2][BNR * 128];
__device__ uint32_t g_h1buf[2][BNR * 128];
__device__ uint32_t g_htw [BNR * 128];          // LN output fp16
__device__ float    g_hid [BNR * 512];
__device__ uint32_t g_Wre0[1024 * 256];         // fp16, rows (j*4+g), k=[Wih|Whh]
__device__ uint32_t g_Wre1[1024 * 256];
__device__ float    g_bre0[1024];
__device__ float    g_bre1[1024];
__device__ uint32_t g_Wh1 [512 * 128];          // heads layer1 weights fp16
__device__ float    g_bh1 [512];
__device__ unsigned g_grpCnt[MT * 32];          // per-group barrier (128B stride)
__device__ unsigned g_grpGen[MT * 32];

// ------------------------------ helpers -----------------------------------
__device__ __forceinline__ void mma_f16(float* d, const uint32_t* a,
                                        uint32_t b0, uint32_t b1) {
    asm volatile(
        "mma.sync.aligned.m16n8k16.row.col.f32.f16.f16.f32 "
        "{%0,%1,%2,%3}, {%4,%5,%6,%7}, {%8,%9}, {%0,%1,%2,%3};"
        : "+f"(d[0]), "+f"(d[1]), "+f"(d[2]), "+f"(d[3])
        : "r"(a[0]), "r"(a[1]), "r"(a[2]), "r"(a[3]), "r"(b0), "r"(b1));
}
__device__ __forceinline__ void ldm_x4(uint32_t& r0, uint32_t& r1,
                                       uint32_t& r2, uint32_t& r3,
                                       uint32_t addr) {
    asm volatile("ldmatrix.sync.aligned.m8n8.x4.shared.b16 {%0,%1,%2,%3}, [%4];"
                 : "=r"(r0), "=r"(r1), "=r"(r2), "=r"(r3) : "r"(addr));
}
__device__ __forceinline__ float tanha(float x) {
    float r;
    asm("tanh.approx.f32 %0, %1;" : "=f"(r) : "f"(x));
    return r;
}
__device__ __forceinline__ float sigf(float x) {
    return fmaf(tanha(0.5f * x), 0.5f, 0.5f);
}
__device__ __forceinline__ void cpa16(uint32_t saddr, const void* g, int sz) {
    asm volatile("cp.async.cg.shared.global [%0], [%1], 16, %2;"
                 :: "r"(saddr), "l"(g), "r"(sz));
}
#define CP_COMMIT() asm volatile("cp.async.commit_group;")

// per-group barrier: 8 CTAs sharing mx group
__device__ __forceinline__ void gbar(int grp) {
    __syncthreads();
    if (threadIdx.x == 0) {
        __threadfence();
        unsigned* cnt = &g_grpCnt[grp * 32];
        unsigned* gen = &g_grpGen[grp * 32];
        unsigned g = *(volatile unsigned*)gen;
        if (atomicAdd(cnt, 1u) == 7u) {
            *(volatile unsigned*)cnt = 0u;
            __threadfence();
            atomicExch(gen, g + 1);
        } else {
            while (*(volatile unsigned*)gen == g) __nanosleep(32);
        }
        __threadfence();
    }
    __syncthreads();
}

// ------------------------------ setup kernels -----------------------------
__global__ void transpose_kernel(const float* __restrict__ x) {
    int id = blockIdx.x * blockDim.x + threadIdx.x;    // BNR*SEQ*32 groups of 8
    if (id >= BNR * SEQ * 32) return;
    int w8 = id & 31;
    int t  = (id >> 5) & 63;
    int m  = id >> 11;
    int b  = m / 100;
    int n  = m - b * 100;
    const float4* src = (const float4*)x + ((((long)(b * SEQ + t) * 100 + n) * 64) + 2 * w8);
    float4 v0 = src[0], v1 = src[1];
    __half2 h0 = __floats2half2_rn(v0.x, v0.y);
    __half2 h1 = __floats2half2_rn(v0.z, v0.w);
    __half2 h2 = __floats2half2_rn(v1.x, v1.y);
    __half2 h3 = __floats2half2_rn(v1.z, v1.w);
    uint4 o;
    o.x = *(uint32_t*)&h0; o.y = *(uint32_t*)&h1;
    o.z = *(uint32_t*)&h2; o.w = *(uint32_t*)&h3;
    ((uint4*)g_xw)[((long)m * SEQ + t) * 32 + w8] = o;
}

__global__ void rearr_w_kernel(const float* __restrict__ Wih,
                               const float* __restrict__ Whh,
                               const float* __restrict__ bih,
                               const float* __restrict__ bhh,
                               uint32_t* __restrict__ Wre,
                               float* __restrict__ bre) {
    int id = blockIdx.x * 256 + threadIdx.x;   // over 1024*256 words
    if (id >= 1024 * 256) return;
    int nre = id >> 8, kw = id & 255;
    int j = nre >> 2, g = nre & 3;
    int srow = g * 256 + j;
    int k = kw * 2;
    float v0, v1;
    if (k < 256) { v0 = Wih[srow * 256 + k];       v1 = Wih[srow * 256 + k + 1]; }
    else         { v0 = Whh[srow * 256 + k - 256]; v1 = Whh[srow * 256 + k - 255]; }
    __half2 h = __floats2half2_rn(v0, v1);
    Wre[id] = *(uint32_t*)&h;
    if (kw == 0) bre[nre] = bih[srow] + bhh[srow];
}

__global__ void rearr_h1_kernel(const float* __restrict__ cw1, const float* __restrict__ cb1,
                                const float* __restrict__ sw1, const float* __restrict__ sb1,
                                const float* __restrict__ lw1, const float* __restrict__ lb1) {
    int id = blockIdx.x * 256 + threadIdx.x;   // 512*128 words
    if (id >= 512 * 128) return;
    int row = id >> 7, kw = id & 127;
    int k = kw * 2;
    const float* w; float b;
    if (row < 128)      { w = cw1 + row * 256;         b = cb1[row]; }
    else if (row < 256) { w = sw1 + (row - 128) * 256; b = sb1[row - 128]; }
    else                { w = lw1 + (row - 256) * 256; b = lb1[row - 256]; }
    __half2 h = __floats2half2_rn(w[k], w[k + 1]);
    g_Wh1[id] = *(uint32_t*)&h;
    if (kw == 0) g_bh1[row] = b;
}

__global__ void zero_state_kernel() {
    int id = blockIdx.x * blockDim.x + threadIdx.x;
    if (id < BNR * 128) { g_h0buf[0][id] = 0u; g_h1buf[0][id] = 0u; }
    if (id < MT * 32) { g_grpCnt[id] = 0u; g_grpGen[id] = 0u; }
}

// ---------------------------------------------------------------------------
// smem: 4 stages x (A 128x36w + B 128x36w) + biases  (issue distance 3 < 4)
#define STG_W   9216
#define STG_B   (STG_W * 4)
#define BOF_B   (4608 * 4)
#define BIAS_W  (4 * STG_W)
#define PSMEM   ((4 * STG_W + 320) * 4)
#define ROWB    144                    /* 36 words * 4 bytes */

// ---------------- LSTM cell phase (fp16 mma + ldmatrix) --------------------
__device__ __forceinline__ void cell_phase(
    uint32_t* sm,
    const uint32_t* __restrict__ A0, long lda0,   // word-unit row stride
    const uint32_t* __restrict__ A1,
    const uint32_t* __restrict__ Wsl,             // fp16 weight slice rows (256w)
    const float* biasS, float* cReg,
    uint32_t* __restrict__ Hw,                    // fp16 h output (word base)
    int m0, int j0)
{
    const int tid  = threadIdx.x;
    const int arow = tid >> 3, ac4 = tid & 7;
    const int lane = tid & 31, wid = tid >> 5;
    const int wm = wid >> 2, wn = wid & 3;
    const int g4 = lane >> 2, t4 = lane & 3;

    int mrow[4], msz[4];
#pragma unroll
    for (int q = 0; q < 4; ++q) {
        int m = m0 + arow + 32 * q;
        bool p = m < BNR;
        mrow[q] = p ? m : 0;
        msz[q]  = p ? 16 : 0;
    }
    const uint32_t sbase = (uint32_t)__cvta_generic_to_shared(sm);
    uint32_t sb = sbase + (uint32_t)((arow * 36 + ac4 * 4) * 4);

    // ldmatrix per-lane base addresses (stage/ks added in loop)
    const uint32_t aPre = sbase +
        (uint32_t)((wm * 64 + (lane & 7) + ((lane >> 3) & 1) * 8) * ROWB +
                   (lane >> 4) * 16);
    const uint32_t bPre = sbase + BOF_B +
        (uint32_t)((wn * 32 + ((lane >> 4) & 1) * 8 + (lane & 7)) * ROWB +
                   ((lane >> 3) & 1) * 16);

    float acc[4][4][4];
#pragma unroll
    for (int a = 0; a < 4; ++a)
#pragma unroll
        for (int b = 0; b < 4; ++b)
#pragma unroll
            for (int k = 0; k < 4; ++k) acc[a][b][k] = 0.f;

    auto issue = [&](int c, int st) {
        const uint32_t* ap; long lda; int kk;
        if (c < 4) { ap = A0; lda = lda0; kk = c * 32; }
        else       { ap = A1; lda = 128;  kk = (c - 4) * 32; }
#pragma unroll
        for (int q = 0; q < 4; ++q) {
            cpa16(sb + st * STG_B + q * 4608,
                  ap + (long)mrow[q] * lda + kk + ac4 * 4, msz[q]);
            cpa16(sb + st * STG_B + BOF_B + q * 4608,
                  Wsl + (long)(arow + 32 * q) * 256 + c * 32 + ac4 * 4, 16);
        }
        CP_COMMIT();
    };

    issue(0, 0); issue(1, 1); issue(2, 2);
    for (int c = 0; c < 8; ++c) {
        const int st = c & 3;
        if (c <= 5)      asm volatile("cp.async.wait_group 2;");
        else if (c == 6) asm volatile("cp.async.wait_group 1;");
        else             asm volatile("cp.async.wait_group 0;");
        __syncthreads();
        if (c + 3 < 8) issue(c + 3, (c + 3) & 3);

#pragma unroll
        for (int ks = 0; ks < 32; ks += 8) {
            uint32_t af[4][4], b0[4], b1[4];
            uint32_t ab = aPre + st * STG_B + ks * 4;
            uint32_t bb = bPre + st * STG_B + ks * 4;
            ldm_x4(af[0][0], af[0][1], af[0][2], af[0][3], ab);
            ldm_x4(af[1][0], af[1][1], af[1][2], af[1][3], ab + 16 * ROWB);
            ldm_x4(af[2][0], af[2][1], af[2][2], af[2][3], ab + 32 * ROWB);
            ldm_x4(af[3][0], af[3][1], af[3][2], af[3][3], ab + 48 * ROWB);
            ldm_x4(b0[0], b1[0], b0[1], b1[1], bb);
            ldm_x4(b0[2], b1[2], b0[3], b1[3], bb + 16 * ROWB);
#pragma unroll
            for (int mf = 0; mf < 4; ++mf)
#pragma unroll
                for (int nf = 0; nf < 4; ++nf)
                    mma_f16(acc[mf][nf], af[mf], b0[nf], b1[nf]);
        }
    }

    // LSTM epilogue (c in registers), fast tanh.approx activations
    const bool oddl = (t4 & 1);
    const unsigned FULL = 0xffffffffu;
    __half* Hh = (__half*)Hw;
#pragma unroll
    for (int mf = 0; mf < 4; ++mf) {
#pragma unroll
        for (int nf = 0; nf < 4; ++nf) {
            float c0v = acc[mf][nf][0], c1v = acc[mf][nf][1];
            float c2v = acc[mf][nf][2], c3v = acc[mf][nf][3];
            float x0 = __shfl_xor_sync(FULL, c0v, 1);
            float x1 = __shfl_xor_sync(FULL, c1v, 1);
            float x2 = __shfl_xor_sync(FULL, c2v, 1);
            float x3 = __shfl_xor_sync(FULL, c3v, 1);
            float gi, gf, gg, go; int rloc;
            if (!oddl) { gi = c0v; gf = c1v; gg = x0;  go = x1;  rloc = g4; }
            else       { gi = x2;  gf = x3;  gg = c2v; go = c3v; rloc = g4 + 8; }
            int rglob = m0 + wm * 64 + mf * 16 + rloc;
            int jl = wn * 8 + nf * 2 + (t4 >> 1);
            gi += biasS[jl * 4 + 0];
            gf += biasS[jl * 4 + 1];
            gg += biasS[jl * 4 + 2];
            go += biasS[jl * 4 + 3];
            float cold = cReg[mf * 4 + nf];
            float cn = sigf(gf) * cold + sigf(gi) * tanha(gg);
            float hn = sigf(go) * tanha(cn);
            cReg[mf * 4 + nf] = cn;
            if (rglob < BNR) Hh[(long)rglob * HD + j0 + jl] = __float2half_rn(hn);
        }
    }
}

// ---------------- heads layer-1 phase (fp16 mma + ldmatrix) ------------------
__device__ __forceinline__ void heads1_phase(
    uint32_t* sm, const uint32_t* __restrict__ A0,
    const uint32_t* __restrict__ Wsl,            // Wh1 rows hn0..hn0+63 (128w)
    const float* biasS, float* __restrict__ hid, int m0, int n0)
{
    const int tid  = threadIdx.x;
    const int arow = tid >> 3, ac4 = tid & 7;
    const int lane = tid & 31, wid = tid >> 5;
    const int wm = wid >> 2, wn = wid & 3;
    const int g4 = lane >> 2, t4 = lane & 3;

    int mrow[4], msz[4];
#pragma unroll
    for (int q = 0; q < 4; ++q) {
        int m = m0 + arow + 32 * q;
        bool p = m < BNR;
        mrow[q] = p ? m : 0;
        msz[q]  = p ? 16 : 0;
    }
    const uint32_t sbase = (uint32_t)__cvta_generic_to_shared(sm);
    uint32_t sb = sbase + (uint32_t)((arow * 36 + ac4 * 4) * 4);

    const uint32_t aPre = sbase +
        (uint32_t)((wm * 64 + (lane & 7) + ((lane >> 3) & 1) * 8) * ROWB +
                   (lane >> 4) * 16);
    const uint32_t bPre = sbase + BOF_B +
        (uint32_t)((wn * 16 + ((lane >> 4) & 1) * 8 + (lane & 7)) * ROWB +
                   ((lane >> 3) & 1) * 16);

    float acc[4][2][4];
#pragma unroll
    for (int a = 0; a < 4; ++a)
#pragma unroll
        for (int b = 0; b < 2; ++b)
#pragma unroll
            for (int k = 0; k < 4; ++k) acc[a][b][k] = 0.f;

    auto issue = [&](int c, int st) {
        int kk = c * 32;
#pragma unroll
        for (int q = 0; q < 4; ++q)
            cpa16(sb + st * STG_B + q * 4608,
                  A0 + (long)mrow[q] * 128 + kk + ac4 * 4, msz[q]);
#pragma unroll
        for (int q = 0; q < 2; ++q)
            cpa16(sb + st * STG_B + BOF_B + q * 4608,
                  Wsl + (long)(arow + 32 * q) * 128 + kk + ac4 * 4, 16);
        CP_COMMIT();
    };

    issue(0, 0); issue(1, 1); issue(2, 2);
    for (int c = 0; c < 4; ++c) {
        const int st = c & 3;
        if (c <= 1)      asm volatile("cp.async.wait_group 2;");
        else if (c == 2) asm volatile("cp.async.wait_group 1;");
        else             asm volatile("cp.async.wait_group 0;");
        __syncthreads();
        if (c + 3 < 4) issue(c + 3, (c + 3) & 3);

#pragma unroll
        for (int ks = 0; ks < 32; ks += 8) {
            uint32_t af[4][4], b0[2], b1[2];
            uint32_t ab = aPre + st * STG_B + ks * 4;
            uint32_t bb = bPre + st * STG_B + ks * 4;
            ldm_x4(af[0][0], af[0][1], af[0][2], af[0][3], ab);
            ldm_x4(af[1][0], af[1][1], af[1][2], af[1][3], ab + 16 * ROWB);
            ldm_x4(af[2][0], af[2][1], af[2][2], af[2][3], ab + 32 * ROWB);
            ldm_x4(af[3][0], af[3][1], af[3][2], af[3][3], ab + 48 * ROWB);
            ldm_x4(b0[0], b1[0], b0[1], b1[1], bb);
#pragma unroll
            for (int mf = 0; mf < 4; ++mf)
#pragma unroll
                for (int nf = 0; nf < 2; ++nf)
                    mma_f16(acc[mf][nf], af[mf], b0[nf], b1[nf]);
        }
    }

#pragma unroll
    for (int mf = 0; mf < 4; ++mf) {
#pragma unroll
        for (int nf = 0; nf < 2; ++nf) {
            int col = wn * 16 + nf * 8 + 2 * t4;
            int r0 = m0 + wm * 64 + mf * 16 + g4;
            float v0 = acc[mf][nf][0] + biasS[col];
            float v1 = acc[mf][nf][1] + biasS[col + 1];
            float v2 = acc[mf][nf][2] + biasS[col];
            float v3 = acc[mf][nf][3] + biasS[col + 1];
            if (r0 < BNR) {
                hid[(long)r0 * 512 + n0 + col]     = fmaxf(v0, 0.f);
                hid[(long)r0 * 512 + n0 + col + 1] = fmaxf(v1, 0.f);
            }
            if (r0 + 8 < BNR) {
                hid[(long)(r0 + 8) * 512 + n0 + col]     = fmaxf(v2, 0.f);
                hid[(long)(r0 + 8) * 512 + n0 + col + 1] = fmaxf(v3, 0.f);
            }
        }
    }
}

// ---------------- LayerNorm phase (warp per row, group-local rows) ----------
__device__ __forceinline__ void ln_phase(
    const uint32_t* __restrict__ h1, const float* __restrict__ gam,
    const float* __restrict__ bet, uint32_t* __restrict__ ht, int rowbase)
{
    const int wid = threadIdx.x >> 5, lane = threadIdx.x & 31;
    const unsigned FULL = 0xffffffffu;
#pragma unroll
    for (int rep = 0; rep < 2; ++rep) {
        int r = rowbase + rep * 8 + wid;
        if (r < BNR) {
            uint4 u = __ldcg((const uint4*)(h1 + (long)r * 128 + lane * 4));
            float v[8];
            __half2 hh;
            hh = *(__half2*)&u.x; v[0] = __low2float(hh); v[1] = __high2float(hh);
            hh = *(__half2*)&u.y; v[2] = __low2float(hh); v[3] = __high2float(hh);
            hh = *(__half2*)&u.z; v[4] = __low2float(hh); v[5] = __high2float(hh);
            hh = *(__half2*)&u.w; v[6] = __low2float(hh); v[7] = __high2float(hh);
            float s1 = 0.f, s2 = 0.f;
#pragma unroll
            for (int i = 0; i < 8; ++i) { s1 += v[i]; s2 += v[i] * v[i]; }
#pragma unroll
            for (int o = 16; o; o >>= 1) {
                s1 += __shfl_xor_sync(FULL, s1, o);
                s2 += __shfl_xor_sync(FULL, s2, o);
            }
            float mean = s1 * (1.f / 256.f);
            float var  = s2 * (1.f / 256.f) - mean * mean;
            float rstd = rsqrtf(var + 1e-5f);
            uint4 o4;
            uint32_t* op = (uint32_t*)&o4;
#pragma unroll
            for (int i = 0; i < 4; ++i) {
                float g0 = __ldg(&gam[lane * 8 + 2 * i]);
                float g1 = __ldg(&gam[lane * 8 + 2 * i + 1]);
                float b0 = __ldg(&bet[lane * 8 + 2 * i]);
                float b1 = __ldg(&bet[lane * 8 + 2 * i + 1]);
                float o0 = (v[2 * i]     - mean) * rstd * g0 + b0;
                float o1 = (v[2 * i + 1] - mean) * rstd * g1 + b1;
                __half2 ho = __floats2half2_rn(o0, o1);
                op[i] = *(uint32_t*)&ho;
            }
            *(uint4*)(ht + (long)r * 128 + lane * 4) = o4;
        }
    }
}

// ---------------- heads layer-2 phase (group-local rows) --------------------
__device__ __forceinline__ void heads2_phase(
    uint32_t* sm, const float* __restrict__ hid,
    const float* __restrict__ cw2, const float* __restrict__ cb2,
    const float* __restrict__ sw2, const float* __restrict__ sb2,
    const float* __restrict__ lw2, const float* __restrict__ lb2,
    float* __restrict__ out, int s, int rowbase)
{
    float* hs = (float*)sm;                 // 16 rows x 512 f32 = 32KB (stage0)
    const int tid = threadIdx.x;
    for (int i = tid; i < 16 * 128; i += 256) {
        int rr = i >> 7, c4 = i & 127;
        int r = rowbase + rr;
        float4 val = make_float4(0.f, 0.f, 0.f, 0.f);
        if (r < BNR) val = __ldcg((const float4*)(hid + (long)r * 512) + c4);
        ((float4*)hs)[rr * 128 + c4] = val;
    }
    __syncthreads();

    const int wid = tid >> 5, lane = tid & 31;
    const unsigned FULL = 0xffffffffu;
#pragma unroll
    for (int rep = 0; rep < 2; ++rep) {
        int rr = rep * 8 + wid;
        int r = rowbase + rr;
        if (r < BNR) {
            int b = r / 100, n = r - b * 100;
            float* ob = out + (((b * NSTEPS + s) * 100 + n) * 22);
            const float* h = hs + rr * 512;
            for (int o = 0; o < 22; ++o) {
                const float* w; float bb; int base, klen;
                if (o < 4)      { w = cw2 + o * 128;       bb = __ldg(&cb2[o]);     base = 0;   klen = 128; }
                else if (o < 6) { w = sw2 + (o - 4) * 128; bb = __ldg(&sb2[o - 4]); base = 128; klen = 128; }
                else            { w = lw2 + (o - 6) * 256; bb = __ldg(&lb2[o - 6]); base = 256; klen = 256; }
                float a = 0.f;
                for (int k = lane; k < klen; k += 32) a += h[base + k] * __ldg(&w[k]);
#pragma unroll
                for (int off = 16; off; off >>= 1) a += __shfl_xor_sync(FULL, a, off);
                if (lane == 0) ob[o] = a + bb;
            }
        }
    }
    __syncthreads();
}

// ---------------------------------------------------------------------------
__global__ void __launch_bounds__(256, 1)
persist_kernel(const float* __restrict__ lng, const float* __restrict__ lnb,
               const float* __restrict__ cw2, const float* __restrict__ cb2,
               const float* __restrict__ sw2, const float* __restrict__ sb2,
               const float* __restrict__ lw2, const float* __restrict__ lb2,
               float* __restrict__ out)
{
    extern __shared__ uint32_t sm[];
    float* bS0 = (float*)(sm + BIAS_W);
    float* bS1 = bS0 + 128;
    float* bSh = bS1 + 128;

    const int tid = threadIdx.x;
    const int cta = blockIdx.x;
    const int mx = cta % MT, ny = cta / MT;
    const int m0  = mx * 128;
    const int nb0 = ny * 128;           // gate-row base
    const int j0  = ny * 32;            // j-col base
    const int hn0 = ny * 64;            // heads1 col base
    const int rowbase = m0 + ny * 16;   // LN/heads2 group-local rows

    if (tid < 128) { bS0[tid] = g_bre0[nb0 + tid]; bS1[tid] = g_bre1[nb0 + tid]; }
    if (tid < 64)  { bSh[tid] = g_bh1[hn0 + tid]; }
    __syncthreads();

    float c0r[16], c1r[16];
#pragma unroll
    for (int i = 0; i < 16; ++i) { c0r[i] = 0.f; c1r[i] = 0.f; }

    const uint32_t* W0sl  = g_Wre0 + (long)nb0 * 256;
    const uint32_t* W1sl  = g_Wre1 + (long)nb0 * 256;
    const uint32_t* Wh1sl = g_Wh1 + (long)hn0 * 128;

    // ---------------- encoder (software-pipelined: phase t = L0(t)+L1(t-1)) --
    cell_phase(sm, g_xw, (long)SEQ * 128, g_h0buf[0],
               W0sl, bS0, c0r, g_h0buf[1], m0, j0);            // L0(0)
    gbar(mx);
    for (int t = 1; t < SEQ; ++t) {
        cell_phase(sm, g_xw + (long)t * 128, (long)SEQ * 128, g_h0buf[t & 1],
                   W0sl, bS0, c0r, g_h0buf[(t + 1) & 1], m0, j0);      // L0(t)
        cell_phase(sm, g_h0buf[t & 1], 128, g_h1buf[(t + 1) & 1],
                   W1sl, bS1, c1r, g_h1buf[t & 1], m0, j0);            // L1(t-1)
        gbar(mx);
    }
    cell_phase(sm, g_h0buf[0], 128, g_h1buf[1],
               W1sl, bS1, c1r, g_h1buf[0], m0, j0);             // L1(63)
    gbar(mx);
    ln_phase(g_h1buf[0], lng, lnb, g_htw, rowbase);
    gbar(mx);

    // ---------------- decoder ----------------
    for (int s = 0; s < NSTEPS; ++s) {
        // phase A: heads1(s) + L0d(s)   (both read only g_htw + old state)
        heads1_phase(sm, g_htw, Wh1sl, bSh, g_hid, m0, hn0);
        cell_phase(sm, g_htw, 128, g_h0buf[s & 1],
                   W0sl, bS0, c0r, g_h0buf[(s + 1) & 1], m0, j0);
        gbar(mx);
        // phase B: L1d(s) + heads2(s)
        cell_phase(sm, g_h0buf[(s + 1) & 1], 128, g_h1buf[s & 1],
                   W1sl, bS1, c1r, g_h1buf[(s + 1) & 1], m0, j0);
        heads2_phase(sm, g_hid, cw2, cb2, sw2, sb2, lw2, lb2, out, s, rowbase);
        if (s < NSTEPS - 1) {
            gbar(mx);
            ln_phase(g_h1buf[(s + 1) & 1], lng, lnb, g_htw, rowbase);
            gbar(mx);
        }
    }
}

// ---------------------------------------------------------------------------
extern "C" void kernel_launch(void* const* d_in, const int* in_sizes, int n_in,
                              void* d_out, int out_size)
{
    (void)in_sizes; (void)n_in; (void)out_size;
    const float* x    = (const float*)d_in[0];
    const float* Wih0 = (const float*)d_in[1];
    const float* Whh0 = (const float*)d_in[2];
    const float* bih0 = (const float*)d_in[3];
    const float* bhh0 = (const float*)d_in[4];
    const float* Wih1 = (const float*)d_in[5];
    const float* Whh1 = (const float*)d_in[6];
    const float* bih1 = (const float*)d_in[7];
    const float* bhh1 = (const float*)d_in[8];
    const float* lng  = (const float*)d_in[9];
    const float* lnb  = (const float*)d_in[10];
    const float* cw1  = (const float*)d_in[11];
    const float* cb1  = (const float*)d_in[12];
    const float* cw2  = (const float*)d_in[13];
    const float* cb2  = (const float*)d_in[14];
    const float* sw1  = (const float*)d_in[15];
    const float* sb1  = (const float*)d_in[16];
    const float* sw2  = (const float*)d_in[17];
    const float* sb2  = (const float*)d_in[18];
    const float* lw1  = (const float*)d_in[19];
    const float* lb1  = (const float*)d_in[20];
    const float* lw2  = (const float*)d_in[21];
    const float* lb2  = (const float*)d_in[22];
    float* out = (float*)d_out;

    uint32_t *Wre0, *Wre1;
    float *bre0, *bre1;
    cudaGetSymbolAddress((void**)&Wre0, g_Wre0);
    cudaGetSymbolAddress((void**)&Wre1, g_Wre1);
    cudaGetSymbolAddress((void**)&bre0, g_bre0);
    cudaGetSymbolAddress((void**)&bre1, g_bre1);

    cudaFuncSetAttribute(persist_kernel,
                         cudaFuncAttributeMaxDynamicSharedMemorySize, PSMEM);

    transpose_kernel<<<(BNR * SEQ * 32 + 255) / 256, 256>>>(x);
    rearr_w_kernel<<<1024, 256>>>(Wih0, Whh0, bih0, bhh0, Wre0, bre0);
    rearr_w_kernel<<<1024, 256>>>(Wih1, Whh1, bih1, bhh1, Wre1, bre1);
    rearr_h1_kernel<<<256, 256>>>(cw1, cb1, sw1, sb1, lw1, lb1);
    zero_state_kernel<<<800, 256>>>();

    persist_kernel<<<NCTA, 256, PSMEM>>>(lng, lnb, cw2, cb2, sw2, sb2,
                                         lw2, lb2, out);
}

// round 10
// speedup vs baseline: 2.5741x; 1.0810x over previous
#include <cuda_runtime.h>
#include <cuda_fp16.h>
#include <cstdint>

#define BNR    1600
#define HD     256
#define SEQ    64
#define NSTEPS 10
#define NCTA   104
#define MT     13

// ------------------------- static device scratch --------------------------
__device__ uint32_t g_xw  [BNR * SEQ * 128];    // x fp16 [m][t][128w]
__device__ uint32_t g_h0buf[2][BNR * 128];
__device__ uint32_t g_h1buf[2][BNR * 128];
__device__ uint32_t g_htw [BNR * 128];          // LN output fp16
__device__ float    g_hid [BNR * 512];
__device__ uint32_t g_Wre0[1024 * 256];         // fp16, rows (j*4+g), k=[Wih|Whh]
__device__ uint32_t g_Wre1[1024 * 256];
__device__ float    g_bre0[1024];
__device__ float    g_bre1[1024];
__device__ uint32_t g_Wh1 [512 * 128];          // heads layer1 weights fp16
__device__ float    g_bh1 [512];
__device__ unsigned g_grpCnt[MT * 32];          // per-group barrier (128B stride)
__device__ unsigned g_grpGen[MT * 32];

// ------------------------------ helpers -----------------------------------
__device__ __forceinline__ void mma_f16(float* d, const uint32_t* a,
                                        uint32_t b0, uint32_t b1) {
    asm volatile(
        "mma.sync.aligned.m16n8k16.row.col.f32.f16.f16.f32 "
        "{%0,%1,%2,%3}, {%4,%5,%6,%7}, {%8,%9}, {%0,%1,%2,%3};"
        : "+f"(d[0]), "+f"(d[1]), "+f"(d[2]), "+f"(d[3])
        : "r"(a[0]), "r"(a[1]), "r"(a[2]), "r"(a[3]), "r"(b0), "r"(b1));
}
__device__ __forceinline__ void ldm_x4(uint32_t& r0, uint32_t& r1,
                                       uint32_t& r2, uint32_t& r3,
                                       uint32_t addr) {
    asm volatile("ldmatrix.sync.aligned.m8n8.x4.shared.b16 {%0,%1,%2,%3}, [%4];"
                 : "=r"(r0), "=r"(r1), "=r"(r2), "=r"(r3) : "r"(addr));
}
__device__ __forceinline__ float tanha(float x) {
    float r;
    asm("tanh.approx.f32 %0, %1;" : "=f"(r) : "f"(x));
    return r;
}
__device__ __forceinline__ float sigf(float x) {
    return fmaf(tanha(0.5f * x), 0.5f, 0.5f);
}
__device__ __forceinline__ void cpa16(uint32_t saddr, const void* g, int sz) {
    asm volatile("cp.async.cg.shared.global [%0], [%1], 16, %2;"
                 :: "r"(saddr), "l"(g), "r"(sz));
}
#define CP_COMMIT() asm volatile("cp.async.commit_group;")

// per-group barrier: 8 CTAs sharing mx group
__device__ __forceinline__ void gbar(int grp) {
    __syncthreads();
    if (threadIdx.x == 0) {
        __threadfence();
        unsigned* cnt = &g_grpCnt[grp * 32];
        unsigned* gen = &g_grpGen[grp * 32];
        unsigned g = *(volatile unsigned*)gen;
        if (atomicAdd(cnt, 1u) == 7u) {
            *(volatile unsigned*)cnt = 0u;
            __threadfence();
            atomicExch(gen, g + 1);
        } else {
            while (*(volatile unsigned*)gen == g) __nanosleep(32);
        }
        __threadfence();
    }
    __syncthreads();
}

// ------------------------------ setup kernels -----------------------------
__global__ void transpose_kernel(const float* __restrict__ x) {
    int id = blockIdx.x * blockDim.x + threadIdx.x;    // BNR*SEQ*32 groups of 8
    if (id >= BNR * SEQ * 32) return;
    int w8 = id & 31;
    int t  = (id >> 5) & 63;
    int m  = id >> 11;
    int b  = m / 100;
    int n  = m - b * 100;
    const float4* src = (const float4*)x + ((((long)(b * SEQ + t) * 100 + n) * 64) + 2 * w8);
    float4 v0 = src[0], v1 = src[1];
    __half2 h0 = __floats2half2_rn(v0.x, v0.y);
    __half2 h1 = __floats2half2_rn(v0.z, v0.w);
    __half2 h2 = __floats2half2_rn(v1.x, v1.y);
    __half2 h3 = __floats2half2_rn(v1.z, v1.w);
    uint4 o;
    o.x = *(uint32_t*)&h0; o.y = *(uint32_t*)&h1;
    o.z = *(uint32_t*)&h2; o.w = *(uint32_t*)&h3;
    ((uint4*)g_xw)[((long)m * SEQ + t) * 32 + w8] = o;
}

__global__ void rearr_w_kernel(const float* __restrict__ Wih,
                               const float* __restrict__ Whh,
                               const float* __restrict__ bih,
                               const float* __restrict__ bhh,
                               uint32_t* __restrict__ Wre,
                               float* __restrict__ bre) {
    int id = blockIdx.x * 256 + threadIdx.x;   // over 1024*256 words
    if (id >= 1024 * 256) return;
    int nre = id >> 8, kw = id & 255;
    int j = nre >> 2, g = nre & 3;
    int srow = g * 256 + j;
    int k = kw * 2;
    float v0, v1;
    if (k < 256) { v0 = Wih[srow * 256 + k];       v1 = Wih[srow * 256 + k + 1]; }
    else         { v0 = Whh[srow * 256 + k - 256]; v1 = Whh[srow * 256 + k - 255]; }
    __half2 h = __floats2half2_rn(v0, v1);
    Wre[id] = *(uint32_t*)&h;
    if (kw == 0) bre[nre] = bih[srow] + bhh[srow];
}

__global__ void rearr_h1_kernel(const float* __restrict__ cw1, const float* __restrict__ cb1,
                                const float* __restrict__ sw1, const float* __restrict__ sb1,
                                const float* __restrict__ lw1, const float* __restrict__ lb1) {
    int id = blockIdx.x * 256 + threadIdx.x;   // 512*128 words
    if (id >= 512 * 128) return;
    int row = id >> 7, kw = id & 127;
    int k = kw * 2;
    const float* w; float b;
    if (row < 128)      { w = cw1 + row * 256;         b = cb1[row]; }
    else if (row < 256) { w = sw1 + (row - 128) * 256; b = sb1[row - 128]; }
    else                { w = lw1 + (row - 256) * 256; b = lb1[row - 256]; }
    __half2 h = __floats2half2_rn(w[k], w[k + 1]);
    g_Wh1[id] = *(uint32_t*)&h;
    if (kw == 0) g_bh1[row] = b;
}

__global__ void zero_state_kernel() {
    int id = blockIdx.x * blockDim.x + threadIdx.x;
    if (id < BNR * 128) { g_h0buf[0][id] = 0u; g_h1buf[0][id] = 0u; }
    if (id < MT * 32) { g_grpCnt[id] = 0u; g_grpGen[id] = 0u; }
}

// ---------------------------------------------------------------------------
// smem: 4 stages x (A 128x36w + B 128x36w) + biases  (issue distance 3 < 4)
#define STG_W   9216
#define STG_B   (STG_W * 4)
#define BOF_B   (4608 * 4)
#define BIAS_W  (4 * STG_W)
#define PSMEM   ((4 * STG_W + 320) * 4)
#define ROWB    144                    /* 36 words * 4 bytes */

// ---------------- LSTM cell phase (fp16 mma + ldmatrix) --------------------
__device__ __forceinline__ void cell_phase(
    uint32_t* sm,
    const uint32_t* __restrict__ A0, long lda0,   // word-unit row stride
    const uint32_t* __restrict__ A1,
    const uint32_t* __restrict__ Wsl,             // fp16 weight slice rows (256w)
    const float* biasS, float* cReg,
    uint32_t* __restrict__ Hw,                    // fp16 h output (word base)
    int m0, int j0)
{
    const int tid  = threadIdx.x;
    const int arow = tid >> 3, ac4 = tid & 7;
    const int lane = tid & 31, wid = tid >> 5;
    const int wm = wid >> 2, wn = wid & 3;
    const int g4 = lane >> 2, t4 = lane & 3;

    int mrow[4], msz[4];
#pragma unroll
    for (int q = 0; q < 4; ++q) {
        int m = m0 + arow + 32 * q;
        bool p = m < BNR;
        mrow[q] = p ? m : 0;
        msz[q]  = p ? 16 : 0;
    }
    const uint32_t sbase = (uint32_t)__cvta_generic_to_shared(sm);
    uint32_t sb = sbase + (uint32_t)((arow * 36 + ac4 * 4) * 4);

    // ldmatrix per-lane base addresses (stage/ks added in loop)
    const uint32_t aPre = sbase +
        (uint32_t)((wm * 64 + (lane & 7) + ((lane >> 3) & 1) * 8) * ROWB +
                   (lane >> 4) * 16);
    const uint32_t bPre = sbase + BOF_B +
        (uint32_t)((wn * 32 + ((lane >> 4) & 1) * 8 + (lane & 7)) * ROWB +
                   ((lane >> 3) & 1) * 16);

    float acc[4][4][4];
#pragma unroll
    for (int a = 0; a < 4; ++a)
#pragma unroll
        for (int b = 0; b < 4; ++b)
#pragma unroll
            for (int k = 0; k < 4; ++k) acc[a][b][k] = 0.f;

    auto issue = [&](int c, int st) {
        const uint32_t* ap; long lda; int kk;
        if (c < 4) { ap = A0; lda = lda0; kk = c * 32; }
        else       { ap = A1; lda = 128;  kk = (c - 4) * 32; }
#pragma unroll
        for (int q = 0; q < 4; ++q) {
            cpa16(sb + st * STG_B + q * 4608,
                  ap + (long)mrow[q] * lda + kk + ac4 * 4, msz[q]);
            cpa16(sb + st * STG_B + BOF_B + q * 4608,
                  Wsl + (long)(arow + 32 * q) * 256 + c * 32 + ac4 * 4, 16);
        }
        CP_COMMIT();
    };

    issue(0, 0); issue(1, 1); issue(2, 2);
    for (int c = 0; c < 8; ++c) {
        const int st = c & 3;
        if (c <= 5)      asm volatile("cp.async.wait_group 2;");
        else if (c == 6) asm volatile("cp.async.wait_group 1;");
        else             asm volatile("cp.async.wait_group 0;");
        __syncthreads();
        if (c + 3 < 8) issue(c + 3, (c + 3) & 3);

#pragma unroll
        for (int ks = 0; ks < 32; ks += 8) {
            uint32_t af[4][4], b0[4], b1[4];
            uint32_t ab = aPre + st * STG_B + ks * 4;
            uint32_t bb = bPre + st * STG_B + ks * 4;
            ldm_x4(af[0][0], af[0][1], af[0][2], af[0][3], ab);
            ldm_x4(af[1][0], af[1][1], af[1][2], af[1][3], ab + 16 * ROWB);
            ldm_x4(af[2][0], af[2][1], af[2][2], af[2][3], ab + 32 * ROWB);
            ldm_x4(af[3][0], af[3][1], af[3][2], af[3][3], ab + 48 * ROWB);
            ldm_x4(b0[0], b1[0], b0[1], b1[1], bb);
            ldm_x4(b0[2], b1[2], b0[3], b1[3], bb + 16 * ROWB);
#pragma unroll
            for (int mf = 0; mf < 4; ++mf)
#pragma unroll
                for (int nf = 0; nf < 4; ++nf)
                    mma_f16(acc[mf][nf], af[mf], b0[nf], b1[nf]);
        }
    }

    // ---- LSTM epilogue: compute, stage h tile in smem, coalesced STG ------
    // stage-0 region reused as __half hs[128][40] (40-half row = 80B, 16B-aligned)
    __half* hs = (__half*)sm;
    const bool oddl = (t4 & 1);
    const unsigned FULL = 0xffffffffu;
#pragma unroll
    for (int mf = 0; mf < 4; ++mf) {
#pragma unroll
        for (int nf = 0; nf < 4; ++nf) {
            float c0v = acc[mf][nf][0], c1v = acc[mf][nf][1];
            float c2v = acc[mf][nf][2], c3v = acc[mf][nf][3];
            float x0 = __shfl_xor_sync(FULL, c0v, 1);
            float x1 = __shfl_xor_sync(FULL, c1v, 1);
            float x2 = __shfl_xor_sync(FULL, c2v, 1);
            float x3 = __shfl_xor_sync(FULL, c3v, 1);
            float gi, gf, gg, go; int rloc;
            if (!oddl) { gi = c0v; gf = c1v; gg = x0;  go = x1;  rloc = g4; }
            else       { gi = x2;  gf = x3;  gg = c2v; go = c3v; rloc = g4 + 8; }
            int rowloc = wm * 64 + mf * 16 + rloc;       // 0..127
            int jl = wn * 8 + nf * 2 + (t4 >> 1);        // 0..31
            gi += biasS[jl * 4 + 0];
            gf += biasS[jl * 4 + 1];
            gg += biasS[jl * 4 + 2];
            go += biasS[jl * 4 + 3];
            float cold = cReg[mf * 4 + nf];
            float cn = sigf(gf) * cold + sigf(gi) * tanha(gg);
            float hn = sigf(go) * tanha(cn);
            cReg[mf * 4 + nf] = cn;
            hs[rowloc * 40 + jl] = __float2half_rn(hn);
        }
    }
    __syncthreads();
    {   // coalesced write: 2 threads per row, 2x STG.128 each (32 halves/row)
        int row  = tid >> 1, part = tid & 1;
        int rglob = m0 + row;
        if (rglob < BNR) {
            const uint4* src = (const uint4*)(hs + row * 40) + part * 2;
            uint4 v0 = src[0], v1 = src[1];
            uint4* dst = (uint4*)(Hw + (long)rglob * 128 + (j0 >> 1)) + part * 2;
            dst[0] = v0; dst[1] = v1;
        }
    }
    __syncthreads();   // protect stage-0 reuse by the next phase
}

// ---------------- heads layer-1 phase (fp16 mma + ldmatrix) ------------------
__device__ __forceinline__ void heads1_phase(
    uint32_t* sm, const uint32_t* __restrict__ A0,
    const uint32_t* __restrict__ Wsl,            // Wh1 rows hn0..hn0+63 (128w)
    const float* biasS, float* __restrict__ hid, int m0, int n0)
{
    const int tid  = threadIdx.x;
    const int arow = tid >> 3, ac4 = tid & 7;
    const int lane = tid & 31, wid = tid >> 5;
    const int wm = wid >> 2, wn = wid & 3;
    const int g4 = lane >> 2, t4 = lane & 3;

    int mrow[4], msz[4];
#pragma unroll
    for (int q = 0; q < 4; ++q) {
        int m = m0 + arow + 32 * q;
        bool p = m < BNR;
        mrow[q] = p ? m : 0;
        msz[q]  = p ? 16 : 0;
    }
    const uint32_t sbase = (uint32_t)__cvta_generic_to_shared(sm);
    uint32_t sb = sbase + (uint32_t)((arow * 36 + ac4 * 4) * 4);

    const uint32_t aPre = sbase +
        (uint32_t)((wm * 64 + (lane & 7) + ((lane >> 3) & 1) * 8) * ROWB +
                   (lane >> 4) * 16);
    const uint32_t bPre = sbase + BOF_B +
        (uint32_t)((wn * 16 + ((lane >> 4) & 1) * 8 + (lane & 7)) * ROWB +
                   ((lane >> 3) & 1) * 16);

    float acc[4][2][4];
#pragma unroll
    for (int a = 0; a < 4; ++a)
#pragma unroll
        for (int b = 0; b < 2; ++b)
#pragma unroll
            for (int k = 0; k < 4; ++k) acc[a][b][k] = 0.f;

    auto issue = [&](int c, int st) {
        int kk = c * 32;
#pragma unroll
        for (int q = 0; q < 4; ++q)
            cpa16(sb + st * STG_B + q * 4608,
                  A0 + (long)mrow[q] * 128 + kk + ac4 * 4, msz[q]);
#pragma unroll
        for (int q = 0; q < 2; ++q)
            cpa16(sb + st * STG_B + BOF_B + q * 4608,
                  Wsl + (long)(arow + 32 * q) * 128 + kk + ac4 * 4, 16);
        CP_COMMIT();
    };

    issue(0, 0); issue(1, 1); issue(2, 2);
    for (int c = 0; c < 4; ++c) {
        const int st = c & 3;
        if (c <= 1)      asm volatile("cp.async.wait_group 2;");
        else if (c == 2) asm volatile("cp.async.wait_group 1;");
        else             asm volatile("cp.async.wait_group 0;");
        __syncthreads();
        if (c + 3 < 4) issue(c + 3, (c + 3) & 3);

#pragma unroll
        for (int ks = 0; ks < 32; ks += 8) {
            uint32_t af[4][4], b0[2], b1[2];
            uint32_t ab = aPre + st * STG_B + ks * 4;
            uint32_t bb = bPre + st * STG_B + ks * 4;
            ldm_x4(af[0][0], af[0][1], af[0][2], af[0][3], ab);
            ldm_x4(af[1][0], af[1][1], af[1][2], af[1][3], ab + 16 * ROWB);
            ldm_x4(af[2][0], af[2][1], af[2][2], af[2][3], ab + 32 * ROWB);
            ldm_x4(af[3][0], af[3][1], af[3][2], af[3][3], ab + 48 * ROWB);
            ldm_x4(b0[0], b1[0], b0[1], b1[1], bb);
#pragma unroll
            for (int mf = 0; mf < 4; ++mf)
#pragma unroll
                for (int nf = 0; nf < 2; ++nf)
                    mma_f16(acc[mf][nf], af[mf], b0[nf], b1[nf]);
        }
    }

#pragma unroll
    for (int mf = 0; mf < 4; ++mf) {
#pragma unroll
        for (int nf = 0; nf < 2; ++nf) {
            int col = wn * 16 + nf * 8 + 2 * t4;
            int r0 = m0 + wm * 64 + mf * 16 + g4;
            float v0 = acc[mf][nf][0] + biasS[col];
            float v1 = acc[mf][nf][1] + biasS[col + 1];
            float v2 = acc[mf][nf][2] + biasS[col];
            float v3 = acc[mf][nf][3] + biasS[col + 1];
            if (r0 < BNR) {
                hid[(long)r0 * 512 + n0 + col]     = fmaxf(v0, 0.f);
                hid[(long)r0 * 512 + n0 + col + 1] = fmaxf(v1, 0.f);
            }
            if (r0 + 8 < BNR) {
                hid[(long)(r0 + 8) * 512 + n0 + col]     = fmaxf(v2, 0.f);
                hid[(long)(r0 + 8) * 512 + n0 + col + 1] = fmaxf(v3, 0.f);
            }
        }
    }
}

// ---------------- LayerNorm phase (warp per row, group-local rows) ----------
__device__ __forceinline__ void ln_phase(
    const uint32_t* __restrict__ h1, const float* __restrict__ gam,
    const float* __restrict__ bet, uint32_t* __restrict__ ht, int rowbase)
{
    const int wid = threadIdx.x >> 5, lane = threadIdx.x & 31;
    const unsigned FULL = 0xffffffffu;
#pragma unroll
    for (int rep = 0; rep < 2; ++rep) {
        int r = rowbase + rep * 8 + wid;
        if (r < BNR) {
            uint4 u = __ldcg((const uint4*)(h1 + (long)r * 128 + lane * 4));
            float v[8];
            __half2 hh;
            hh = *(__half2*)&u.x; v[0] = __low2float(hh); v[1] = __high2float(hh);
            hh = *(__half2*)&u.y; v[2] = __low2float(hh); v[3] = __high2float(hh);
            hh = *(__half2*)&u.z; v[4] = __low2float(hh); v[5] = __high2float(hh);
            hh = *(__half2*)&u.w; v[6] = __low2float(hh); v[7] = __high2float(hh);
            float s1 = 0.f, s2 = 0.f;
#pragma unroll
            for (int i = 0; i < 8; ++i) { s1 += v[i]; s2 += v[i] * v[i]; }
#pragma unroll
            for (int o = 16; o; o >>= 1) {
                s1 += __shfl_xor_sync(FULL, s1, o);
                s2 += __shfl_xor_sync(FULL, s2, o);
            }
            float mean = s1 * (1.f / 256.f);
            float var  = s2 * (1.f / 256.f) - mean * mean;
            float rstd = rsqrtf(var + 1e-5f);
            uint4 o4;
            uint32_t* op = (uint32_t*)&o4;
#pragma unroll
            for (int i = 0; i < 4; ++i) {
                float g0 = __ldg(&gam[lane * 8 + 2 * i]);
                float g1 = __ldg(&gam[lane * 8 + 2 * i + 1]);
                float b0 = __ldg(&bet[lane * 8 + 2 * i]);
                float b1 = __ldg(&bet[lane * 8 + 2 * i + 1]);
                float o0 = (v[2 * i]     - mean) * rstd * g0 + b0;
                float o1 = (v[2 * i + 1] - mean) * rstd * g1 + b1;
                __half2 ho = __floats2half2_rn(o0, o1);
                op[i] = *(uint32_t*)&ho;
            }
            *(uint4*)(ht + (long)r * 128 + lane * 4) = o4;
        }
    }
}

// ---------------- heads layer-2 phase (group-local rows) --------------------
__device__ __forceinline__ void heads2_phase(
    uint32_t* sm, const float* __restrict__ hid,
    const float* __restrict__ cw2, const float* __restrict__ cb2,
    const float* __restrict__ sw2, const float* __restrict__ sb2,
    const float* __restrict__ lw2, const float* __restrict__ lb2,
    float* __restrict__ out, int s, int rowbase)
{
    float* hs = (float*)sm;                 // 16 rows x 512 f32 = 32KB (stage0)
    const int tid = threadIdx.x;
    for (int i = tid; i < 16 * 128; i += 256) {
        int rr = i >> 7, c4 = i & 127;
        int r = rowbase + rr;
        float4 val = make_float4(0.f, 0.f, 0.f, 0.f);
        if (r < BNR) val = __ldcg((const float4*)(hid + (long)r * 512) + c4);
        ((float4*)hs)[rr * 128 + c4] = val;
    }
    __syncthreads();

    const int wid = tid >> 5, lane = tid & 31;
    const unsigned FULL = 0xffffffffu;
#pragma unroll
    for (int rep = 0; rep < 2; ++rep) {
        int rr = rep * 8 + wid;
        int r = rowbase + rr;
        if (r < BNR) {
            int b = r / 100, n = r - b * 100;
            float* ob = out + (((b * NSTEPS + s) * 100 + n) * 22);
            const float* h = hs + rr * 512;
            for (int o = 0; o < 22; ++o) {
                const float* w; float bb; int base, klen;
                if (o < 4)      { w = cw2 + o * 128;       bb = __ldg(&cb2[o]);     base = 0;   klen = 128; }
                else if (o < 6) { w = sw2 + (o - 4) * 128; bb = __ldg(&sb2[o - 4]); base = 128; klen = 128; }
                else            { w = lw2 + (o - 6) * 256; bb = __ldg(&lb2[o - 6]); base = 256; klen = 256; }
                float a = 0.f;
                for (int k = lane; k < klen; k += 32) a += h[base + k] * __ldg(&w[k]);
#pragma unroll
                for (int off = 16; off; off >>= 1) a += __shfl_xor_sync(FULL, a, off);
                if (lane == 0) ob[o] = a + bb;
            }
        }
    }
    __syncthreads();
}

// ---------------------------------------------------------------------------
__global__ void __launch_bounds__(256, 1)
persist_kernel(const float* __restrict__ lng, const float* __restrict__ lnb,
               const float* __restrict__ cw2, const float* __restrict__ cb2,
               const float* __restrict__ sw2, const float* __restrict__ sb2,
               const float* __restrict__ lw2, const float* __restrict__ lb2,
               float* __restrict__ out)
{
    extern __shared__ uint32_t sm[];
    float* bS0 = (float*)(sm + BIAS_W);
    float* bS1 = bS0 + 128;
    float* bSh = bS1 + 128;

    const int tid = threadIdx.x;
    const int cta = blockIdx.x;
    const int mx = cta % MT, ny = cta / MT;
    const int m0  = mx * 128;
    const int nb0 = ny * 128;           // gate-row base
    const int j0  = ny * 32;            // j-col base
    const int hn0 = ny * 64;            // heads1 col base
    const int rowbase = m0 + ny * 16;   // LN/heads2 group-local rows

    if (tid < 128) { bS0[tid] = g_bre0[nb0 + tid]; bS1[tid] = g_bre1[nb0 + tid]; }
    if (tid < 64)  { bSh[tid] = g_bh1[hn0 + tid]; }
    __syncthreads();

    float c0r[16], c1r[16];
#pragma unroll
    for (int i = 0; i < 16; ++i) { c0r[i] = 0.f; c1r[i] = 0.f; }

    const uint32_t* W0sl  = g_Wre0 + (long)nb0 * 256;
    const uint32_t* W1sl  = g_Wre1 + (long)nb0 * 256;
    const uint32_t* Wh1sl = g_Wh1 + (long)hn0 * 128;

    // ---------------- encoder (software-pipelined: phase t = L0(t)+L1(t-1)) --
    cell_phase(sm, g_xw, (long)SEQ * 128, g_h0buf[0],
               W0sl, bS0, c0r, g_h0buf[1], m0, j0);            // L0(0)
    gbar(mx);
    for (int t = 1; t < SEQ; ++t) {
        cell_phase(sm, g_xw + (long)t * 128, (long)SEQ * 128, g_h0buf[t & 1],
                   W0sl, bS0, c0r, g_h0buf[(t + 1) & 1], m0, j0);      // L0(t)
        cell_phase(sm, g_h0buf[t & 1], 128, g_h1buf[(t + 1) & 1],
                   W1sl, bS1, c1r, g_h1buf[t & 1], m0, j0);            // L1(t-1)
        gbar(mx);
    }
    cell_phase(sm, g_h0buf[0], 128, g_h1buf[1],
               W1sl, bS1, c1r, g_h1buf[0], m0, j0);             // L1(63)
    gbar(mx);
    ln_phase(g_h1buf[0], lng, lnb, g_htw, rowbase);
    gbar(mx);

    // ---------------- decoder ----------------
    for (int s = 0; s < NSTEPS; ++s) {
        // phase A: heads1(s) + L0d(s)   (both read only g_htw + old state)
        heads1_phase(sm, g_htw, Wh1sl, bSh, g_hid, m0, hn0);
        cell_phase(sm, g_htw, 128, g_h0buf[s & 1],
                   W0sl, bS0, c0r, g_h0buf[(s + 1) & 1], m0, j0);
        gbar(mx);
        // phase B: L1d(s) + heads2(s)
        cell_phase(sm, g_h0buf[(s + 1) & 1], 128, g_h1buf[s & 1],
                   W1sl, bS1, c1r, g_h1buf[(s + 1) & 1], m0, j0);
        heads2_phase(sm, g_hid, cw2, cb2, sw2, sb2, lw2, lb2, out, s, rowbase);
        if (s < NSTEPS - 1) {
            gbar(mx);
            ln_phase(g_h1buf[(s + 1) & 1], lng, lnb, g_htw, rowbase);
            gbar(mx);
        }
    }
}

// ---------------------------------------------------------------------------
extern "C" void kernel_launch(void* const* d_in, const int* in_sizes, int n_in,
                              void* d_out, int out_size)
{
    (void)in_sizes; (void)n_in; (void)out_size;
    const float* x    = (const float*)d_in[0];
    const float* Wih0 = (const float*)d_in[1];
    const float* Whh0 = (const float*)d_in[2];
    const float* bih0 = (const float*)d_in[3];
    const float* bhh0 = (const float*)d_in[4];
    const float* Wih1 = (const float*)d_in[5];
    const float* Whh1 = (const float*)d_in[6];
    const float* bih1 = (const float*)d_in[7];
    const float* bhh1 = (const float*)d_in[8];
    const float* lng  = (const float*)d_in[9];
    const float* lnb  = (const float*)d_in[10];
    const float* cw1  = (const float*)d_in[11];
    const float* cb1  = (const float*)d_in[12];
    const float* cw2  = (const float*)d_in[13];
    const float* cb2  = (const float*)d_in[14];
    const float* sw1  = (const float*)d_in[15];
    const float* sb1  = (const float*)d_in[16];
    const float* sw2  = (const float*)d_in[17];
    const float* sb2  = (const float*)d_in[18];
    const float* lw1  = (const float*)d_in[19];
    const float* lb1  = (const float*)d_in[20];
    const float* lw2  = (const float*)d_in[21];
    const float* lb2  = (const float*)d_in[22];
    float* out = (float*)d_out;

    uint32_t *Wre0, *Wre1;
    float *bre0, *bre1;
    cudaGetSymbolAddress((void**)&Wre0, g_Wre0);
    cudaGetSymbolAddress((void**)&Wre1, g_Wre1);
    cudaGetSymbolAddress((void**)&bre0, g_bre0);
    cudaGetSymbolAddress((void**)&bre1, g_bre1);

    cudaFuncSetAttribute(persist_kernel,
                         cudaFuncAttributeMaxDynamicSharedMemorySize, PSMEM);

    transpose_kernel<<<(BNR * SEQ * 32 + 255) / 256, 256>>>(x);
    rearr_w_kernel<<<1024, 256>>>(Wih0, Whh0, bih0, bhh0, Wre0, bre0);
    rearr_w_kernel<<<1024, 256>>>(Wih1, Whh1, bih1, bhh1, Wre1, bre1);
    rearr_h1_kernel<<<256, 256>>>(cw1, cb1, sw1, sb1, lw1, lb1);
    zero_state_kernel<<<800, 256>>>();

    persist_kernel<<<NCTA, 256, PSMEM>>>(lng, lnb, cw2, cb2, sw2, sb2,
                                         lw2, lb2, out);
}

// round 11
// speedup vs baseline: 2.9986x; 1.1649x over previous
#include <cuda_runtime.h>
#include <cuda_fp16.h>
#include <cstdint>

#define BNR    1600
#define HD     256
#define SEQ    64
#define NSTEPS 10
#define MT     17          /* M groups of 96 rows */
#define MROWS  96
#define NCTA   (MT * 8)    /* 136 CTAs, one wave on 148 SMs */

// ------------------------- static device scratch --------------------------
__device__ uint32_t g_xw  [BNR * SEQ * 128];    // x fp16 [m][t][128w]
__device__ uint32_t g_h0buf[2][BNR * 128];
__device__ uint32_t g_h1buf[2][BNR * 128];
__device__ uint32_t g_htw [BNR * 128];          // LN output fp16
__device__ float    g_hid [BNR * 512];
__device__ uint32_t g_Wre0[1024 * 256];         // fp16, rows (j*4+g), k=[Wih|Whh]
__device__ uint32_t g_Wre1[1024 * 256];
__device__ float    g_bre0[1024];
__device__ float    g_bre1[1024];
__device__ uint32_t g_Wh1 [512 * 128];          // heads layer1 weights fp16
__device__ float    g_bh1 [512];
__device__ unsigned g_grpCnt[MT * 32];          // per-group barrier (128B stride)
__device__ unsigned g_grpGen[MT * 32];

// ------------------------------ helpers -----------------------------------
__device__ __forceinline__ void mma_f16(float* d, const uint32_t* a,
                                        uint32_t b0, uint32_t b1) {
    asm volatile(
        "mma.sync.aligned.m16n8k16.row.col.f32.f16.f16.f32 "
        "{%0,%1,%2,%3}, {%4,%5,%6,%7}, {%8,%9}, {%0,%1,%2,%3};"
        : "+f"(d[0]), "+f"(d[1]), "+f"(d[2]), "+f"(d[3])
        : "r"(a[0]), "r"(a[1]), "r"(a[2]), "r"(a[3]), "r"(b0), "r"(b1));
}
__device__ __forceinline__ void ldm_x4(uint32_t& r0, uint32_t& r1,
                                       uint32_t& r2, uint32_t& r3,
                                       uint32_t addr) {
    asm volatile("ldmatrix.sync.aligned.m8n8.x4.shared.b16 {%0,%1,%2,%3}, [%4];"
                 : "=r"(r0), "=r"(r1), "=r"(r2), "=r"(r3) : "r"(addr));
}
__device__ __forceinline__ float tanha(float x) {
    float r;
    asm("tanh.approx.f32 %0, %1;" : "=f"(r) : "f"(x));
    return r;
}
__device__ __forceinline__ float sigf(float x) {
    return fmaf(tanha(0.5f * x), 0.5f, 0.5f);
}
__device__ __forceinline__ void cpa16(uint32_t saddr, const void* g, int sz) {
    asm volatile("cp.async.cg.shared.global [%0], [%1], 16, %2;"
                 :: "r"(saddr), "l"(g), "r"(sz));
}
#define CP_COMMIT() asm volatile("cp.async.commit_group;")

// per-group barrier: 8 CTAs sharing mx group
__device__ __forceinline__ void gbar(int grp) {
    __syncthreads();
    if (threadIdx.x == 0) {
        __threadfence();
        unsigned* cnt = &g_grpCnt[grp * 32];
        unsigned* gen = &g_grpGen[grp * 32];
        unsigned g = *(volatile unsigned*)gen;
        if (atomicAdd(cnt, 1u) == 7u) {
            *(volatile unsigned*)cnt = 0u;
            __threadfence();
            atomicExch(gen, g + 1);
        } else {
            while (*(volatile unsigned*)gen == g) __nanosleep(32);
        }
        __threadfence();
    }
    __syncthreads();
}

// ------------------------------ setup kernels -----------------------------
__global__ void transpose_kernel(const float* __restrict__ x) {
    int id = blockIdx.x * blockDim.x + threadIdx.x;    // BNR*SEQ*32 groups of 8
    if (id >= BNR * SEQ * 32) return;
    int w8 = id & 31;
    int t  = (id >> 5) & 63;
    int m  = id >> 11;
    int b  = m / 100;
    int n  = m - b * 100;
    const float4* src = (const float4*)x + ((((long)(b * SEQ + t) * 100 + n) * 64) + 2 * w8);
    float4 v0 = src[0], v1 = src[1];
    __half2 h0 = __floats2half2_rn(v0.x, v0.y);
    __half2 h1 = __floats2half2_rn(v0.z, v0.w);
    __half2 h2 = __floats2half2_rn(v1.x, v1.y);
    __half2 h3 = __floats2half2_rn(v1.z, v1.w);
    uint4 o;
    o.x = *(uint32_t*)&h0; o.y = *(uint32_t*)&h1;
    o.z = *(uint32_t*)&h2; o.w = *(uint32_t*)&h3;
    ((uint4*)g_xw)[((long)m * SEQ + t) * 32 + w8] = o;
}

__global__ void rearr_w_kernel(const float* __restrict__ Wih,
                               const float* __restrict__ Whh,
                               const float* __restrict__ bih,
                               const float* __restrict__ bhh,
                               uint32_t* __restrict__ Wre,
                               float* __restrict__ bre) {
    int id = blockIdx.x * 256 + threadIdx.x;   // over 1024*256 words
    if (id >= 1024 * 256) return;
    int nre = id >> 8, kw = id & 255;
    int j = nre >> 2, g = nre & 3;
    int srow = g * 256 + j;
    int k = kw * 2;
    float v0, v1;
    if (k < 256) { v0 = Wih[srow * 256 + k];       v1 = Wih[srow * 256 + k + 1]; }
    else         { v0 = Whh[srow * 256 + k - 256]; v1 = Whh[srow * 256 + k - 255]; }
    __half2 h = __floats2half2_rn(v0, v1);
    Wre[id] = *(uint32_t*)&h;
    if (kw == 0) bre[nre] = bih[srow] + bhh[srow];
}

__global__ void rearr_h1_kernel(const float* __restrict__ cw1, const float* __restrict__ cb1,
                                const float* __restrict__ sw1, const float* __restrict__ sb1,
                                const float* __restrict__ lw1, const float* __restrict__ lb1) {
    int id = blockIdx.x * 256 + threadIdx.x;   // 512*128 words
    if (id >= 512 * 128) return;
    int row = id >> 7, kw = id & 127;
    int k = kw * 2;
    const float* w; float b;
    if (row < 128)      { w = cw1 + row * 256;         b = cb1[row]; }
    else if (row < 256) { w = sw1 + (row - 128) * 256; b = sb1[row - 128]; }
    else                { w = lw1 + (row - 256) * 256; b = lb1[row - 256]; }
    __half2 h = __floats2half2_rn(w[k], w[k + 1]);
    g_Wh1[id] = *(uint32_t*)&h;
    if (kw == 0) g_bh1[row] = b;
}

__global__ void zero_state_kernel() {
    int id = blockIdx.x * blockDim.x + threadIdx.x;
    if (id < BNR * 128) { g_h0buf[0][id] = 0u; g_h1buf[0][id] = 0u; }
    if (id < MT * 32) { g_grpCnt[id] = 0u; g_grpGen[id] = 0u; }
}

// ---------------------------------------------------------------------------
// smem: 4 stages x (A 128x36w + B 128x36w) + biases (A region: 96 rows used)
#define STG_W   9216
#define STG_B   (STG_W * 4)
#define BOF_B   (4608 * 4)
#define BIAS_W  (4 * STG_W)
#define PSMEM   ((4 * STG_W + 320) * 4)
#define ROWB    144                    /* 36 words * 4 bytes */

// ---------------- LSTM cell phase (fp16 mma + ldmatrix) --------------------
// gates[96 rows x 128 gate-rows], K = 512 halves = 8 chunks of 64
__device__ __forceinline__ void cell_phase(
    uint32_t* sm,
    const uint32_t* __restrict__ A0, long lda0,   // word-unit row stride
    const uint32_t* __restrict__ A1,
    const uint32_t* __restrict__ Wsl,             // fp16 weight slice rows (256w)
    const float* biasS, float* cReg,              // cReg[12]
    uint32_t* __restrict__ Hw,                    // fp16 h output (word base)
    int m0, int j0)
{
    const int tid  = threadIdx.x;
    const int arow = tid >> 3, ac4 = tid & 7;
    const int lane = tid & 31, wid = tid >> 5;
    const int wm = wid >> 2, wn = wid & 3;
    const int g4 = lane >> 2, t4 = lane & 3;

    int mrow[3], msz[3];
#pragma unroll
    for (int q = 0; q < 3; ++q) {
        int m = m0 + arow + 32 * q;
        bool p = m < BNR;
        mrow[q] = p ? m : 0;
        msz[q]  = p ? 16 : 0;
    }
    const uint32_t sbase = (uint32_t)__cvta_generic_to_shared(sm);
    uint32_t sb = sbase + (uint32_t)((arow * 36 + ac4 * 4) * 4);

    // ldmatrix per-lane base addresses (stage/ks added in loop)
    const uint32_t aPre = sbase +
        (uint32_t)((wm * 48 + (lane & 7) + ((lane >> 3) & 1) * 8) * ROWB +
                   (lane >> 4) * 16);
    const uint32_t bPre = sbase + BOF_B +
        (uint32_t)((wn * 32 + ((lane >> 4) & 1) * 8 + (lane & 7)) * ROWB +
                   ((lane >> 3) & 1) * 16);

    float acc[3][4][4];
#pragma unroll
    for (int a = 0; a < 3; ++a)
#pragma unroll
        for (int b = 0; b < 4; ++b)
#pragma unroll
            for (int k = 0; k < 4; ++k) acc[a][b][k] = 0.f;

    auto issue = [&](int c, int st) {
        const uint32_t* ap; long lda; int kk;
        if (c < 4) { ap = A0; lda = lda0; kk = c * 32; }
        else       { ap = A1; lda = 128;  kk = (c - 4) * 32; }
#pragma unroll
        for (int q = 0; q < 3; ++q)
            cpa16(sb + st * STG_B + q * 4608,
                  ap + (long)mrow[q] * lda + kk + ac4 * 4, msz[q]);
#pragma unroll
        for (int q = 0; q < 4; ++q)
            cpa16(sb + st * STG_B + BOF_B + q * 4608,
                  Wsl + (long)(arow + 32 * q) * 256 + c * 32 + ac4 * 4, 16);
        CP_COMMIT();
    };

    issue(0, 0); issue(1, 1); issue(2, 2);
    for (int c = 0; c < 8; ++c) {
        const int st = c & 3;
        if (c <= 5)      asm volatile("cp.async.wait_group 2;");
        else if (c == 6) asm volatile("cp.async.wait_group 1;");
        else             asm volatile("cp.async.wait_group 0;");
        __syncthreads();
        if (c + 3 < 8) issue(c + 3, (c + 3) & 3);

#pragma unroll
        for (int ks = 0; ks < 32; ks += 8) {
            uint32_t af[3][4], b0[4], b1[4];
            uint32_t ab = aPre + st * STG_B + ks * 4;
            uint32_t bb = bPre + st * STG_B + ks * 4;
            ldm_x4(af[0][0], af[0][1], af[0][2], af[0][3], ab);
            ldm_x4(af[1][0], af[1][1], af[1][2], af[1][3], ab + 16 * ROWB);
            ldm_x4(af[2][0], af[2][1], af[2][2], af[2][3], ab + 32 * ROWB);
            ldm_x4(b0[0], b1[0], b0[1], b1[1], bb);
            ldm_x4(b0[2], b1[2], b0[3], b1[3], bb + 16 * ROWB);
#pragma unroll
            for (int mf = 0; mf < 3; ++mf)
#pragma unroll
                for (int nf = 0; nf < 4; ++nf)
                    mma_f16(acc[mf][nf], af[mf], b0[nf], b1[nf]);
        }
    }

    // ---- LSTM epilogue: compute, stage h tile in smem, coalesced STG ------
    __half* hs = (__half*)sm;          // reused stage0: __half hs[96][40]
    const bool oddl = (t4 & 1);
    const unsigned FULL = 0xffffffffu;
#pragma unroll
    for (int mf = 0; mf < 3; ++mf) {
#pragma unroll
        for (int nf = 0; nf < 4; ++nf) {
            float c0v = acc[mf][nf][0], c1v = acc[mf][nf][1];
            float c2v = acc[mf][nf][2], c3v = acc[mf][nf][3];
            float x0 = __shfl_xor_sync(FULL, c0v, 1);
            float x1 = __shfl_xor_sync(FULL, c1v, 1);
            float x2 = __shfl_xor_sync(FULL, c2v, 1);
            float x3 = __shfl_xor_sync(FULL, c3v, 1);
            float gi, gf, gg, go; int rloc;
            if (!oddl) { gi = c0v; gf = c1v; gg = x0;  go = x1;  rloc = g4; }
            else       { gi = x2;  gf = x3;  gg = c2v; go = c3v; rloc = g4 + 8; }
            int rowloc = wm * 48 + mf * 16 + rloc;       // 0..95
            int jl = wn * 8 + nf * 2 + (t4 >> 1);        // 0..31
            gi += biasS[jl * 4 + 0];
            gf += biasS[jl * 4 + 1];
            gg += biasS[jl * 4 + 2];
            go += biasS[jl * 4 + 3];
            float cold = cReg[mf * 4 + nf];
            float cn = sigf(gf) * cold + sigf(gi) * tanha(gg);
            float hn = sigf(go) * tanha(cn);
            cReg[mf * 4 + nf] = cn;
            hs[rowloc * 40 + jl] = __float2half_rn(hn);
        }
    }
    __syncthreads();
    if (tid < 192) {   // coalesced write: 2 threads/row, 2x STG.128 each
        int row  = tid >> 1, part = tid & 1;
        int rglob = m0 + row;
        if (rglob < BNR) {
            const uint4* src = (const uint4*)(hs + row * 40) + part * 2;
            uint4 v0 = src[0], v1 = src[1];
            uint4* dst = (uint4*)(Hw + (long)rglob * 128 + (j0 >> 1)) + part * 2;
            dst[0] = v0; dst[1] = v1;
        }
    }
    __syncthreads();   // protect stage-0 reuse by the next phase
}

// ---------------- heads layer-1 phase (fp16 mma + ldmatrix) ------------------
__device__ __forceinline__ void heads1_phase(
    uint32_t* sm, const uint32_t* __restrict__ A0,
    const uint32_t* __restrict__ Wsl,            // Wh1 rows hn0..hn0+63 (128w)
    const float* biasS, float* __restrict__ hid, int m0, int n0)
{
    const int tid  = threadIdx.x;
    const int arow = tid >> 3, ac4 = tid & 7;
    const int lane = tid & 31, wid = tid >> 5;
    const int wm = wid >> 2, wn = wid & 3;
    const int g4 = lane >> 2, t4 = lane & 3;

    int mrow[3], msz[3];
#pragma unroll
    for (int q = 0; q < 3; ++q) {
        int m = m0 + arow + 32 * q;
        bool p = m < BNR;
        mrow[q] = p ? m : 0;
        msz[q]  = p ? 16 : 0;
    }
    const uint32_t sbase = (uint32_t)__cvta_generic_to_shared(sm);
    uint32_t sb = sbase + (uint32_t)((arow * 36 + ac4 * 4) * 4);

    const uint32_t aPre = sbase +
        (uint32_t)((wm * 48 + (lane & 7) + ((lane >> 3) & 1) * 8) * ROWB +
                   (lane >> 4) * 16);
    const uint32_t bPre = sbase + BOF_B +
        (uint32_t)((wn * 16 + ((lane >> 4) & 1) * 8 + (lane & 7)) * ROWB +
                   ((lane >> 3) & 1) * 16);

    float acc[3][2][4];
#pragma unroll
    for (int a = 0; a < 3; ++a)
#pragma unroll
        for (int b = 0; b < 2; ++b)
#pragma unroll
            for (int k = 0; k < 4; ++k) acc[a][b][k] = 0.f;

    auto issue = [&](int c, int st) {
        int kk = c * 32;
#pragma unroll
        for (int q = 0; q < 3; ++q)
            cpa16(sb + st * STG_B + q * 4608,
                  A0 + (long)mrow[q] * 128 + kk + ac4 * 4, msz[q]);
#pragma unroll
        for (int q = 0; q < 2; ++q)
            cpa16(sb + st * STG_B + BOF_B + q * 4608,
                  Wsl + (long)(arow + 32 * q) * 128 + kk + ac4 * 4, 16);
        CP_COMMIT();
    };

    issue(0, 0); issue(1, 1); issue(2, 2);
    for (int c = 0; c < 4; ++c) {
        const int st = c & 3;
        if (c <= 1)      asm volatile("cp.async.wait_group 2;");
        else if (c == 2) asm volatile("cp.async.wait_group 1;");
        else             asm volatile("cp.async.wait_group 0;");
        __syncthreads();
        if (c + 3 < 4) issue(c + 3, (c + 3) & 3);

#pragma unroll
        for (int ks = 0; ks < 32; ks += 8) {
            uint32_t af[3][4], b0[2], b1[2];
            uint32_t ab = aPre + st * STG_B + ks * 4;
            uint32_t bb = bPre + st * STG_B + ks * 4;
            ldm_x4(af[0][0], af[0][1], af[0][2], af[0][3], ab);
            ldm_x4(af[1][0], af[1][1], af[1][2], af[1][3], ab + 16 * ROWB);
            ldm_x4(af[2][0], af[2][1], af[2][2], af[2][3], ab + 32 * ROWB);
            ldm_x4(b0[0], b1[0], b0[1], b1[1], bb);
#pragma unroll
            for (int mf = 0; mf < 3; ++mf)
#pragma unroll
                for (int nf = 0; nf < 2; ++nf)
                    mma_f16(acc[mf][nf], af[mf], b0[nf], b1[nf]);
        }
    }

#pragma unroll
    for (int mf = 0; mf < 3; ++mf) {
#pragma unroll
        for (int nf = 0; nf < 2; ++nf) {
            int col = wn * 16 + nf * 8 + 2 * t4;
            int r0 = m0 + wm * 48 + mf * 16 + g4;
            float v0 = acc[mf][nf][0] + biasS[col];
            float v1 = acc[mf][nf][1] + biasS[col + 1];
            float v2 = acc[mf][nf][2] + biasS[col];
            float v3 = acc[mf][nf][3] + biasS[col + 1];
            if (r0 < BNR) {
                hid[(long)r0 * 512 + n0 + col]     = fmaxf(v0, 0.f);
                hid[(long)r0 * 512 + n0 + col + 1] = fmaxf(v1, 0.f);
            }
            if (r0 + 8 < BNR) {
                hid[(long)(r0 + 8) * 512 + n0 + col]     = fmaxf(v2, 0.f);
                hid[(long)(r0 + 8) * 512 + n0 + col + 1] = fmaxf(v3, 0.f);
            }
        }
    }
}

// ---------------- LayerNorm phase (warp per row, 12 rows per CTA) -----------
__device__ __forceinline__ void ln_phase(
    const uint32_t* __restrict__ h1, const float* __restrict__ gam,
    const float* __restrict__ bet, uint32_t* __restrict__ ht, int rowbase)
{
    const int wid = threadIdx.x >> 5, lane = threadIdx.x & 31;
    const unsigned FULL = 0xffffffffu;
#pragma unroll
    for (int rep = 0; rep < 2; ++rep) {
        int rr = rep * 8 + wid;
        int r = rowbase + rr;
        if (rr < 12 && r < BNR) {
            uint4 u = __ldcg((const uint4*)(h1 + (long)r * 128 + lane * 4));
            float v[8];
            __half2 hh;
            hh = *(__half2*)&u.x; v[0] = __low2float(hh); v[1] = __high2float(hh);
            hh = *(__half2*)&u.y; v[2] = __low2float(hh); v[3] = __high2float(hh);
            hh = *(__half2*)&u.z; v[4] = __low2float(hh); v[5] = __high2float(hh);
            hh = *(__half2*)&u.w; v[6] = __low2float(hh); v[7] = __high2float(hh);
            float s1 = 0.f, s2 = 0.f;
#pragma unroll
            for (int i = 0; i < 8; ++i) { s1 += v[i]; s2 += v[i] * v[i]; }
#pragma unroll
            for (int o = 16; o; o >>= 1) {
                s1 += __shfl_xor_sync(FULL, s1, o);
                s2 += __shfl_xor_sync(FULL, s2, o);
            }
            float mean = s1 * (1.f / 256.f);
            float var  = s2 * (1.f / 256.f) - mean * mean;
            float rstd = rsqrtf(var + 1e-5f);
            uint4 o4;
            uint32_t* op = (uint32_t*)&o4;
#pragma unroll
            for (int i = 0; i < 4; ++i) {
                float g0 = __ldg(&gam[lane * 8 + 2 * i]);
                float g1 = __ldg(&gam[lane * 8 + 2 * i + 1]);
                float b0 = __ldg(&bet[lane * 8 + 2 * i]);
                float b1 = __ldg(&bet[lane * 8 + 2 * i + 1]);
                float o0 = (v[2 * i]     - mean) * rstd * g0 + b0;
                float o1 = (v[2 * i + 1] - mean) * rstd * g1 + b1;
                __half2 ho = __floats2half2_rn(o0, o1);
                op[i] = *(uint32_t*)&ho;
            }
            *(uint4*)(ht + (long)r * 128 + lane * 4) = o4;
        }
    }
}

// ---------------- heads layer-2 phase (12 rows per CTA) ---------------------
__device__ __forceinline__ void heads2_phase(
    uint32_t* sm, const float* __restrict__ hid,
    const float* __restrict__ cw2, const float* __restrict__ cb2,
    const float* __restrict__ sw2, const float* __restrict__ sb2,
    const float* __restrict__ lw2, const float* __restrict__ lb2,
    float* __restrict__ out, int s, int rowbase)
{
    float* hs = (float*)sm;                 // 12 rows x 512 f32 = 24KB (stage0)
    const int tid = threadIdx.x;
    for (int i = tid; i < 12 * 128; i += 256) {
        int rr = i >> 7, c4 = i & 127;
        int r = rowbase + rr;
        float4 val = make_float4(0.f, 0.f, 0.f, 0.f);
        if (r < BNR) val = __ldcg((const float4*)(hid + (long)r * 512) + c4);
        ((float4*)hs)[rr * 128 + c4] = val;
    }
    __syncthreads();

    const int wid = tid >> 5, lane = tid & 31;
    const unsigned FULL = 0xffffffffu;
#pragma unroll
    for (int rep = 0; rep < 2; ++rep) {
        int rr = rep * 8 + wid;
        int r = rowbase + rr;
        if (rr < 12 && r < BNR) {
            int b = r / 100, n = r - b * 100;
            float* ob = out + (((b * NSTEPS + s) * 100 + n) * 22);
            const float* h = hs + rr * 512;
            for (int o = 0; o < 22; ++o) {
                const float* w; float bb; int base, klen;
                if (o < 4)      { w = cw2 + o * 128;       bb = __ldg(&cb2[o]);     base = 0;   klen = 128; }
                else if (o < 6) { w = sw2 + (o - 4) * 128; bb = __ldg(&sb2[o - 4]); base = 128; klen = 128; }
                else            { w = lw2 + (o - 6) * 256; bb = __ldg(&lb2[o - 6]); base = 256; klen = 256; }
                float a = 0.f;
                for (int k = lane; k < klen; k += 32) a += h[base + k] * __ldg(&w[k]);
#pragma unroll
                for (int off = 16; off; off >>= 1) a += __shfl_xor_sync(FULL, a, off);
                if (lane == 0) ob[o] = a + bb;
            }
        }
    }
    __syncthreads();
}

// ---------------------------------------------------------------------------
__global__ void __launch_bounds__(256, 1)
persist_kernel(const float* __restrict__ lng, const float* __restrict__ lnb,
               const float* __restrict__ cw2, const float* __restrict__ cb2,
               const float* __restrict__ sw2, const float* __restrict__ sb2,
               const float* __restrict__ lw2, const float* __restrict__ lb2,
               float* __restrict__ out)
{
    extern __shared__ uint32_t sm[];
    float* bS0 = (float*)(sm + BIAS_W);
    float* bS1 = bS0 + 128;
    float* bSh = bS1 + 128;

    const int tid = threadIdx.x;
    const int cta = blockIdx.x;
    const int mx = cta % MT, ny = cta / MT;
    const int m0  = mx * MROWS;
    const int nb0 = ny * 128;           // gate-row base
    const int j0  = ny * 32;            // j-col base
    const int hn0 = ny * 64;            // heads1 col base
    const int rowbase = m0 + ny * 12;   // LN/heads2 group-local rows (12 each)

    if (tid < 128) { bS0[tid] = g_bre0[nb0 + tid]; bS1[tid] = g_bre1[nb0 + tid]; }
    if (tid < 64)  { bSh[tid] = g_bh1[hn0 + tid]; }
    __syncthreads();

    float c0r[12], c1r[12];
#pragma unroll
    for (int i = 0; i < 12; ++i) { c0r[i] = 0.f; c1r[i] = 0.f; }

    const uint32_t* W0sl  = g_Wre0 + (long)nb0 * 256;
    const uint32_t* W1sl  = g_Wre1 + (long)nb0 * 256;
    const uint32_t* Wh1sl = g_Wh1 + (long)hn0 * 128;

    // ---------------- encoder (software-pipelined: phase t = L0(t)+L1(t-1)) --
    cell_phase(sm, g_xw, (long)SEQ * 128, g_h0buf[0],
               W0sl, bS0, c0r, g_h0buf[1], m0, j0);            // L0(0)
    gbar(mx);
    for (int t = 1; t < SEQ; ++t) {
        cell_phase(sm, g_xw + (long)t * 128, (long)SEQ * 128, g_h0buf[t & 1],
                   W0sl, bS0, c0r, g_h0buf[(t + 1) & 1], m0, j0);      // L0(t)
        cell_phase(sm, g_h0buf[t & 1], 128, g_h1buf[(t + 1) & 1],
                   W1sl, bS1, c1r, g_h1buf[t & 1], m0, j0);            // L1(t-1)
        gbar(mx);
    }
    cell_phase(sm, g_h0buf[0], 128, g_h1buf[1],
               W1sl, bS1, c1r, g_h1buf[0], m0, j0);             // L1(63)
    gbar(mx);
    ln_phase(g_h1buf[0], lng, lnb, g_htw, rowbase);
    gbar(mx);

    // ---------------- decoder ----------------
    for (int s = 0; s < NSTEPS; ++s) {
        // phase A: heads1(s) + L0d(s)   (both read only g_htw + old state)
        heads1_phase(sm, g_htw, Wh1sl, bSh, g_hid, m0, hn0);
        cell_phase(sm, g_htw, 128, g_h0buf[s & 1],
                   W0sl, bS0, c0r, g_h0buf[(s + 1) & 1], m0, j0);
        gbar(mx);
        // phase B: L1d(s) + heads2(s)
        cell_phase(sm, g_h0buf[(s + 1) & 1], 128, g_h1buf[s & 1],
                   W1sl, bS1, c1r, g_h1buf[(s + 1) & 1], m0, j0);
        heads2_phase(sm, g_hid, cw2, cb2, sw2, sb2, lw2, lb2, out, s, rowbase);
        if (s < NSTEPS - 1) {
            gbar(mx);
            ln_phase(g_h1buf[(s + 1) & 1], lng, lnb, g_htw, rowbase);
            gbar(mx);
        }
    }
}

// ---------------------------------------------------------------------------
extern "C" void kernel_launch(void* const* d_in, const int* in_sizes, int n_in,
                              void* d_out, int out_size)
{
    (void)in_sizes; (void)n_in; (void)out_size;
    const float* x    = (const float*)d_in[0];
    const float* Wih0 = (const float*)d_in[1];
    const float* Whh0 = (const float*)d_in[2];
    const float* bih0 = (const float*)d_in[3];
    const float* bhh0 = (const float*)d_in[4];
    const float* Wih1 = (const float*)d_in[5];
    const float* Whh1 = (const float*)d_in[6];
    const float* bih1 = (const float*)d_in[7];
    const float* bhh1 = (const float*)d_in[8];
    const float* lng  = (const float*)d_in[9];
    const float* lnb  = (const float*)d_in[10];
    const float* cw1  = (const float*)d_in[11];
    const float* cb1  = (const float*)d_in[12];
    const float* cw2  = (const float*)d_in[13];
    const float* cb2  = (const float*)d_in[14];
    const float* sw1  = (const float*)d_in[15];
    const float* sb1  = (const float*)d_in[16];
    const float* sw2  = (const float*)d_in[17];
    const float* sb2  = (const float*)d_in[18];
    const float* lw1  = (const float*)d_in[19];
    const float* lb1  = (const float*)d_in[20];
    const float* lw2  = (const float*)d_in[21];
    const float* lb2  = (const float*)d_in[22];
    float* out = (float*)d_out;

    uint32_t *Wre0, *Wre1;
    float *bre0, *bre1;
    cudaGetSymbolAddress((void**)&Wre0, g_Wre0);
    cudaGetSymbolAddress((void**)&Wre1, g_Wre1);
    cudaGetSymbolAddress((void**)&bre0, g_bre0);
    cudaGetSymbolAddress((void**)&bre1, g_bre1);

    cudaFuncSetAttribute(persist_kernel,
                         cudaFuncAttributeMaxDynamicSharedMemorySize, PSMEM);

    transpose_kernel<<<(BNR * SEQ * 32 + 255) / 256, 256>>>(x);
    rearr_w_kernel<<<1024, 256>>>(Wih0, Whh0, bih0, bhh0, Wre0, bre0);
    rearr_w_kernel<<<1024, 256>>>(Wih1, Whh1, bih1, bhh1, Wre1, bre1);
    rearr_h1_kernel<<<256, 256>>>(cw1, cb1, sw1, sb1, lw1, lb1);
    zero_state_kernel<<<800, 256>>>();

    persist_kernel<<<NCTA, 256, PSMEM>>>(lng, lnb, cw2, cb2, sw2, sb2,
                                         lw2, lb2, out);
}

// round 12
// speedup vs baseline: 3.0277x; 1.0097x over previous
#include <cuda_runtime.h>
#include <cuda_fp16.h>
#include <cstdint>

#define BNR    1600
#define HD     256
#define SEQ    64
#define NSTEPS 10
#define MT     17          /* M groups of 96 rows */
#define MROWS  96
#define NCTA   (MT * 8)    /* 136 CTAs, one wave on 148 SMs */

// ------------------------- static device scratch --------------------------
__device__ uint32_t g_xw  [BNR * SEQ * 128];    // x fp16 [m][t][128w]
__device__ uint32_t g_h0buf[2][BNR * 128];
__device__ uint32_t g_h1buf[2][BNR * 128];
__device__ uint32_t g_htw [BNR * 128];          // LN output fp16
__device__ float    g_hid [BNR * 512];
__device__ uint32_t g_Wre0[1024 * 256];         // fp16, rows (j*4+g), k=[Wih|Whh]
__device__ uint32_t g_Wre1[1024 * 256];
__device__ float    g_bre0[1024];
__device__ float    g_bre1[1024];
__device__ uint32_t g_Wh1 [512 * 128];          // heads layer1 weights fp16
__device__ float    g_bh1 [512];
__device__ unsigned g_grpCnt[MT * 32];          // per-group barrier (128B stride)
__device__ unsigned g_grpGen[MT * 32];

// ------------------------------ helpers -----------------------------------
__device__ __forceinline__ void mma_f16(float* d, const uint32_t* a,
                                        uint32_t b0, uint32_t b1) {
    asm volatile(
        "mma.sync.aligned.m16n8k16.row.col.f32.f16.f16.f32 "
        "{%0,%1,%2,%3}, {%4,%5,%6,%7}, {%8,%9}, {%0,%1,%2,%3};"
        : "+f"(d[0]), "+f"(d[1]), "+f"(d[2]), "+f"(d[3])
        : "r"(a[0]), "r"(a[1]), "r"(a[2]), "r"(a[3]), "r"(b0), "r"(b1));
}
__device__ __forceinline__ void ldm_x4(uint32_t& r0, uint32_t& r1,
                                       uint32_t& r2, uint32_t& r3,
                                       uint32_t addr) {
    asm volatile("ldmatrix.sync.aligned.m8n8.x4.shared.b16 {%0,%1,%2,%3}, [%4];"
                 : "=r"(r0), "=r"(r1), "=r"(r2), "=r"(r3) : "r"(addr));
}
__device__ __forceinline__ float tanha(float x) {
    float r;
    asm("tanh.approx.f32 %0, %1;" : "=f"(r) : "f"(x));
    return r;
}
__device__ __forceinline__ float sigf(float x) {
    return fmaf(tanha(0.5f * x), 0.5f, 0.5f);
}
__device__ __forceinline__ void cpa16(uint32_t saddr, const void* g, int sz) {
    asm volatile("cp.async.cg.shared.global [%0], [%1], 16, %2;"
                 :: "r"(saddr), "l"(g), "r"(sz));
}
#define CP_COMMIT() asm volatile("cp.async.commit_group;")

// per-group barrier: 8 CTAs sharing mx group
__device__ __forceinline__ void gbar(int grp) {
    __syncthreads();
    if (threadIdx.x == 0) {
        __threadfence();
        unsigned* cnt = &g_grpCnt[grp * 32];
        unsigned* gen = &g_grpGen[grp * 32];
        unsigned g = *(volatile unsigned*)gen;
        if (atomicAdd(cnt, 1u) == 7u) {
            *(volatile unsigned*)cnt = 0u;
            __threadfence();
            atomicExch(gen, g + 1);
        } else {
            while (*(volatile unsigned*)gen == g) __nanosleep(32);
        }
        __threadfence();
    }
    __syncthreads();
}

// ------------------------------ setup kernels -----------------------------
__global__ void transpose_kernel(const float* __restrict__ x) {
    int id = blockIdx.x * blockDim.x + threadIdx.x;    // BNR*SEQ*32 groups of 8
    if (id >= BNR * SEQ * 32) return;
    int w8 = id & 31;
    int t  = (id >> 5) & 63;
    int m  = id >> 11;
    int b  = m / 100;
    int n  = m - b * 100;
    const float4* src = (const float4*)x + ((((long)(b * SEQ + t) * 100 + n) * 64) + 2 * w8);
    float4 v0 = src[0], v1 = src[1];
    __half2 h0 = __floats2half2_rn(v0.x, v0.y);
    __half2 h1 = __floats2half2_rn(v0.z, v0.w);
    __half2 h2 = __floats2half2_rn(v1.x, v1.y);
    __half2 h3 = __floats2half2_rn(v1.z, v1.w);
    uint4 o;
    o.x = *(uint32_t*)&h0; o.y = *(uint32_t*)&h1;
    o.z = *(uint32_t*)&h2; o.w = *(uint32_t*)&h3;
    ((uint4*)g_xw)[((long)m * SEQ + t) * 32 + w8] = o;
}

__global__ void rearr_w_kernel(const float* __restrict__ Wih,
                               const float* __restrict__ Whh,
                               const float* __restrict__ bih,
                               const float* __restrict__ bhh,
                               uint32_t* __restrict__ Wre,
                               float* __restrict__ bre) {
    int id = blockIdx.x * 256 + threadIdx.x;   // over 1024*256 words
    if (id >= 1024 * 256) return;
    int nre = id >> 8, kw = id & 255;
    int j = nre >> 2, g = nre & 3;
    int srow = g * 256 + j;
    int k = kw * 2;
    float v0, v1;
    if (k < 256) { v0 = Wih[srow * 256 + k];       v1 = Wih[srow * 256 + k + 1]; }
    else         { v0 = Whh[srow * 256 + k - 256]; v1 = Whh[srow * 256 + k - 255]; }
    __half2 h = __floats2half2_rn(v0, v1);
    Wre[id] = *(uint32_t*)&h;
    if (kw == 0) bre[nre] = bih[srow] + bhh[srow];
}

__global__ void rearr_h1_kernel(const float* __restrict__ cw1, const float* __restrict__ cb1,
                                const float* __restrict__ sw1, const float* __restrict__ sb1,
                                const float* __restrict__ lw1, const float* __restrict__ lb1) {
    int id = blockIdx.x * 256 + threadIdx.x;   // 512*128 words
    if (id >= 512 * 128) return;
    int row = id >> 7, kw = id & 127;
    int k = kw * 2;
    const float* w; float b;
    if (row < 128)      { w = cw1 + row * 256;         b = cb1[row]; }
    else if (row < 256) { w = sw1 + (row - 128) * 256; b = sb1[row - 128]; }
    else                { w = lw1 + (row - 256) * 256; b = lb1[row - 256]; }
    __half2 h = __floats2half2_rn(w[k], w[k + 1]);
    g_Wh1[id] = *(uint32_t*)&h;
    if (kw == 0) g_bh1[row] = b;
}

__global__ void zero_state_kernel() {
    int id = blockIdx.x * blockDim.x + threadIdx.x;
    if (id < BNR * 128) { g_h0buf[0][id] = 0u; g_h1buf[0][id] = 0u; }
    if (id < MT * 32) { g_grpCnt[id] = 0u; g_grpGen[id] = 0u; }
}

// ---------------------------------------------------------------------------
// smem: 4 stages x (A 128x36w + B 128x36w) + biases + 2 dedicated h-stages
#define STG_W   9216
#define STG_B   (STG_W * 4)
#define BOF_B   (4608 * 4)
#define BIAS_W  (4 * STG_W)
#define HS0_W   (BIAS_W + 320)            /* __half hs0[96*40] = 1920 words */
#define HS1_W   (HS0_W + 1920)
#define PSMEM   ((HS1_W + 1920) * 4)
#define ROWB    144                        /* 36 words * 4 bytes */

// ---------------- shared epilogue helper (per-warp, writes hs) -------------
__device__ __forceinline__ void lstm_epi(
    const float acc[3][4][4], const float* biasS, float* cReg, __half* hs,
    int wm, int wn, int g4, int t4)
{
    const bool oddl = (t4 & 1);
    const unsigned FULL = 0xffffffffu;
#pragma unroll
    for (int mf = 0; mf < 3; ++mf) {
#pragma unroll
        for (int nf = 0; nf < 4; ++nf) {
            float c0v = acc[mf][nf][0], c1v = acc[mf][nf][1];
            float c2v = acc[mf][nf][2], c3v = acc[mf][nf][3];
            float x0 = __shfl_xor_sync(FULL, c0v, 1);
            float x1 = __shfl_xor_sync(FULL, c1v, 1);
            float x2 = __shfl_xor_sync(FULL, c2v, 1);
            float x3 = __shfl_xor_sync(FULL, c3v, 1);
            float gi, gf, gg, go; int rloc;
            if (!oddl) { gi = c0v; gf = c1v; gg = x0;  go = x1;  rloc = g4; }
            else       { gi = x2;  gf = x3;  gg = c2v; go = c3v; rloc = g4 + 8; }
            int rowloc = wm * 48 + mf * 16 + rloc;       // 0..95
            int jl = wn * 8 + nf * 2 + (t4 >> 1);        // 0..31
            gi += biasS[jl * 4 + 0];
            gf += biasS[jl * 4 + 1];
            gg += biasS[jl * 4 + 2];
            go += biasS[jl * 4 + 3];
            float cold = cReg[mf * 4 + nf];
            float cn = sigf(gf) * cold + sigf(gi) * tanha(gg);
            float hn = sigf(go) * tanha(cn);
            cReg[mf * 4 + nf] = cn;
            hs[rowloc * 40 + jl] = __float2half_rn(hn);
        }
    }
}

// ---------------- compute one K-chunk from stage st into acc ---------------
__device__ __forceinline__ void chunk_mma(
    float acc[3][4][4], uint32_t aPre, uint32_t bPre, int st)
{
#pragma unroll
    for (int ks = 0; ks < 32; ks += 8) {
        uint32_t af[3][4], b0[4], b1[4];
        uint32_t ab = aPre + st * STG_B + ks * 4;
        uint32_t bb = bPre + st * STG_B + ks * 4;
        ldm_x4(af[0][0], af[0][1], af[0][2], af[0][3], ab);
        ldm_x4(af[1][0], af[1][1], af[1][2], af[1][3], ab + 16 * ROWB);
        ldm_x4(af[2][0], af[2][1], af[2][2], af[2][3], ab + 32 * ROWB);
        ldm_x4(b0[0], b1[0], b0[1], b1[1], bb);
        ldm_x4(b0[2], b1[2], b0[3], b1[3], bb + 16 * ROWB);
#pragma unroll
        for (int mf = 0; mf < 3; ++mf)
#pragma unroll
            for (int nf = 0; nf < 4; ++nf)
                mma_f16(acc[mf][nf], af[mf], b0[nf], b1[nf]);
    }
}

// ---------------- fused dual-cell phase: L0(t) + L1(t-1), 16 chunks --------
__device__ __forceinline__ void cell2_phase(
    uint32_t* sm,
    const uint32_t* __restrict__ Ax, long ldax,   // x(t)
    const uint32_t* __restrict__ H0p,             // h0(t-1)
    const uint32_t* __restrict__ H1p,             // h1(t-2)
    const uint32_t* __restrict__ W0sl,
    const uint32_t* __restrict__ W1sl,
    const float* bS0, const float* bS1,
    float* c0r, float* c1r,
    uint32_t* __restrict__ H0out, uint32_t* __restrict__ H1out,
    int m0, int j0)
{
    const int tid  = threadIdx.x;
    const int arow = tid >> 3, ac4 = tid & 7;
    const int lane = tid & 31, wid = tid >> 5;
    const int wm = wid >> 2, wn = wid & 3;
    const int g4 = lane >> 2, t4 = lane & 3;

    int mrow[3], msz[3];
#pragma unroll
    for (int q = 0; q < 3; ++q) {
        int m = m0 + arow + 32 * q;
        bool p = m < BNR;
        mrow[q] = p ? m : 0;
        msz[q]  = p ? 16 : 0;
    }
    const uint32_t sbase = (uint32_t)__cvta_generic_to_shared(sm);
    uint32_t sb = sbase + (uint32_t)((arow * 36 + ac4 * 4) * 4);
    const uint32_t aPre = sbase +
        (uint32_t)((wm * 48 + (lane & 7) + ((lane >> 3) & 1) * 8) * ROWB +
                   (lane >> 4) * 16);
    const uint32_t bPre = sbase + BOF_B +
        (uint32_t)((wn * 32 + ((lane >> 4) & 1) * 8 + (lane & 7)) * ROWB +
                   ((lane >> 3) & 1) * 16);
    __half* hs0 = (__half*)(sm + HS0_W);
    __half* hs1 = (__half*)(sm + HS1_W);

    auto issue = [&](int c) {
        const int st = c & 3;
        const uint32_t* ap; long lda; int kk;
        if (c < 4)       { ap = Ax;  lda = ldax; kk = c * 32; }
        else if (c < 8)  { ap = H0p; lda = 128;  kk = (c - 4) * 32; }
        else if (c < 12) { ap = H0p; lda = 128;  kk = (c - 8) * 32; }
        else             { ap = H1p; lda = 128;  kk = (c - 12) * 32; }
        const uint32_t* wsl = (c < 8) ? W0sl : W1sl;
        const int kw = (c < 8) ? c * 32 : (c - 8) * 32;
#pragma unroll
        for (int q = 0; q < 3; ++q)
            cpa16(sb + st * STG_B + q * 4608,
                  ap + (long)mrow[q] * lda + kk + ac4 * 4, msz[q]);
#pragma unroll
        for (int q = 0; q < 4; ++q)
            cpa16(sb + st * STG_B + BOF_B + q * 4608,
                  wsl + (long)(arow + 32 * q) * 256 + kw + ac4 * 4, 16);
        CP_COMMIT();
    };

    issue(0); issue(1); issue(2);

    {   // -------- cell 0 (chunks 0..7) --------
        float acc[3][4][4];
#pragma unroll
        for (int a = 0; a < 3; ++a)
#pragma unroll
            for (int b = 0; b < 4; ++b)
#pragma unroll
                for (int k = 0; k < 4; ++k) acc[a][b][k] = 0.f;
        for (int c = 0; c < 8; ++c) {
            asm volatile("cp.async.wait_group 2;");
            __syncthreads();
            issue(c + 3);
            chunk_mma(acc, aPre, bPre, c & 3);
        }
        lstm_epi(acc, bS0, c0r, hs0, wm, wn, g4, t4);   // no sync needed here
    }
    {   // -------- cell 1 (chunks 8..15) --------
        float acc[3][4][4];
#pragma unroll
        for (int a = 0; a < 3; ++a)
#pragma unroll
            for (int b = 0; b < 4; ++b)
#pragma unroll
                for (int k = 0; k < 4; ++k) acc[a][b][k] = 0.f;
        for (int c = 8; c < 16; ++c) {
            if (c <= 13)      asm volatile("cp.async.wait_group 2;");
            else if (c == 14) asm volatile("cp.async.wait_group 1;");
            else              asm volatile("cp.async.wait_group 0;");
            __syncthreads();
            if (c + 3 < 16) issue(c + 3);
            chunk_mma(acc, aPre, bPre, c & 3);
        }
        lstm_epi(acc, bS1, c1r, hs1, wm, wn, g4, t4);
    }
    __syncthreads();
    if (tid < 192) {   // coalesced stores for both h tiles
        int row = tid >> 1, part = tid & 1;
        int rglob = m0 + row;
        if (rglob < BNR) {
            const uint4* s0 = (const uint4*)(hs0 + row * 40) + part * 2;
            uint4 a0 = s0[0], a1 = s0[1];
            uint4* d0 = (uint4*)(H0out + (long)rglob * 128 + (j0 >> 1)) + part * 2;
            d0[0] = a0; d0[1] = a1;
            const uint4* s1 = (const uint4*)(hs1 + row * 40) + part * 2;
            uint4 b0 = s1[0], b1 = s1[1];
            uint4* d1 = (uint4*)(H1out + (long)rglob * 128 + (j0 >> 1)) + part * 2;
            d1[0] = b0; d1[1] = b1;
        }
    }
    __syncthreads();
}

// ---------------- single LSTM cell phase (edges + decoder) -----------------
__device__ __forceinline__ void cell_phase(
    uint32_t* sm,
    const uint32_t* __restrict__ A0, long lda0,
    const uint32_t* __restrict__ A1,
    const uint32_t* __restrict__ Wsl,
    const float* biasS, float* cReg,
    uint32_t* __restrict__ Hw,
    int m0, int j0)
{
    const int tid  = threadIdx.x;
    const int arow = tid >> 3, ac4 = tid & 7;
    const int lane = tid & 31, wid = tid >> 5;
    const int wm = wid >> 2, wn = wid & 3;
    const int g4 = lane >> 2, t4 = lane & 3;

    int mrow[3], msz[3];
#pragma unroll
    for (int q = 0; q < 3; ++q) {
        int m = m0 + arow + 32 * q;
        bool p = m < BNR;
        mrow[q] = p ? m : 0;
        msz[q]  = p ? 16 : 0;
    }
    const uint32_t sbase = (uint32_t)__cvta_generic_to_shared(sm);
    uint32_t sb = sbase + (uint32_t)((arow * 36 + ac4 * 4) * 4);
    const uint32_t aPre = sbase +
        (uint32_t)((wm * 48 + (lane & 7) + ((lane >> 3) & 1) * 8) * ROWB +
                   (lane >> 4) * 16);
    const uint32_t bPre = sbase + BOF_B +
        (uint32_t)((wn * 32 + ((lane >> 4) & 1) * 8 + (lane & 7)) * ROWB +
                   ((lane >> 3) & 1) * 16);
    __half* hs0 = (__half*)(sm + HS0_W);

    float acc[3][4][4];
#pragma unroll
    for (int a = 0; a < 3; ++a)
#pragma unroll
        for (int b = 0; b < 4; ++b)
#pragma unroll
            for (int k = 0; k < 4; ++k) acc[a][b][k] = 0.f;

    auto issue = [&](int c) {
        const int st = c & 3;
        const uint32_t* ap; long lda; int kk;
        if (c < 4) { ap = A0; lda = lda0; kk = c * 32; }
        else       { ap = A1; lda = 128;  kk = (c - 4) * 32; }
#pragma unroll
        for (int q = 0; q < 3; ++q)
            cpa16(sb + st * STG_B + q * 4608,
                  ap + (long)mrow[q] * lda + kk + ac4 * 4, msz[q]);
#pragma unroll
        for (int q = 0; q < 4; ++q)
            cpa16(sb + st * STG_B + BOF_B + q * 4608,
                  Wsl + (long)(arow + 32 * q) * 256 + c * 32 + ac4 * 4, 16);
        CP_COMMIT();
    };

    issue(0); issue(1); issue(2);
    for (int c = 0; c < 8; ++c) {
        if (c <= 5)      asm volatile("cp.async.wait_group 2;");
        else if (c == 6) asm volatile("cp.async.wait_group 1;");
        else             asm volatile("cp.async.wait_group 0;");
        __syncthreads();
        if (c + 3 < 8) issue(c + 3);
        chunk_mma(acc, aPre, bPre, c & 3);
    }

    lstm_epi(acc, biasS, cReg, hs0, wm, wn, g4, t4);
    __syncthreads();
    if (tid < 192) {
        int row = tid >> 1, part = tid & 1;
        int rglob = m0 + row;
        if (rglob < BNR) {
            const uint4* src = (const uint4*)(hs0 + row * 40) + part * 2;
            uint4 v0 = src[0], v1 = src[1];
            uint4* dst = (uint4*)(Hw + (long)rglob * 128 + (j0 >> 1)) + part * 2;
            dst[0] = v0; dst[1] = v1;
        }
    }
    __syncthreads();
}

// ---------------- heads layer-1 phase (fp16 mma + ldmatrix) ------------------
__device__ __forceinline__ void heads1_phase(
    uint32_t* sm, const uint32_t* __restrict__ A0,
    const uint32_t* __restrict__ Wsl,
    const float* biasS, float* __restrict__ hid, int m0, int n0)
{
    const int tid  = threadIdx.x;
    const int arow = tid >> 3, ac4 = tid & 7;
    const int lane = tid & 31, wid = tid >> 5;
    const int wm = wid >> 2, wn = wid & 3;
    const int g4 = lane >> 2, t4 = lane & 3;

    int mrow[3], msz[3];
#pragma unroll
    for (int q = 0; q < 3; ++q) {
        int m = m0 + arow + 32 * q;
        bool p = m < BNR;
        mrow[q] = p ? m : 0;
        msz[q]  = p ? 16 : 0;
    }
    const uint32_t sbase = (uint32_t)__cvta_generic_to_shared(sm);
    uint32_t sb = sbase + (uint32_t)((arow * 36 + ac4 * 4) * 4);
    const uint32_t aPre = sbase +
        (uint32_t)((wm * 48 + (lane & 7) + ((lane >> 3) & 1) * 8) * ROWB +
                   (lane >> 4) * 16);
    const uint32_t bPre = sbase + BOF_B +
        (uint32_t)((wn * 16 + ((lane >> 4) & 1) * 8 + (lane & 7)) * ROWB +
                   ((lane >> 3) & 1) * 16);

    float acc[3][2][4];
#pragma unroll
    for (int a = 0; a < 3; ++a)
#pragma unroll
        for (int b = 0; b < 2; ++b)
#pragma unroll
            for (int k = 0; k < 4; ++k) acc[a][b][k] = 0.f;

    auto issue = [&](int c, int st) {
        int kk = c * 32;
#pragma unroll
        for (int q = 0; q < 3; ++q)
            cpa16(sb + st * STG_B + q * 4608,
                  A0 + (long)mrow[q] * 128 + kk + ac4 * 4, msz[q]);
#pragma unroll
        for (int q = 0; q < 2; ++q)
            cpa16(sb + st * STG_B + BOF_B + q * 4608,
                  Wsl + (long)(arow + 32 * q) * 128 + kk + ac4 * 4, 16);
        CP_COMMIT();
    };

    issue(0, 0); issue(1, 1); issue(2, 2);
    for (int c = 0; c < 4; ++c) {
        const int st = c & 3;
        if (c <= 1)      asm volatile("cp.async.wait_group 2;");
        else if (c == 2) asm volatile("cp.async.wait_group 1;");
        else             asm volatile("cp.async.wait_group 0;");
        __syncthreads();
        if (c + 3 < 4) issue(c + 3, (c + 3) & 3);

#pragma unroll
        for (int ks = 0; ks < 32; ks += 8) {
            uint32_t af[3][4], b0[2], b1[2];
            uint32_t ab = aPre + st * STG_B + ks * 4;
            uint32_t bb = bPre + st * STG_B + ks * 4;
            ldm_x4(af[0][0], af[0][1], af[0][2], af[0][3], ab);
            ldm_x4(af[1][0], af[1][1], af[1][2], af[1][3], ab + 16 * ROWB);
            ldm_x4(af[2][0], af[2][1], af[2][2], af[2][3], ab + 32 * ROWB);
            ldm_x4(b0[0], b1[0], b0[1], b1[1], bb);
#pragma unroll
            for (int mf = 0; mf < 3; ++mf)
#pragma unroll
                for (int nf = 0; nf < 2; ++nf)
                    mma_f16(acc[mf][nf], af[mf], b0[nf], b1[nf]);
        }
    }

#pragma unroll
    for (int mf = 0; mf < 3; ++mf) {
#pragma unroll
        for (int nf = 0; nf < 2; ++nf) {
            int col = wn * 16 + nf * 8 + 2 * t4;
            int r0 = m0 + wm * 48 + mf * 16 + g4;
            float v0 = acc[mf][nf][0] + biasS[col];
            float v1 = acc[mf][nf][1] + biasS[col + 1];
            float v2 = acc[mf][nf][2] + biasS[col];
            float v3 = acc[mf][nf][3] + biasS[col + 1];
            if (r0 < BNR) {
                hid[(long)r0 * 512 + n0 + col]     = fmaxf(v0, 0.f);
                hid[(long)r0 * 512 + n0 + col + 1] = fmaxf(v1, 0.f);
            }
            if (r0 + 8 < BNR) {
                hid[(long)(r0 + 8) * 512 + n0 + col]     = fmaxf(v2, 0.f);
                hid[(long)(r0 + 8) * 512 + n0 + col + 1] = fmaxf(v3, 0.f);
            }
        }
    }
}

// ---------------- LayerNorm phase (warp per row, 12 rows per CTA) -----------
__device__ __forceinline__ void ln_phase(
    const uint32_t* __restrict__ h1, const float* __restrict__ gam,
    const float* __restrict__ bet, uint32_t* __restrict__ ht, int rowbase)
{
    const int wid = threadIdx.x >> 5, lane = threadIdx.x & 31;
    const unsigned FULL = 0xffffffffu;
#pragma unroll
    for (int rep = 0; rep < 2; ++rep) {
        int rr = rep * 8 + wid;
        int r = rowbase + rr;
        if (rr < 12 && r < BNR) {
            uint4 u = __ldcg((const uint4*)(h1 + (long)r * 128 + lane * 4));
            float v[8];
            __half2 hh;
            hh = *(__half2*)&u.x; v[0] = __low2float(hh); v[1] = __high2float(hh);
            hh = *(__half2*)&u.y; v[2] = __low2float(hh); v[3] = __high2float(hh);
            hh = *(__half2*)&u.z; v[4] = __low2float(hh); v[5] = __high2float(hh);
            hh = *(__half2*)&u.w; v[6] = __low2float(hh); v[7] = __high2float(hh);
            float s1 = 0.f, s2 = 0.f;
#pragma unroll
            for (int i = 0; i < 8; ++i) { s1 += v[i]; s2 += v[i] * v[i]; }
#pragma unroll
            for (int o = 16; o; o >>= 1) {
                s1 += __shfl_xor_sync(FULL, s1, o);
                s2 += __shfl_xor_sync(FULL, s2, o);
            }
            float mean = s1 * (1.f / 256.f);
            float var  = s2 * (1.f / 256.f) - mean * mean;
            float rstd = rsqrtf(var + 1e-5f);
            uint4 o4;
            uint32_t* op = (uint32_t*)&o4;
#pragma unroll
            for (int i = 0; i < 4; ++i) {
                float g0 = __ldg(&gam[lane * 8 + 2 * i]);
                float g1 = __ldg(&gam[lane * 8 + 2 * i + 1]);
                float b0 = __ldg(&bet[lane * 8 + 2 * i]);
                float b1 = __ldg(&bet[lane * 8 + 2 * i + 1]);
                float o0 = (v[2 * i]     - mean) * rstd * g0 + b0;
                float o1 = (v[2 * i + 1] - mean) * rstd * g1 + b1;
                __half2 ho = __floats2half2_rn(o0, o1);
                op[i] = *(uint32_t*)&ho;
            }
            *(uint4*)(ht + (long)r * 128 + lane * 4) = o4;
        }
    }
}

// ---------------- heads layer-2 phase (12 rows per CTA) ---------------------
__device__ __forceinline__ void heads2_phase(
    uint32_t* sm, const float* __restrict__ hid,
    const float* __restrict__ cw2, const float* __restrict__ cb2,
    const float* __restrict__ sw2, const float* __restrict__ sb2,
    const float* __restrict__ lw2, const float* __restrict__ lb2,
    float* __restrict__ out, int s, int rowbase)
{
    float* hs = (float*)sm;                 // 12 rows x 512 f32 = 24KB (stage0)
    const int tid = threadIdx.x;
    for (int i = tid; i < 12 * 128; i += 256) {
        int rr = i >> 7, c4 = i & 127;
        int r = rowbase + rr;
        float4 val = make_float4(0.f, 0.f, 0.f, 0.f);
        if (r < BNR) val = __ldcg((const float4*)(hid + (long)r * 512) + c4);
        ((float4*)hs)[rr * 128 + c4] = val;
    }
    __syncthreads();

    const int wid = tid >> 5, lane = tid & 31;
    const unsigned FULL = 0xffffffffu;
#pragma unroll
    for (int rep = 0; rep < 2; ++rep) {
        int rr = rep * 8 + wid;
        int r = rowbase + rr;
        if (rr < 12 && r < BNR) {
            int b = r / 100, n = r - b * 100;
            float* ob = out + (((b * NSTEPS + s) * 100 + n) * 22);
            const float* h = hs + rr * 512;
            for (int o = 0; o < 22; ++o) {
                const float* w; float bb; int base, klen;
                if (o < 4)      { w = cw2 + o * 128;       bb = __ldg(&cb2[o]);     base = 0;   klen = 128; }
                else if (o < 6) { w = sw2 + (o - 4) * 128; bb = __ldg(&sb2[o - 4]); base = 128; klen = 128; }
                else            { w = lw2 + (o - 6) * 256; bb = __ldg(&lb2[o - 6]); base = 256; klen = 256; }
                float a = 0.f;
                for (int k = lane; k < klen; k += 32) a += h[base + k] * __ldg(&w[k]);
#pragma unroll
                for (int off = 16; off; off >>= 1) a += __shfl_xor_sync(FULL, a, off);
                if (lane == 0) ob[o] = a + bb;
            }
        }
    }
    __syncthreads();
}

// ---------------------------------------------------------------------------
__global__ void __launch_bounds__(256, 1)
persist_kernel(const float* __restrict__ lng, const float* __restrict__ lnb,
               const float* __restrict__ cw2, const float* __restrict__ cb2,
               const float* __restrict__ sw2, const float* __restrict__ sb2,
               const float* __restrict__ lw2, const float* __restrict__ lb2,
               float* __restrict__ out)
{
    extern __shared__ uint32_t sm[];
    float* bS0 = (float*)(sm + BIAS_W);
    float* bS1 = bS0 + 128;
    float* bSh = bS1 + 128;

    const int tid = threadIdx.x;
    const int cta = blockIdx.x;
    const int mx = cta % MT, ny = cta / MT;
    const int m0  = mx * MROWS;
    const int nb0 = ny * 128;           // gate-row base
    const int j0  = ny * 32;            // j-col base
    const int hn0 = ny * 64;            // heads1 col base
    const int rowbase = m0 + ny * 12;   // LN/heads2 group-local rows (12 each)

    if (tid < 128) { bS0[tid] = g_bre0[nb0 + tid]; bS1[tid] = g_bre1[nb0 + tid]; }
    if (tid < 64)  { bSh[tid] = g_bh1[hn0 + tid]; }
    __syncthreads();

    float c0r[12], c1r[12];
#pragma unroll
    for (int i = 0; i < 12; ++i) { c0r[i] = 0.f; c1r[i] = 0.f; }

    const uint32_t* W0sl  = g_Wre0 + (long)nb0 * 256;
    const uint32_t* W1sl  = g_Wre1 + (long)nb0 * 256;
    const uint32_t* Wh1sl = g_Wh1 + (long)hn0 * 128;

    // ---------------- encoder (fused: phase t = L0(t)+L1(t-1)) --------------
    cell_phase(sm, g_xw, (long)SEQ * 128, g_h0buf[0],
               W0sl, bS0, c0r, g_h0buf[1], m0, j0);            // L0(0)
    gbar(mx);
    for (int t = 1; t < SEQ; ++t) {
        cell2_phase(sm, g_xw + (long)t * 128, (long)SEQ * 128,
                    g_h0buf[t & 1], g_h1buf[(t + 1) & 1],
                    W0sl, W1sl, bS0, bS1, c0r, c1r,
                    g_h0buf[(t + 1) & 1], g_h1buf[t & 1], m0, j0);
        gbar(mx);
    }
    cell_phase(sm, g_h0buf[0], 128, g_h1buf[1],
               W1sl, bS1, c1r, g_h1buf[0], m0, j0);             // L1(63)
    gbar(mx);
    ln_phase(g_h1buf[0], lng, lnb, g_htw, rowbase);
    gbar(mx);

    // ---------------- decoder ----------------
    for (int s = 0; s < NSTEPS; ++s) {
        heads1_phase(sm, g_htw, Wh1sl, bSh, g_hid, m0, hn0);
        cell_phase(sm, g_htw, 128, g_h0buf[s & 1],
                   W0sl, bS0, c0r, g_h0buf[(s + 1) & 1], m0, j0);
        gbar(mx);
        cell_phase(sm, g_h0buf[(s + 1) & 1], 128, g_h1buf[s & 1],
                   W1sl, bS1, c1r, g_h1buf[(s + 1) & 1], m0, j0);
        heads2_phase(sm, g_hid, cw2, cb2, sw2, sb2, lw2, lb2, out, s, rowbase);
        if (s < NSTEPS - 1) {
            gbar(mx);
            ln_phase(g_h1buf[(s + 1) & 1], lng, lnb, g_htw, rowbase);
            gbar(mx);
        }
    }
}

// ---------------------------------------------------------------------------
extern "C" void kernel_launch(void* const* d_in, const int* in_sizes, int n_in,
                              void* d_out, int out_size)
{
    (void)in_sizes; (void)n_in; (void)out_size;
    const float* x    = (const float*)d_in[0];
    const float* Wih0 = (const float*)d_in[1];
    const float* Whh0 = (const float*)d_in[2];
    const float* bih0 = (const float*)d_in[3];
    const float* bhh0 = (const float*)d_in[4];
    const float* Wih1 = (const float*)d_in[5];
    const float* Whh1 = (const float*)d_in[6];
    const float* bih1 = (const float*)d_in[7];
    const float* bhh1 = (const float*)d_in[8];
    const float* lng  = (const float*)d_in[9];
    const float* lnb  = (const float*)d_in[10];
    const float* cw1  = (const float*)d_in[11];
    const float* cb1  = (const float*)d_in[12];
    const float* cw2  = (const float*)d_in[13];
    const float* cb2  = (const float*)d_in[14];
    const float* sw1  = (const float*)d_in[15];
    const float* sb1  = (const float*)d_in[16];
    const float* sw2  = (const float*)d_in[17];
    const float* sb2  = (const float*)d_in[18];
    const float* lw1  = (const float*)d_in[19];
    const float* lb1  = (const float*)d_in[20];
    const float* lw2  = (const float*)d_in[21];
    const float* lb2  = (const float*)d_in[22];
    float* out = (float*)d_out;

    uint32_t *Wre0, *Wre1;
    float *bre0, *bre1;
    cudaGetSymbolAddress((void**)&Wre0, g_Wre0);
    cudaGetSymbolAddress((void**)&Wre1, g_Wre1);
    cudaGetSymbolAddress((void**)&bre0, g_bre0);
    cudaGetSymbolAddress((void**)&bre1, g_bre1);

    cudaFuncSetAttribute(persist_kernel,
                         cudaFuncAttributeMaxDynamicSharedMemorySize, PSMEM);

    transpose_kernel<<<(BNR * SEQ * 32 + 255) / 256, 256>>>(x);
    rearr_w_kernel<<<1024, 256>>>(Wih0, Whh0, bih0, bhh0, Wre0, bre0);
    rearr_w_kernel<<<1024, 256>>>(Wih1, Whh1, bih1, bhh1, Wre1, bre1);
    rearr_h1_kernel<<<256, 256>>>(cw1, cb1, sw1, sb1, lw1, lb1);
    zero_state_kernel<<<800, 256>>>();

    persist_kernel<<<NCTA, 256, PSMEM>>>(lng, lnb, cw2, cb2, sw2, sb2,
                                         lw2, lb2, out);
}